// round 2
// baseline (speedup 1.0000x reference)
#include <cuda_runtime.h>
#include <cuda_bf16.h>
#include <math.h>

// ---------------- problem constants ----------------
#define BD 8
#define LD 5
#define NP 4096
#define NANCH 64
#define NTOT 4160          // NP + NANCH
#define MM 260             // NTOT / 16
#define NF 3
#define SEQ 780            // NF*MM
#define ROWS 6240          // BD*SEQ
#define DIM 512
#define HEADS 8
#define DH 64
#define INNER 512
#define MLP 1024
#define OUTD 1088
#define KNN 32
#define DEPTH 5

// ---------------- scratch (device globals; no allocation allowed) ----------------
__device__ float g_axyz[BD * NF * MM * 3];
__device__ float g_x[ROWS * DIM];
__device__ float g_xn[ROWS * DIM];
__device__ float g_qkv[ROWS * 3 * INNER];
__device__ float g_att[ROWS * INNER];
__device__ float g_ff1[ROWS * MLP];
__device__ float g_pool[BD * DIM];
__device__ float g_pooln[BD * DIM];
__device__ float g_h1[BD * MLP];
__device__ float g_h2[BD * OUTD];

// ---------------- helpers ----------------
__device__ __forceinline__ void get_pt(const float* __restrict__ pts, int b, int layer, int j,
                                       float& x, float& y, float& z) {
    if (j < NP) {
        const float* p = pts + ((size_t)((b * LD + layer) * NP + j)) * 3;
        x = p[0]; y = p[1]; z = p[2];
    } else {
        int i = j - NP;
        x = -1.5f + (float)(i >> 4);
        y = -1.5f + (float)((i >> 2) & 3);
        z = -1.5f + (float)(i & 3);
    }
}

__device__ __forceinline__ float gelu_f(float x) {
    return 0.5f * x * (1.0f + erff(x * 0.7071067811865476f));
}

// ---------------- FPS: one block per (b, frame) ----------------
// dynamic smem: sx,sy,sz,dist each NTOT floats
__global__ void fps_kernel(const float* __restrict__ points, float* __restrict__ axyz) {
    const int bf = blockIdx.x;
    const int b = bf / NF, f = bf % NF;
    const int layer = 2 * f;  // frames[:, 1+2f] == pts[:, 2f]
    extern __shared__ float sm[];
    float* sx = sm;
    float* sy = sm + NTOT;
    float* sz = sm + 2 * NTOT;
    float* dist = sm + 3 * NTOT;
    __shared__ float rv[16];
    __shared__ int ri[16];
    __shared__ int s_last;
    int tid = threadIdx.x;

    for (int j = tid; j < NTOT; j += 512) {
        float x, y, z;
        get_pt(points, b, layer, j, x, y, z);
        sx[j] = x; sy[j] = y; sz[j] = z;
        dist[j] = 1e10f;
    }
    __syncthreads();

    int last = 0;
    float* aout = axyz + (size_t)bf * MM * 3;
    for (int s = 0; s < MM; s++) {
        float lx = sx[last], ly = sy[last], lz = sz[last];
        if (tid == 0) { aout[s * 3 + 0] = lx; aout[s * 3 + 1] = ly; aout[s * 3 + 2] = lz; }
        float bv = -1.0f; int bi = 0x7fffffff;
        for (int j = tid; j < NTOT; j += 512) {
            float dx = sx[j] - lx, dy = sy[j] - ly, dz = sz[j] - lz;
            // match XLA: no fma contraction in the distance
            float d = __fadd_rn(__fadd_rn(__fmul_rn(dx, dx), __fmul_rn(dy, dy)), __fmul_rn(dz, dz));
            float nd = fminf(dist[j], d);
            dist[j] = nd;
            if (nd > bv) { bv = nd; bi = j; }  // ascending j keeps lowest index on ties
        }
        for (int off = 16; off; off >>= 1) {
            float ov = __shfl_down_sync(0xffffffffu, bv, off);
            int oi = __shfl_down_sync(0xffffffffu, bi, off);
            if (ov > bv || (ov == bv && oi < bi)) { bv = ov; bi = oi; }
        }
        if ((tid & 31) == 0) { rv[tid >> 5] = bv; ri[tid >> 5] = bi; }
        __syncthreads();
        if (tid < 32) {
            float v2 = (tid < 16) ? rv[tid] : -2.0f;
            int i2 = (tid < 16) ? ri[tid] : 0x7fffffff;
            for (int off = 8; off; off >>= 1) {
                float ov = __shfl_down_sync(0xffffffffu, v2, off);
                int oi = __shfl_down_sync(0xffffffffu, i2, off);
                if (ov > v2 || (ov == v2 && oi < i2)) { v2 = ov; i2 = oi; }
            }
            if (tid == 0) s_last = i2;
        }
        __syncthreads();
        last = s_last;
    }
}

// ---------------- ball query + conv + maxpool + pos embed ----------------
// block per (m, f, b), 256 threads. warps 0..2 do ball query for the 3 windows.
__global__ void group_kernel(const float* __restrict__ points,
                             const float* __restrict__ conv_d_w,
                             const float* __restrict__ conv_f_w,
                             const float* __restrict__ pos_w,
                             const float* __restrict__ pos_b,
                             const float* __restrict__ axyz,
                             float* __restrict__ xout) {
    const int m = blockIdx.x, f = blockIdx.y, b = blockIdx.z;
    __shared__ float gpts[3][KNN][3];
    __shared__ int scnt[3];
    __shared__ float sa[3];
    const int tid = threadIdx.x;

    if (tid < 3) sa[tid] = axyz[((size_t)((b * NF + f) * MM + m)) * 3 + tid];
    __syncthreads();
    const float ax = sa[0], ay = sa[1], az = sa[2];

    const int w = tid >> 5, lane = tid & 31;
    if (w < 3) {
        int layer = 2 * f - 1 + w;
        layer = layer < 0 ? 0 : (layer > 4 ? 4 : layer);
        const float R2 = (float)(0.7 * 0.7);  // rounds like XLA's python-scalar threshold
        int cnt = 0;
        for (int j0 = 0; j0 < NTOT && cnt < KNN; j0 += 32) {
            int j = j0 + lane;
            float px, py, pz;
            get_pt(points, b, layer, j, px, py, pz);
            float dx = px - ax, dy = py - ay, dz = pz - az;
            float d2 = __fadd_rn(__fadd_rn(__fmul_rn(dx, dx), __fmul_rn(dy, dy)), __fmul_rn(dz, dz));
            unsigned mask = __ballot_sync(0xffffffffu, d2 < R2);
            while (mask && cnt < KNN) {
                int src = __ffs(mask) - 1;
                mask &= mask - 1;
                float gx = __shfl_sync(0xffffffffu, px, src);
                float gy = __shfl_sync(0xffffffffu, py, src);
                float gz = __shfl_sync(0xffffffffu, pz, src);
                if (lane == 0) { gpts[w][cnt][0] = gx; gpts[w][cnt][1] = gy; gpts[w][cnt][2] = gz; }
                cnt++;
            }
        }
        if (cnt == 0) {
            if (lane == 0) {
                float gx, gy, gz;
                get_pt(points, b, layer, 0, gx, gy, gz);
                gpts[w][0][0] = gx; gpts[w][0][1] = gy; gpts[w][0][2] = gz;
            }
            cnt = 1;
        }
        if (lane == 0) scnt[w] = cnt;
    }
    __syncthreads();

    const int c0 = scnt[0], c1 = scnt[1], c2 = scnt[2];
    const int cs[3] = {c0, c1, c2};
#pragma unroll
    for (int dd = 0; dd < 2; dd++) {
        int d = tid + dd * 256;
        float wf0 = conv_f_w[d * 3 + 0], wf1 = conv_f_w[d * 3 + 1], wf2 = conv_f_w[d * 3 + 2];
        float wd0 = conv_d_w[d * 4 + 0], wd1 = conv_d_w[d * 4 + 1], wd2 = conv_d_w[d * 4 + 2], wd3 = conv_d_w[d * 4 + 3];
        float ws0 = wf0 + wd0, ws1 = wf1 + wd1, ws2 = wf2 + wd2;
        float adot = ax * wd0 + ay * wd1 + az * wd2;
        float maxv = -1e30f;
        for (int ww = 0; ww < 3; ww++) {
            float dt = (float)(ww - 1);
            float base = dt * wd3 - adot;
            int cn = cs[ww];
            for (int k = 0; k < cn; k++) {
                float gx = gpts[ww][k][0], gy = gpts[ww][k][1], gz = gpts[ww][k][2];
                float v = fmaf(gx, ws0, fmaf(gy, ws1, fmaf(gz, ws2, base)));
                maxv = fmaxf(maxv, v);
            }
        }
        float pw0 = pos_w[d * 4 + 0], pw1 = pos_w[d * 4 + 1], pw2 = pos_w[d * 4 + 2], pw3 = pos_w[d * 4 + 3];
        float t = (float)(f + 1);
        float outv = maxv + ax * pw0 + ay * pw1 + az * pw2 + t * pw3 + pos_b[d];
        xout[((size_t)(b * SEQ + f * MM + m)) * DIM + d] = outv;
    }
}

// ---------------- LayerNorm (rows x 512), 128 threads ----------------
__global__ void ln_kernel(const float* __restrict__ x, const float* __restrict__ gg,
                          const float* __restrict__ bb, float* __restrict__ y) {
    const int r = blockIdx.x;
    const float* xr = x + (size_t)r * DIM;
    float* yr = y + (size_t)r * DIM;
    const int tid = threadIdx.x;
    float v[4];
    float s = 0.f;
#pragma unroll
    for (int i = 0; i < 4; i++) { v[i] = xr[tid + i * 128]; s += v[i]; }
    __shared__ float red[4];
    __shared__ float s_stat;
    for (int off = 16; off; off >>= 1) s += __shfl_down_sync(0xffffffffu, s, off);
    if ((tid & 31) == 0) red[tid >> 5] = s;
    __syncthreads();
    if (tid == 0) s_stat = (red[0] + red[1] + red[2] + red[3]) * (1.0f / DIM);
    __syncthreads();
    float mu = s_stat;
    float q = 0.f;
#pragma unroll
    for (int i = 0; i < 4; i++) { float d = v[i] - mu; q += d * d; }
    __syncthreads();
    for (int off = 16; off; off >>= 1) q += __shfl_down_sync(0xffffffffu, q, off);
    if ((tid & 31) == 0) red[tid >> 5] = q;
    __syncthreads();
    if (tid == 0) s_stat = (red[0] + red[1] + red[2] + red[3]) * (1.0f / DIM);
    __syncthreads();
    float inv = rsqrtf(s_stat + 1e-5f);
#pragma unroll
    for (int i = 0; i < 4; i++) {
        int c = tid + i * 128;
        yr[c] = (v[i] - mu) * inv * gg[c] + bb[c];
    }
}

// ---------------- fp32 tiled GEMM: C[R,Cn] = A[R,Kd] @ W[Kd,Cn] (+bias)(+gelu)(+residual) ----------------
template <bool WITH_BIAS, bool WITH_GELU, bool WITH_RES>
__global__ void gemm_kernel(const float* __restrict__ A, const float* __restrict__ W,
                            const float* __restrict__ bias, const float* __restrict__ Rd,
                            float* __restrict__ C, int Rr, int Kd, int Cn) {
    __shared__ float As[16][65];
    __shared__ float Bs[16][64];
    const int bn = blockIdx.x * 64;
    const int bm = blockIdx.y * 64;
    const int tid = threadIdx.x;
    const int tx = tid & 15, ty = tid >> 4;
    float acc[4][4];
#pragma unroll
    for (int u = 0; u < 4; u++)
#pragma unroll
        for (int v = 0; v < 4; v++) acc[u][v] = 0.f;

    for (int k0 = 0; k0 < Kd; k0 += 16) {
#pragma unroll
        for (int i = 0; i < 4; i++) {
            int lid = tid + i * 256;
            int kk = lid & 15, m = lid >> 4;
            int row = bm + m;
            As[kk][m] = (row < Rr) ? A[(size_t)row * Kd + k0 + kk] : 0.f;
        }
#pragma unroll
        for (int i = 0; i < 4; i++) {
            int lid = tid + i * 256;
            int n = lid & 63, kk = lid >> 6;
            Bs[kk][n] = W[(size_t)(k0 + kk) * Cn + bn + n];
        }
        __syncthreads();
#pragma unroll
        for (int kk = 0; kk < 16; kk++) {
            float a[4];
#pragma unroll
            for (int u = 0; u < 4; u++) a[u] = As[kk][ty * 4 + u];
            float4 bv = *reinterpret_cast<const float4*>(&Bs[kk][tx * 4]);
            float bb4[4] = {bv.x, bv.y, bv.z, bv.w};
#pragma unroll
            for (int u = 0; u < 4; u++)
#pragma unroll
                for (int v = 0; v < 4; v++) acc[u][v] = fmaf(a[u], bb4[v], acc[u][v]);
        }
        __syncthreads();
    }
#pragma unroll
    for (int u = 0; u < 4; u++) {
        int row = bm + ty * 4 + u;
        if (row < Rr) {
#pragma unroll
            for (int v = 0; v < 4; v++) {
                int col = bn + tx * 4 + v;
                float c = acc[u][v];
                if (WITH_BIAS) c += bias[col];
                if (WITH_GELU) c = gelu_f(c);
                if (WITH_RES) c += Rd[(size_t)row * Cn + col];
                C[(size_t)row * Cn + col] = c;
            }
        }
    }
}

// ---------------- attention: flash-style, block per (qtile, head, batch) ----------------
// dyn smem: Qs/Ks/Vs/Ps each 64*65, + 3*64 row stats
__global__ void attn_kernel(const float* __restrict__ qkv, float* __restrict__ o) {
    extern __shared__ float sm[];
    float* Qs = sm;                 // 64*65
    float* Ks = Qs + 64 * 65;       // 64*65
    float* Vs = Ks + 64 * 65;       // 64*65
    float* Ps = Vs + 64 * 65;       // 64*65
    float* mrow = Ps + 64 * 65;     // 64
    float* lrow = mrow + 64;        // 64
    float* crow = lrow + 64;        // 64

    const int qt = blockIdx.x, h = blockIdx.y, b = blockIdx.z;
    const int tid = threadIdx.x;
    const int qi = tid >> 2;
    const int kbase = (tid & 3) * 16;
    const int dbase = kbase;

    // load Q tile
#pragma unroll
    for (int i = 0; i < 16; i++) {
        int lid = tid + i * 256;
        int r = lid >> 6, d = lid & 63;
        int s = qt * 64 + r;
        Qs[r * 65 + d] = (s < SEQ) ? qkv[((size_t)(b * SEQ + s)) * (3 * INNER) + h * DH + d] : 0.f;
    }
    if (tid < 64) { mrow[tid] = -1e30f; lrow[tid] = 0.f; }
    float oacc[16];
#pragma unroll
    for (int i = 0; i < 16; i++) oacc[i] = 0.f;
    __syncthreads();

    for (int kt = 0; kt < 13; kt++) {
#pragma unroll
        for (int i = 0; i < 16; i++) {
            int lid = tid + i * 256;
            int r = lid >> 6, d = lid & 63;
            int s = kt * 64 + r;
            size_t base = ((size_t)(b * SEQ + (s < SEQ ? s : 0))) * (3 * INNER) + h * DH + d;
            Ks[r * 65 + d] = (s < SEQ) ? qkv[base + INNER] : 0.f;
            Vs[r * 65 + d] = (s < SEQ) ? qkv[base + 2 * INNER] : 0.f;
        }
        __syncthreads();

        // scores: thread owns (qi, kbase..kbase+15)
        float sreg[16];
#pragma unroll
        for (int j = 0; j < 16; j++) sreg[j] = 0.f;
        for (int d = 0; d < 64; d++) {
            float q = Qs[qi * 65 + d];
#pragma unroll
            for (int j = 0; j < 16; j++) sreg[j] = fmaf(q, Ks[(kbase + j) * 65 + d], sreg[j]);
        }
#pragma unroll
        for (int j = 0; j < 16; j++) {
            int kg = kt * 64 + kbase + j;
            Ps[qi * 65 + kbase + j] = (kg < SEQ) ? sreg[j] * 0.125f : -1e30f;
        }
        __syncthreads();

        // row softmax update
        if (tid < 64) {
            int row = tid;
            float rm = -1e30f;
            for (int kj = 0; kj < 64; kj++) rm = fmaxf(rm, Ps[row * 65 + kj]);
            float mold = mrow[row];
            float mnew = fmaxf(mold, rm);
            float corr = expf(mold - mnew);
            float ssum = 0.f;
            for (int kj = 0; kj < 64; kj++) {
                float p = expf(Ps[row * 65 + kj] - mnew);
                Ps[row * 65 + kj] = p;
                ssum += p;
            }
            lrow[row] = lrow[row] * corr + ssum;
            mrow[row] = mnew;
            crow[row] = corr;
        }
        __syncthreads();

        // accumulate O
        float corr = crow[qi];
#pragma unroll
        for (int i = 0; i < 16; i++) oacc[i] *= corr;
        for (int kj = 0; kj < 64; kj++) {
            float p = Ps[qi * 65 + kj];
            const float* vrow = &Vs[kj * 65 + dbase];
#pragma unroll
            for (int i = 0; i < 16; i++) oacc[i] = fmaf(p, vrow[i], oacc[i]);
        }
        __syncthreads();
    }

    int s = qt * 64 + qi;
    if (s < SEQ) {
        float inv = 1.0f / lrow[qi];
        float* orow = o + ((size_t)(b * SEQ + s)) * INNER + h * DH + dbase;
#pragma unroll
        for (int i = 0; i < 16; i++) orow[i] = oacc[i] * inv;
    }
}

// ---------------- max over sequence ----------------
__global__ void maxpool_kernel(const float* __restrict__ x, float* __restrict__ o) {
    const int b = blockIdx.x, d = threadIdx.x;
    float m = -1e30f;
    for (int s = 0; s < SEQ; s++) m = fmaxf(m, x[((size_t)(b * SEQ + s)) * DIM + d]);
    o[b * DIM + d] = m;
}

// ---------------- head softmax @ anchors ----------------
__global__ void head_kernel(const float* __restrict__ h2, float* __restrict__ out) {
    const int bg = blockIdx.x;
    const int b = bg / 17, g = bg % 17;
    const int tid = threadIdx.x;  // 64
    float v = h2[b * OUTD + g * 64 + tid];
    __shared__ float wred[2];
    __shared__ float wts[64];
    float m = v;
    for (int off = 16; off; off >>= 1) m = fmaxf(m, __shfl_xor_sync(0xffffffffu, m, off));
    if ((tid & 31) == 0) wred[tid >> 5] = m;
    __syncthreads();
    m = fmaxf(wred[0], wred[1]);
    float e = expf(v - m);
    float s = e;
    for (int off = 16; off; off >>= 1) s += __shfl_xor_sync(0xffffffffu, s, off);
    __syncthreads();
    if ((tid & 31) == 0) wred[tid >> 5] = s;
    __syncthreads();
    float tot = wred[0] + wred[1];
    wts[tid] = e / tot;
    __syncthreads();
    if (tid < 3) {
        float acc = 0.f;
        for (int j = 0; j < 64; j++) {
            float ac = (tid == 0) ? (-1.5f + (float)(j >> 4))
                     : (tid == 1) ? (-1.5f + (float)((j >> 2) & 3))
                                  : (-1.5f + (float)(j & 3));
            acc += wts[j] * ac;
        }
        out[(size_t)(b * 17 + g) * 3 + tid] = acc;
    }
}

// ---------------- launch ----------------
#define FPS_SMEM (NTOT * 4 * 4)
#define ATTN_SMEM ((64 * 65 * 4 + 3 * 64) * 4)

extern "C" void kernel_launch(void* const* d_in, const int* in_sizes, int n_in,
                              void* d_out, int out_size) {
    const float* points     = (const float*)d_in[0];
    const float* conv_d_w   = (const float*)d_in[1];
    const float* conv_f_w   = (const float*)d_in[2];
    const float* pos_w      = (const float*)d_in[3];
    const float* pos_b      = (const float*)d_in[4];
    const float* ln1_g      = (const float*)d_in[5];
    const float* ln1_b      = (const float*)d_in[6];
    const float* qkv_w      = (const float*)d_in[7];
    const float* attn_out_w = (const float*)d_in[8];
    const float* attn_out_b = (const float*)d_in[9];
    const float* ln2_g      = (const float*)d_in[10];
    const float* ln2_b      = (const float*)d_in[11];
    const float* ff1_w      = (const float*)d_in[12];
    const float* ff1_b      = (const float*)d_in[13];
    const float* ff2_w      = (const float*)d_in[14];
    const float* ff2_b      = (const float*)d_in[15];
    const float* head_ln_g  = (const float*)d_in[16];
    const float* head_ln_b  = (const float*)d_in[17];
    const float* head1_w    = (const float*)d_in[18];
    const float* head1_b    = (const float*)d_in[19];
    const float* head2_w    = (const float*)d_in[20];
    const float* head2_b    = (const float*)d_in[21];
    float* out = (float*)d_out;

    static bool inited = false;
    static float *p_axyz, *p_x, *p_xn, *p_qkv, *p_att, *p_ff1, *p_pool, *p_pooln, *p_h1, *p_h2;
    if (!inited) {
        cudaGetSymbolAddress((void**)&p_axyz, g_axyz);
        cudaGetSymbolAddress((void**)&p_x, g_x);
        cudaGetSymbolAddress((void**)&p_xn, g_xn);
        cudaGetSymbolAddress((void**)&p_qkv, g_qkv);
        cudaGetSymbolAddress((void**)&p_att, g_att);
        cudaGetSymbolAddress((void**)&p_ff1, g_ff1);
        cudaGetSymbolAddress((void**)&p_pool, g_pool);
        cudaGetSymbolAddress((void**)&p_pooln, g_pooln);
        cudaGetSymbolAddress((void**)&p_h1, g_h1);
        cudaGetSymbolAddress((void**)&p_h2, g_h2);
        cudaFuncSetAttribute(fps_kernel, cudaFuncAttributeMaxDynamicSharedMemorySize, FPS_SMEM);
        cudaFuncSetAttribute(attn_kernel, cudaFuncAttributeMaxDynamicSharedMemorySize, ATTN_SMEM);
        inited = true;
    }

    // 1. FPS anchors
    fps_kernel<<<BD * NF, 512, FPS_SMEM>>>(points, p_axyz);
    // 2. grouping + conv + max + positional embed -> x
    group_kernel<<<dim3(MM, NF, BD), 256>>>(points, conv_d_w, conv_f_w, pos_w, pos_b, p_axyz, p_x);

    // 3. transformer
    const int GB_M = (ROWS + 63) / 64;  // 98
    for (int l = 0; l < DEPTH; l++) {
        ln_kernel<<<ROWS, 128>>>(p_x, ln1_g + l * DIM, ln1_b + l * DIM, p_xn);
        gemm_kernel<false, false, false><<<dim3(3 * INNER / 64, GB_M), 256>>>(
            p_xn, qkv_w + (size_t)l * DIM * 3 * INNER, nullptr, nullptr, p_qkv, ROWS, DIM, 3 * INNER);
        attn_kernel<<<dim3(13, HEADS, BD), 256, ATTN_SMEM>>>(p_qkv, p_att);
        gemm_kernel<true, false, true><<<dim3(DIM / 64, GB_M), 256>>>(
            p_att, attn_out_w + (size_t)l * INNER * DIM, attn_out_b + l * DIM, p_x, p_x, ROWS, INNER, DIM);
        ln_kernel<<<ROWS, 128>>>(p_x, ln2_g + l * DIM, ln2_b + l * DIM, p_xn);
        gemm_kernel<true, true, false><<<dim3(MLP / 64, GB_M), 256>>>(
            p_xn, ff1_w + (size_t)l * DIM * MLP, ff1_b + l * MLP, nullptr, p_ff1, ROWS, DIM, MLP);
        gemm_kernel<true, false, true><<<dim3(DIM / 64, GB_M), 256>>>(
            p_ff1, ff2_w + (size_t)l * MLP * DIM, ff2_b + l * DIM, p_x, p_x, ROWS, MLP, DIM);
    }

    // 4. head
    maxpool_kernel<<<BD, DIM>>>(p_x, p_pool);
    ln_kernel<<<BD, 128>>>(p_pool, head_ln_g, head_ln_b, p_pooln);
    gemm_kernel<true, true, false><<<dim3(MLP / 64, 1), 256>>>(p_pooln, head1_w, head1_b, nullptr, p_h1, BD, DIM, MLP);
    gemm_kernel<true, false, false><<<dim3(OUTD / 64, 1), 256>>>(p_h1, head2_w, head2_b, nullptr, p_h2, BD, MLP, OUTD);
    head_kernel<<<BD * 17, 64>>>(p_h2, out);
}

// round 5
// speedup vs baseline: 1.8478x; 1.8478x over previous
#include <cuda_runtime.h>
#include <cuda_bf16.h>
#include <math.h>

// ---------------- problem constants ----------------
#define BD 8
#define LD 5
#define NP 4096
#define NANCH 64
#define NTOT 4160          // NP + NANCH
#define MM 260             // NTOT / 16
#define NF 3
#define SEQ 780            // NF*MM
#define ROWS 6240          // BD*SEQ
#define DIM 512
#define HEADS 8
#define DH 64
#define INNER 512
#define MLP 1024
#define OUTD 1088
#define KNN 32
#define DEPTH 5

// ---------------- scratch (device globals; no allocation allowed) ----------------
__device__ float g_axyz[BD * NF * MM * 3];
__device__ float g_x[ROWS * DIM];
__device__ float g_xn[ROWS * DIM];
__device__ float g_qkv[ROWS * 3 * INNER];
__device__ float g_att[ROWS * INNER];
__device__ float g_ff1[ROWS * MLP];
__device__ float g_pmax[BD * 13 * DIM];
__device__ float g_pool[BD * DIM];
__device__ float g_pooln[BD * DIM];
__device__ float g_h1[BD * MLP];
__device__ float g_h2[BD * OUTD];

// ---------------- helpers ----------------
__device__ __forceinline__ void get_pt(const float* __restrict__ pts, int b, int layer, int j,
                                       float& x, float& y, float& z) {
    if (j < NP) {
        const float* p = pts + ((size_t)((b * LD + layer) * NP + j)) * 3;
        x = p[0]; y = p[1]; z = p[2];
    } else {
        int i = j - NP;
        x = -1.5f + (float)(i >> 4);
        y = -1.5f + (float)((i >> 2) & 3);
        z = -1.5f + (float)(i & 3);
    }
}

__device__ __forceinline__ float gelu_f(float x) {
    return 0.5f * x * (1.0f + erff(x * 0.7071067811865476f));
}

// ---------------- FPS: one block per (b, frame) ----------------
__global__ void fps_kernel(const float* __restrict__ points, float* __restrict__ axyz) {
    const int bf = blockIdx.x;
    const int b = bf / NF, f = bf % NF;
    const int layer = 2 * f;  // frames[:, 1+2f] == pts[:, 2f]
    extern __shared__ float sm[];
    float* sx = sm;
    float* sy = sm + NTOT;
    float* sz = sm + 2 * NTOT;
    float* dist = sm + 3 * NTOT;
    __shared__ float rv[16];
    __shared__ int ri[16];
    __shared__ int s_last;
    int tid = threadIdx.x;

    for (int j = tid; j < NTOT; j += 512) {
        float x, y, z;
        get_pt(points, b, layer, j, x, y, z);
        sx[j] = x; sy[j] = y; sz[j] = z;
        dist[j] = 1e10f;
    }
    __syncthreads();

    int last = 0;
    float* aout = axyz + (size_t)bf * MM * 3;
    for (int s = 0; s < MM; s++) {
        float lx = sx[last], ly = sy[last], lz = sz[last];
        if (tid == 0) { aout[s * 3 + 0] = lx; aout[s * 3 + 1] = ly; aout[s * 3 + 2] = lz; }
        float bv = -1.0f; int bi = 0x7fffffff;
        for (int j = tid; j < NTOT; j += 512) {
            float dx = sx[j] - lx, dy = sy[j] - ly, dz = sz[j] - lz;
            // match XLA: no fma contraction in the distance
            float d = __fadd_rn(__fadd_rn(__fmul_rn(dx, dx), __fmul_rn(dy, dy)), __fmul_rn(dz, dz));
            float nd = fminf(dist[j], d);
            dist[j] = nd;
            if (nd > bv) { bv = nd; bi = j; }  // ascending j keeps lowest index on ties
        }
        for (int off = 16; off; off >>= 1) {
            float ov = __shfl_down_sync(0xffffffffu, bv, off);
            int oi = __shfl_down_sync(0xffffffffu, bi, off);
            if (ov > bv || (ov == bv && oi < bi)) { bv = ov; bi = oi; }
        }
        if ((tid & 31) == 0) { rv[tid >> 5] = bv; ri[tid >> 5] = bi; }
        __syncthreads();
        if (tid < 32) {
            float v2 = (tid < 16) ? rv[tid] : -2.0f;
            int i2 = (tid < 16) ? ri[tid] : 0x7fffffff;
            for (int off = 8; off; off >>= 1) {
                float ov = __shfl_down_sync(0xffffffffu, v2, off);
                int oi = __shfl_down_sync(0xffffffffu, i2, off);
                if (ov > v2 || (ov == v2 && oi < i2)) { v2 = ov; i2 = oi; }
            }
            if (tid == 0) s_last = i2;
        }
        __syncthreads();
        last = s_last;
    }
}

// ---------------- ball query + conv + maxpool + pos embed ----------------
__global__ void group_kernel(const float* __restrict__ points,
                             const float* __restrict__ conv_d_w,
                             const float* __restrict__ conv_f_w,
                             const float* __restrict__ pos_w,
                             const float* __restrict__ pos_b,
                             const float* __restrict__ axyz,
                             float* __restrict__ xout) {
    const int m = blockIdx.x, f = blockIdx.y, b = blockIdx.z;
    __shared__ float gpts[3][KNN][3];
    __shared__ int scnt[3];
    __shared__ float sa[3];
    const int tid = threadIdx.x;

    if (tid < 3) sa[tid] = axyz[((size_t)((b * NF + f) * MM + m)) * 3 + tid];
    __syncthreads();
    const float ax = sa[0], ay = sa[1], az = sa[2];

    const int w = tid >> 5, lane = tid & 31;
    if (w < 3) {
        int layer = 2 * f - 1 + w;
        layer = layer < 0 ? 0 : (layer > 4 ? 4 : layer);
        const float R2 = (float)(0.7 * 0.7);  // rounds like the python-scalar threshold
        int cnt = 0;
        for (int j0 = 0; j0 < NTOT && cnt < KNN; j0 += 32) {
            int j = j0 + lane;
            float px, py, pz;
            get_pt(points, b, layer, j, px, py, pz);
            float dx = px - ax, dy = py - ay, dz = pz - az;
            float d2 = __fadd_rn(__fadd_rn(__fmul_rn(dx, dx), __fmul_rn(dy, dy)), __fmul_rn(dz, dz));
            unsigned mask = __ballot_sync(0xffffffffu, d2 < R2);
            while (mask && cnt < KNN) {
                int src = __ffs(mask) - 1;
                mask &= mask - 1;
                float gx = __shfl_sync(0xffffffffu, px, src);
                float gy = __shfl_sync(0xffffffffu, py, src);
                float gz = __shfl_sync(0xffffffffu, pz, src);
                if (lane == 0) { gpts[w][cnt][0] = gx; gpts[w][cnt][1] = gy; gpts[w][cnt][2] = gz; }
                cnt++;
            }
        }
        if (cnt == 0) {
            if (lane == 0) {
                float gx, gy, gz;
                get_pt(points, b, layer, 0, gx, gy, gz);
                gpts[w][0][0] = gx; gpts[w][0][1] = gy; gpts[w][0][2] = gz;
            }
            cnt = 1;
        }
        if (lane == 0) scnt[w] = cnt;
    }
    __syncthreads();

    const int cs[3] = {scnt[0], scnt[1], scnt[2]};
#pragma unroll
    for (int dd = 0; dd < 2; dd++) {
        int d = tid + dd * 256;
        float wf0 = conv_f_w[d * 3 + 0], wf1 = conv_f_w[d * 3 + 1], wf2 = conv_f_w[d * 3 + 2];
        float wd0 = conv_d_w[d * 4 + 0], wd1 = conv_d_w[d * 4 + 1], wd2 = conv_d_w[d * 4 + 2], wd3 = conv_d_w[d * 4 + 3];
        float ws0 = wf0 + wd0, ws1 = wf1 + wd1, ws2 = wf2 + wd2;
        float adot = ax * wd0 + ay * wd1 + az * wd2;
        float maxv = -1e30f;
        for (int ww = 0; ww < 3; ww++) {
            float dt = (float)(ww - 1);
            float base = dt * wd3 - adot;
            int cn = cs[ww];
            for (int k = 0; k < cn; k++) {
                float gx = gpts[ww][k][0], gy = gpts[ww][k][1], gz = gpts[ww][k][2];
                float v = fmaf(gx, ws0, fmaf(gy, ws1, fmaf(gz, ws2, base)));
                maxv = fmaxf(maxv, v);
            }
        }
        float pw0 = pos_w[d * 4 + 0], pw1 = pos_w[d * 4 + 1], pw2 = pos_w[d * 4 + 2], pw3 = pos_w[d * 4 + 3];
        float t = (float)(f + 1);
        float outv = maxv + ax * pw0 + ay * pw1 + az * pw2 + t * pw3 + pos_b[d];
        xout[((size_t)(b * SEQ + f * MM + m)) * DIM + d] = outv;
    }
}

// ---------------- LayerNorm (rows x 512), 128 threads ----------------
__global__ void ln_kernel(const float* __restrict__ x, const float* __restrict__ gg,
                          const float* __restrict__ bb, float* __restrict__ y) {
    const int r = blockIdx.x;
    const float* xr = x + (size_t)r * DIM;
    float* yr = y + (size_t)r * DIM;
    const int tid = threadIdx.x;
    float v[4];
    float s = 0.f;
#pragma unroll
    for (int i = 0; i < 4; i++) { v[i] = xr[tid + i * 128]; s += v[i]; }
    __shared__ float red[4];
    __shared__ float s_stat;
    for (int off = 16; off; off >>= 1) s += __shfl_down_sync(0xffffffffu, s, off);
    if ((tid & 31) == 0) red[tid >> 5] = s;
    __syncthreads();
    if (tid == 0) s_stat = (red[0] + red[1] + red[2] + red[3]) * (1.0f / DIM);
    __syncthreads();
    float mu = s_stat;
    float q = 0.f;
#pragma unroll
    for (int i = 0; i < 4; i++) { float d = v[i] - mu; q += d * d; }
    __syncthreads();
    for (int off = 16; off; off >>= 1) q += __shfl_down_sync(0xffffffffu, q, off);
    if ((tid & 31) == 0) red[tid >> 5] = q;
    __syncthreads();
    if (tid == 0) s_stat = (red[0] + red[1] + red[2] + red[3]) * (1.0f / DIM);
    __syncthreads();
    float inv = rsqrtf(s_stat + 1e-5f);
#pragma unroll
    for (int i = 0; i < 4; i++) {
        int c = tid + i * 128;
        yr[c] = (v[i] - mu) * inv * gg[c] + bb[c];
    }
}

// ---------------- fp32 tiled GEMM: 128x64 tile, 8x4 per thread ----------------
template <bool WITH_BIAS, bool WITH_GELU, bool WITH_RES>
__global__ __launch_bounds__(256)
void gemm128(const float* __restrict__ A, const float* __restrict__ W,
             const float* __restrict__ bias, const float* __restrict__ Rd,
             float* __restrict__ C, int Rr, int Kd, int Cn) {
    __shared__ float As[8][132];
    __shared__ float Bs[8][64];
    const int bn = blockIdx.x * 64;
    const int bm = blockIdx.y * 128;
    const int tid = threadIdx.x;
    const int tx = tid & 15, ty = tid >> 4;
    float acc[8][4];
#pragma unroll
    for (int u = 0; u < 8; u++)
#pragma unroll
        for (int v = 0; v < 4; v++) acc[u][v] = 0.f;

    const int arow = bm + (tid >> 1);
    const int kh = (tid & 1) * 4;
    const bool aval = arow < Rr;
    const int am = tid >> 1;
    // B loader: 128 float4 per k-chunk (8 rows x 16 float4); tid<128 active
    const int bk = tid >> 4;          // 0..15 -> row pairs? use tid<128: row = tid>>4 (0..7 for tid<128)
    const int bn4 = (tid & 15) * 4;

    for (int k0 = 0; k0 < Kd; k0 += 8) {
        float4 av = make_float4(0.f, 0.f, 0.f, 0.f);
        if (aval) av = *reinterpret_cast<const float4*>(A + (size_t)arow * Kd + k0 + kh);
        As[kh + 0][am] = av.x; As[kh + 1][am] = av.y; As[kh + 2][am] = av.z; As[kh + 3][am] = av.w;
        if (tid < 128) {
            float4 bv = *reinterpret_cast<const float4*>(W + (size_t)(k0 + bk) * Cn + bn + bn4);
            *reinterpret_cast<float4*>(&Bs[bk][bn4]) = bv;
        }
        __syncthreads();
#pragma unroll
        for (int kk = 0; kk < 8; kk++) {
            float4 a0 = *reinterpret_cast<const float4*>(&As[kk][ty * 8]);
            float4 a1 = *reinterpret_cast<const float4*>(&As[kk][ty * 8 + 4]);
            float4 b4 = *reinterpret_cast<const float4*>(&Bs[kk][tx * 4]);
            float aa[8] = {a0.x, a0.y, a0.z, a0.w, a1.x, a1.y, a1.z, a1.w};
            float bb4[4] = {b4.x, b4.y, b4.z, b4.w};
#pragma unroll
            for (int u = 0; u < 8; u++)
#pragma unroll
                for (int v = 0; v < 4; v++) acc[u][v] = fmaf(aa[u], bb4[v], acc[u][v]);
        }
        __syncthreads();
    }
#pragma unroll
    for (int u = 0; u < 8; u++) {
        int row = bm + ty * 8 + u;
        if (row < Rr) {
#pragma unroll
            for (int v = 0; v < 4; v++) {
                int col = bn + tx * 4 + v;
                float c = acc[u][v];
                if (WITH_BIAS) c += bias[col];
                if (WITH_GELU) c = gelu_f(c);
                if (WITH_RES) c += Rd[(size_t)row * Cn + col];
                C[(size_t)row * Cn + col] = c;
            }
        }
    }
}

// ---------------- attention: flash-style, 4q x 4k register blocking ----------------
// dyn smem: Qs[64][65], Ks[64][65], Vs[64][64], Ps[64][65]
__global__ __launch_bounds__(256)
void attn_kernel(const float* __restrict__ qkv, float* __restrict__ o) {
    extern __shared__ float sm[];
    float* Qs = sm;                  // 64*65
    float* Ks = Qs + 64 * 65;        // 64*65
    float* Vs = Ks + 64 * 65;        // 64*64 (unpadded for float4)
    float* Ps = Vs + 64 * 64;        // 64*65

    const int qt = blockIdx.x, h = blockIdx.y, b = blockIdx.z;
    const int tid = threadIdx.x;
    const int tx = tid & 15, ty = tid >> 4;

#pragma unroll
    for (int i = 0; i < 16; i++) {
        int lid = tid + i * 256;
        int r = lid >> 6, d = lid & 63;
        int s = qt * 64 + r;
        Qs[r * 65 + d] = (s < SEQ) ? qkv[((size_t)(b * SEQ + s)) * (3 * INNER) + h * DH + d] : 0.f;
    }
    float oacc[4][4];
    float mcur[4], lcur[4];
#pragma unroll
    for (int u = 0; u < 4; u++) {
        mcur[u] = -1e30f; lcur[u] = 0.f;
#pragma unroll
        for (int v = 0; v < 4; v++) oacc[u][v] = 0.f;
    }
    __syncthreads();

    for (int kt = 0; kt < 13; kt++) {
#pragma unroll
        for (int i = 0; i < 16; i++) {
            int lid = tid + i * 256;
            int r = lid >> 6, d = lid & 63;
            int s = kt * 64 + r;
            size_t base = ((size_t)(b * SEQ + (s < SEQ ? s : 0))) * (3 * INNER) + h * DH + d;
            Ks[r * 65 + d] = (s < SEQ) ? qkv[base + INNER] : 0.f;
            Vs[r * 64 + d] = (s < SEQ) ? qkv[base + 2 * INNER] : 0.f;
        }
        __syncthreads();

        float sreg[4][4];
#pragma unroll
        for (int u = 0; u < 4; u++)
#pragma unroll
            for (int v = 0; v < 4; v++) sreg[u][v] = 0.f;
#pragma unroll 2
        for (int d = 0; d < 64; d++) {
            float qv[4], kv[4];
#pragma unroll
            for (int u = 0; u < 4; u++) qv[u] = Qs[(ty * 4 + u) * 65 + d];
#pragma unroll
            for (int v = 0; v < 4; v++) kv[v] = Ks[(tx * 4 + v) * 65 + d];
#pragma unroll
            for (int u = 0; u < 4; u++)
#pragma unroll
                for (int v = 0; v < 4; v++) sreg[u][v] = fmaf(qv[u], kv[v], sreg[u][v]);
        }
#pragma unroll
        for (int u = 0; u < 4; u++)
#pragma unroll
            for (int v = 0; v < 4; v++) {
                int kg = kt * 64 + tx * 4 + v;
                sreg[u][v] = (kg < SEQ) ? sreg[u][v] * 0.125f : -1e30f;
            }

        float corr[4];
#pragma unroll
        for (int u = 0; u < 4; u++) {
            float rm = fmaxf(fmaxf(sreg[u][0], sreg[u][1]), fmaxf(sreg[u][2], sreg[u][3]));
#pragma unroll
            for (int off = 1; off < 16; off <<= 1) rm = fmaxf(rm, __shfl_xor_sync(0xffffffffu, rm, off));
            float mnew = fmaxf(mcur[u], rm);
            corr[u] = __expf(mcur[u] - mnew);
            float ssum = 0.f;
#pragma unroll
            for (int v = 0; v < 4; v++) {
                float p = __expf(sreg[u][v] - mnew);
                Ps[(ty * 4 + u) * 65 + tx * 4 + v] = p;
                ssum += p;
            }
#pragma unroll
            for (int off = 1; off < 16; off <<= 1) ssum += __shfl_xor_sync(0xffffffffu, ssum, off);
            lcur[u] = lcur[u] * corr[u] + ssum;
            mcur[u] = mnew;
        }
        __syncwarp();

#pragma unroll
        for (int u = 0; u < 4; u++)
#pragma unroll
            for (int v = 0; v < 4; v++) oacc[u][v] *= corr[u];
#pragma unroll 2
        for (int k = 0; k < 64; k++) {
            float4 vv = *reinterpret_cast<const float4*>(&Vs[k * 64 + tx * 4]);
            float vvv[4] = {vv.x, vv.y, vv.z, vv.w};
#pragma unroll
            for (int u = 0; u < 4; u++) {
                float p = Ps[(ty * 4 + u) * 65 + k];
#pragma unroll
                for (int v = 0; v < 4; v++) oacc[u][v] = fmaf(p, vvv[v], oacc[u][v]);
            }
        }
        __syncthreads();
    }

#pragma unroll
    for (int u = 0; u < 4; u++) {
        int s = qt * 64 + ty * 4 + u;
        if (s < SEQ) {
            float inv = 1.0f / lcur[u];
#pragma unroll
            for (int v = 0; v < 4; v++)
                o[((size_t)(b * SEQ + s)) * INNER + h * DH + tx * 4 + v] = oacc[u][v] * inv;
        }
    }
}

// ---------------- max over sequence: two stage ----------------
__global__ void maxpool1_kernel(const float* __restrict__ x, float* __restrict__ part) {
    const int c = blockIdx.x, b = blockIdx.y;
    const int d = threadIdx.x;  // 512
    const int s0 = c * 60;
    float m0 = -1e30f, m1 = -1e30f, m2 = -1e30f, m3 = -1e30f;
    for (int s = s0; s < s0 + 60; s += 4) {
        m0 = fmaxf(m0, x[((size_t)(b * SEQ + s + 0)) * DIM + d]);
        m1 = fmaxf(m1, x[((size_t)(b * SEQ + s + 1)) * DIM + d]);
        m2 = fmaxf(m2, x[((size_t)(b * SEQ + s + 2)) * DIM + d]);
        m3 = fmaxf(m3, x[((size_t)(b * SEQ + s + 3)) * DIM + d]);
    }
    part[((size_t)(b * 13 + c)) * DIM + d] = fmaxf(fmaxf(m0, m1), fmaxf(m2, m3));
}

__global__ void maxpool2_kernel(const float* __restrict__ part, float* __restrict__ o) {
    const int b = blockIdx.x, d = threadIdx.x;
    float m = -1e30f;
#pragma unroll
    for (int c = 0; c < 13; c++) m = fmaxf(m, part[((size_t)(b * 13 + c)) * DIM + d]);
    o[b * DIM + d] = m;
}

// ---------------- head softmax @ anchors ----------------
__global__ void head_kernel(const float* __restrict__ h2, float* __restrict__ out) {
    const int bg = blockIdx.x;
    const int b = bg / 17, g = bg % 17;
    const int tid = threadIdx.x;  // 64
    float v = h2[b * OUTD + g * 64 + tid];
    __shared__ float wred[2];
    __shared__ float wts[64];
    float m = v;
    for (int off = 16; off; off >>= 1) m = fmaxf(m, __shfl_xor_sync(0xffffffffu, m, off));
    if ((tid & 31) == 0) wred[tid >> 5] = m;
    __syncthreads();
    m = fmaxf(wred[0], wred[1]);
    float e = expf(v - m);
    float s = e;
    for (int off = 16; off; off >>= 1) s += __shfl_xor_sync(0xffffffffu, s, off);
    __syncthreads();
    if ((tid & 31) == 0) wred[tid >> 5] = s;
    __syncthreads();
    float tot = wred[0] + wred[1];
    wts[tid] = e / tot;
    __syncthreads();
    if (tid < 3) {
        float acc = 0.f;
        for (int j = 0; j < 64; j++) {
            float ac = (tid == 0) ? (-1.5f + (float)(j >> 4))
                     : (tid == 1) ? (-1.5f + (float)((j >> 2) & 3))
                                  : (-1.5f + (float)(j & 3));
            acc += wts[j] * ac;
        }
        out[(size_t)(b * 17 + g) * 3 + tid] = acc;
    }
}

// ---------------- launch ----------------
#define FPS_SMEM (NTOT * 4 * 4)
#define ATTN_SMEM ((64 * 65 * 3 + 64 * 64) * 4)

extern "C" void kernel_launch(void* const* d_in, const int* in_sizes, int n_in,
                              void* d_out, int out_size) {
    const float* points     = (const float*)d_in[0];
    const float* conv_d_w   = (const float*)d_in[1];
    const float* conv_f_w   = (const float*)d_in[2];
    const float* pos_w      = (const float*)d_in[3];
    const float* pos_b      = (const float*)d_in[4];
    const float* ln1_g      = (const float*)d_in[5];
    const float* ln1_b      = (const float*)d_in[6];
    const float* qkv_w      = (const float*)d_in[7];
    const float* attn_out_w = (const float*)d_in[8];
    const float* attn_out_b = (const float*)d_in[9];
    const float* ln2_g      = (const float*)d_in[10];
    const float* ln2_b      = (const float*)d_in[11];
    const float* ff1_w      = (const float*)d_in[12];
    const float* ff1_b      = (const float*)d_in[13];
    const float* ff2_w      = (const float*)d_in[14];
    const float* ff2_b      = (const float*)d_in[15];
    const float* head_ln_g  = (const float*)d_in[16];
    const float* head_ln_b  = (const float*)d_in[17];
    const float* head1_w    = (const float*)d_in[18];
    const float* head1_b    = (const float*)d_in[19];
    const float* head2_w    = (const float*)d_in[20];
    const float* head2_b    = (const float*)d_in[21];
    float* out = (float*)d_out;

    static bool inited = false;
    static float *p_axyz, *p_x, *p_xn, *p_qkv, *p_att, *p_ff1, *p_pmax, *p_pool, *p_pooln, *p_h1, *p_h2;
    if (!inited) {
        cudaGetSymbolAddress((void**)&p_axyz, g_axyz);
        cudaGetSymbolAddress((void**)&p_x, g_x);
        cudaGetSymbolAddress((void**)&p_xn, g_xn);
        cudaGetSymbolAddress((void**)&p_qkv, g_qkv);
        cudaGetSymbolAddress((void**)&p_att, g_att);
        cudaGetSymbolAddress((void**)&p_ff1, g_ff1);
        cudaGetSymbolAddress((void**)&p_pmax, g_pmax);
        cudaGetSymbolAddress((void**)&p_pool, g_pool);
        cudaGetSymbolAddress((void**)&p_pooln, g_pooln);
        cudaGetSymbolAddress((void**)&p_h1, g_h1);
        cudaGetSymbolAddress((void**)&p_h2, g_h2);
        cudaFuncSetAttribute(fps_kernel, cudaFuncAttributeMaxDynamicSharedMemorySize, FPS_SMEM);
        cudaFuncSetAttribute(attn_kernel, cudaFuncAttributeMaxDynamicSharedMemorySize, ATTN_SMEM);
        inited = true;
    }

    // 1. FPS anchors
    fps_kernel<<<BD * NF, 512, FPS_SMEM>>>(points, p_axyz);
    // 2. grouping + conv + max + positional embed -> x
    group_kernel<<<dim3(MM, NF, BD), 256>>>(points, conv_d_w, conv_f_w, pos_w, pos_b, p_axyz, p_x);

    // 3. transformer
    const int GB_M = (ROWS + 127) / 128;  // 49
    for (int l = 0; l < DEPTH; l++) {
        ln_kernel<<<ROWS, 128>>>(p_x, ln1_g + l * DIM, ln1_b + l * DIM, p_xn);
        gemm128<false, false, false><<<dim3(3 * INNER / 64, GB_M), 256>>>(
            p_xn, qkv_w + (size_t)l * DIM * 3 * INNER, nullptr, nullptr, p_qkv, ROWS, DIM, 3 * INNER);
        attn_kernel<<<dim3(13, HEADS, BD), 256, ATTN_SMEM>>>(p_qkv, p_att);
        gemm128<true, false, true><<<dim3(DIM / 64, GB_M), 256>>>(
            p_att, attn_out_w + (size_t)l * INNER * DIM, attn_out_b + l * DIM, p_x, p_x, ROWS, INNER, DIM);
        ln_kernel<<<ROWS, 128>>>(p_x, ln2_g + l * DIM, ln2_b + l * DIM, p_xn);
        gemm128<true, true, false><<<dim3(MLP / 64, GB_M), 256>>>(
            p_xn, ff1_w + (size_t)l * DIM * MLP, ff1_b + l * MLP, nullptr, p_ff1, ROWS, DIM, MLP);
        gemm128<true, false, true><<<dim3(DIM / 64, GB_M), 256>>>(
            p_ff1, ff2_w + (size_t)l * MLP * DIM, ff2_b + l * DIM, p_x, p_x, ROWS, MLP, DIM);
    }

    // 4. head
    maxpool1_kernel<<<dim3(13, BD), DIM>>>(p_x, p_pmax);
    maxpool2_kernel<<<BD, DIM>>>(p_pmax, p_pool);
    ln_kernel<<<BD, 128>>>(p_pool, head_ln_g, head_ln_b, p_pooln);
    gemm128<true, true, false><<<dim3(MLP / 64, 1), 256>>>(p_pooln, head1_w, head1_b, nullptr, p_h1, BD, DIM, MLP);
    gemm128<true, false, false><<<dim3(OUTD / 64, 1), 256>>>(p_h1, head2_w, head2_b, nullptr, p_h2, BD, MLP, OUTD);
    head_kernel<<<BD * 17, 64>>>(p_h2, out);
}

// round 7
// speedup vs baseline: 2.7723x; 1.5003x over previous
#include <cuda_runtime.h>
#include <cuda_bf16.h>
#include <math.h>
#include <stdint.h>

// ---------------- problem constants ----------------
#define BD 8
#define LD 5
#define NP 4096
#define NANCH 64
#define NTOT 4160          // NP + NANCH
#define MM 260             // NTOT / 16
#define NF 3
#define SEQ 780            // NF*MM
#define ROWS 6240          // BD*SEQ
#define DIM 512
#define HEADS 8
#define DH 64
#define INNER 512
#define MLP 1024
#define OUTD 1088
#define KNN 32
#define DEPTH 5

// ---------------- scratch (device globals; no allocation allowed) ----------------
__device__ float g_axyz[BD * NF * MM * 3];
__device__ float g_x[ROWS * DIM];
__device__ float g_xn[ROWS * DIM];
__device__ float g_qkv[ROWS * 3 * INNER];
__device__ float g_att[ROWS * INNER];
__device__ float g_ff1[ROWS * MLP];
__device__ float g_pmax[BD * 13 * DIM];
__device__ float g_pool[BD * DIM];
__device__ float g_pooln[BD * DIM];
__device__ float g_h1[BD * MLP];
__device__ float g_h2[BD * OUTD];
// transposed (and tf32-rounded) weights, layout [n][k]
__device__ float g_t_qkv[DEPTH * 3 * INNER * DIM];
__device__ float g_t_ao [DEPTH * DIM * INNER];
__device__ float g_t_ff1[DEPTH * MLP * DIM];
__device__ float g_t_ff2[DEPTH * DIM * MLP];

// ---------------- helpers ----------------
__device__ __forceinline__ float to_tf32(float x) {
    uint32_t u; asm("cvt.rna.tf32.f32 %0, %1;" : "=r"(u) : "f"(x));
    return __uint_as_float(u);
}

__device__ __forceinline__ void get_pt(const float* __restrict__ pts, int b, int layer, int j,
                                       float& x, float& y, float& z) {
    if (j < NP) {
        const float* p = pts + ((size_t)((b * LD + layer) * NP + j)) * 3;
        x = p[0]; y = p[1]; z = p[2];
    } else {
        int i = j - NP;
        x = -1.5f + (float)(i >> 4);
        y = -1.5f + (float)((i >> 2) & 3);
        z = -1.5f + (float)(i & 3);
    }
}

__device__ __forceinline__ float gelu_f(float x) {
    return 0.5f * x * (1.0f + erff(x * 0.7071067811865476f));
}

__device__ __forceinline__ void mma_tf32(float* d, const uint32_t* a, const uint32_t* b) {
    asm volatile(
        "mma.sync.aligned.m16n8k8.row.col.f32.tf32.tf32.f32 "
        "{%0,%1,%2,%3}, {%4,%5,%6,%7}, {%8,%9}, {%0,%1,%2,%3};"
        : "+f"(d[0]), "+f"(d[1]), "+f"(d[2]), "+f"(d[3])
        : "r"(a[0]), "r"(a[1]), "r"(a[2]), "r"(a[3]), "r"(b[0]), "r"(b[1]));
}

// ---------------- FPS: one block per (b, frame) ----------------
__global__ void fps_kernel(const float* __restrict__ points, float* __restrict__ axyz) {
    const int bf = blockIdx.x;
    const int b = bf / NF, f = bf % NF;
    const int layer = 2 * f;
    extern __shared__ float sm[];
    float* sx = sm;
    float* sy = sm + NTOT;
    float* sz = sm + 2 * NTOT;
    float* dist = sm + 3 * NTOT;
    __shared__ float rv[16];
    __shared__ int ri[16];
    __shared__ int s_last;
    int tid = threadIdx.x;

    for (int j = tid; j < NTOT; j += 512) {
        float x, y, z;
        get_pt(points, b, layer, j, x, y, z);
        sx[j] = x; sy[j] = y; sz[j] = z;
        dist[j] = 1e10f;
    }
    __syncthreads();

    int last = 0;
    float* aout = axyz + (size_t)bf * MM * 3;
    for (int s = 0; s < MM; s++) {
        float lx = sx[last], ly = sy[last], lz = sz[last];
        if (tid == 0) { aout[s * 3 + 0] = lx; aout[s * 3 + 1] = ly; aout[s * 3 + 2] = lz; }
        float bv = -1.0f; int bi = 0x7fffffff;
        for (int j = tid; j < NTOT; j += 512) {
            float dx = sx[j] - lx, dy = sy[j] - ly, dz = sz[j] - lz;
            float d = __fadd_rn(__fadd_rn(__fmul_rn(dx, dx), __fmul_rn(dy, dy)), __fmul_rn(dz, dz));
            float nd = fminf(dist[j], d);
            dist[j] = nd;
            if (nd > bv) { bv = nd; bi = j; }
        }
        for (int off = 16; off; off >>= 1) {
            float ov = __shfl_down_sync(0xffffffffu, bv, off);
            int oi = __shfl_down_sync(0xffffffffu, bi, off);
            if (ov > bv || (ov == bv && oi < bi)) { bv = ov; bi = oi; }
        }
        if ((tid & 31) == 0) { rv[tid >> 5] = bv; ri[tid >> 5] = bi; }
        __syncthreads();
        if (tid < 32) {
            float v2 = (tid < 16) ? rv[tid] : -2.0f;
            int i2 = (tid < 16) ? ri[tid] : 0x7fffffff;
            for (int off = 8; off; off >>= 1) {
                float ov = __shfl_down_sync(0xffffffffu, v2, off);
                int oi = __shfl_down_sync(0xffffffffu, i2, off);
                if (ov > v2 || (ov == v2 && oi < i2)) { v2 = ov; i2 = oi; }
            }
            if (tid == 0) s_last = i2;
        }
        __syncthreads();
        last = s_last;
    }
}

// ---------------- ball query + conv + maxpool + pos embed ----------------
__global__ void group_kernel(const float* __restrict__ points,
                             const float* __restrict__ conv_d_w,
                             const float* __restrict__ conv_f_w,
                             const float* __restrict__ pos_w,
                             const float* __restrict__ pos_b,
                             const float* __restrict__ axyz,
                             float* __restrict__ xout) {
    const int m = blockIdx.x, f = blockIdx.y, b = blockIdx.z;
    __shared__ float gpts[3][KNN][3];
    __shared__ int scnt[3];
    __shared__ float sa[3];
    const int tid = threadIdx.x;

    if (tid < 3) sa[tid] = axyz[((size_t)((b * NF + f) * MM + m)) * 3 + tid];
    __syncthreads();
    const float ax = sa[0], ay = sa[1], az = sa[2];

    const int w = tid >> 5, lane = tid & 31;
    if (w < 3) {
        int layer = 2 * f - 1 + w;
        layer = layer < 0 ? 0 : (layer > 4 ? 4 : layer);
        const float R2 = (float)(0.7 * 0.7);
        int cnt = 0;
        for (int j0 = 0; j0 < NTOT && cnt < KNN; j0 += 32) {
            int j = j0 + lane;
            float px, py, pz;
            get_pt(points, b, layer, j, px, py, pz);
            float dx = px - ax, dy = py - ay, dz = pz - az;
            float d2 = __fadd_rn(__fadd_rn(__fmul_rn(dx, dx), __fmul_rn(dy, dy)), __fmul_rn(dz, dz));
            unsigned mask = __ballot_sync(0xffffffffu, d2 < R2);
            while (mask && cnt < KNN) {
                int src = __ffs(mask) - 1;
                mask &= mask - 1;
                float gx = __shfl_sync(0xffffffffu, px, src);
                float gy = __shfl_sync(0xffffffffu, py, src);
                float gz = __shfl_sync(0xffffffffu, pz, src);
                if (lane == 0) { gpts[w][cnt][0] = gx; gpts[w][cnt][1] = gy; gpts[w][cnt][2] = gz; }
                cnt++;
            }
        }
        if (cnt == 0) {
            if (lane == 0) {
                float gx, gy, gz;
                get_pt(points, b, layer, 0, gx, gy, gz);
                gpts[w][0][0] = gx; gpts[w][0][1] = gy; gpts[w][0][2] = gz;
            }
            cnt = 1;
        }
        if (lane == 0) scnt[w] = cnt;
    }
    __syncthreads();

    const int cs[3] = {scnt[0], scnt[1], scnt[2]};
#pragma unroll
    for (int dd = 0; dd < 2; dd++) {
        int d = tid + dd * 256;
        float wf0 = conv_f_w[d * 3 + 0], wf1 = conv_f_w[d * 3 + 1], wf2 = conv_f_w[d * 3 + 2];
        float wd0 = conv_d_w[d * 4 + 0], wd1 = conv_d_w[d * 4 + 1], wd2 = conv_d_w[d * 4 + 2], wd3 = conv_d_w[d * 4 + 3];
        float ws0 = wf0 + wd0, ws1 = wf1 + wd1, ws2 = wf2 + wd2;
        float adot = ax * wd0 + ay * wd1 + az * wd2;
        float maxv = -1e30f;
        for (int ww = 0; ww < 3; ww++) {
            float dt = (float)(ww - 1);
            float base = dt * wd3 - adot;
            int cn = cs[ww];
            for (int k = 0; k < cn; k++) {
                float gx = gpts[ww][k][0], gy = gpts[ww][k][1], gz = gpts[ww][k][2];
                float v = fmaf(gx, ws0, fmaf(gy, ws1, fmaf(gz, ws2, base)));
                maxv = fmaxf(maxv, v);
            }
        }
        float pw0 = pos_w[d * 4 + 0], pw1 = pos_w[d * 4 + 1], pw2 = pos_w[d * 4 + 2], pw3 = pos_w[d * 4 + 3];
        float t = (float)(f + 1);
        float outv = maxv + ax * pw0 + ay * pw1 + az * pw2 + t * pw3 + pos_b[d];
        xout[((size_t)(b * SEQ + f * MM + m)) * DIM + d] = outv;
    }
}

// ---------------- LayerNorm (rows x 512), 128 threads ----------------
__global__ void ln_kernel(const float* __restrict__ x, const float* __restrict__ gg,
                          const float* __restrict__ bb, float* __restrict__ y) {
    const int r = blockIdx.x;
    const float* xr = x + (size_t)r * DIM;
    float* yr = y + (size_t)r * DIM;
    const int tid = threadIdx.x;
    float v[4];
    float s = 0.f;
#pragma unroll
    for (int i = 0; i < 4; i++) { v[i] = xr[tid + i * 128]; s += v[i]; }
    __shared__ float red[4];
    __shared__ float s_stat;
    for (int off = 16; off; off >>= 1) s += __shfl_down_sync(0xffffffffu, s, off);
    if ((tid & 31) == 0) red[tid >> 5] = s;
    __syncthreads();
    if (tid == 0) s_stat = (red[0] + red[1] + red[2] + red[3]) * (1.0f / DIM);
    __syncthreads();
    float mu = s_stat;
    float q = 0.f;
#pragma unroll
    for (int i = 0; i < 4; i++) { float d = v[i] - mu; q += d * d; }
    __syncthreads();
    for (int off = 16; off; off >>= 1) q += __shfl_down_sync(0xffffffffu, q, off);
    if ((tid & 31) == 0) red[tid >> 5] = q;
    __syncthreads();
    if (tid == 0) s_stat = (red[0] + red[1] + red[2] + red[3]) * (1.0f / DIM);
    __syncthreads();
    float inv = rsqrtf(s_stat + 1e-5f);
#pragma unroll
    for (int i = 0; i < 4; i++) {
        int c = tid + i * 128;
        yr[c] = (v[i] - mu) * inv * gg[c] + bb[c];
    }
}

// ---------------- weight transpose (+tf32 round): Wt[n][k] = tf32(W[k][n]) ----------------
__global__ void wtrans_kernel(const float* __restrict__ W, float* __restrict__ Wt, int K, int N) {
    __shared__ float t[32][33];
    const int n0 = blockIdx.x * 32, k0 = blockIdx.y * 32;
    const int x = threadIdx.x, y = threadIdx.y;  // 32 x 8
#pragma unroll
    for (int i = y; i < 32; i += 8)
        t[i][x] = W[(size_t)(k0 + i) * N + n0 + x];
    __syncthreads();
#pragma unroll
    for (int i = y; i < 32; i += 8)
        Wt[(size_t)(n0 + i) * K + k0 + x] = to_tf32(t[x][i]);
}

// ---------------- tensor-core tf32 GEMM via mma.sync: C = A @ Bt^T ----------------
// tile 128x128x32; 256 threads = 8 warps (4m x 2n); warp does 32x64 via 2x8 m16n8k8
template <bool WITH_BIAS, bool WITH_GELU, bool WITH_RES>
__global__ __launch_bounds__(256)
void mma_gemm(const float* __restrict__ A, const float* __restrict__ Bt,
              const float* __restrict__ bias, const float* __restrict__ Rd,
              float* __restrict__ C, int Rr, int Kd, int Cn) {
    __shared__ float As[128][36];
    __shared__ float Bs[128][36];
    const int bm = blockIdx.y * 128, bn = blockIdx.x * 128;
    const int tid = threadIdx.x, wid = tid >> 5, lane = tid & 31;
    const int wm = wid & 3, wn = wid >> 2;       // warp grid 4(m) x 2(n)
    const int gid = lane >> 2, tig = lane & 3;   // groupID, threadID_in_group

    float acc[2][8][4];
#pragma unroll
    for (int mt = 0; mt < 2; mt++)
#pragma unroll
        for (int nt = 0; nt < 8; nt++)
#pragma unroll
            for (int i = 0; i < 4; i++) acc[mt][nt][i] = 0.f;

    for (int k0 = 0; k0 < Kd; k0 += 32) {
        // stage A (tf32-rounded) and B (pre-rounded) tiles: 128 rows x 32 floats each
#pragma unroll
        for (int i = 0; i < 4; i++) {
            int lin = tid + i * 256;
            int row = lin >> 3, kq = (lin & 7) * 4;
            float4 v = make_float4(0.f, 0.f, 0.f, 0.f);
            if (bm + row < Rr) v = *reinterpret_cast<const float4*>(A + (size_t)(bm + row) * Kd + k0 + kq);
            v.x = to_tf32(v.x); v.y = to_tf32(v.y); v.z = to_tf32(v.z); v.w = to_tf32(v.w);
            As[row][kq] = v.x; As[row][kq + 1] = v.y; As[row][kq + 2] = v.z; As[row][kq + 3] = v.w;
            float4 wv = *reinterpret_cast<const float4*>(Bt + (size_t)(bn + row) * Kd + k0 + kq);
            Bs[row][kq] = wv.x; Bs[row][kq + 1] = wv.y; Bs[row][kq + 2] = wv.z; Bs[row][kq + 3] = wv.w;
        }
        __syncthreads();
#pragma unroll
        for (int ks = 0; ks < 4; ks++) {
            const int kb = ks * 8;
            uint32_t af[2][4];
#pragma unroll
            for (int mt = 0; mt < 2; mt++) {
                int row = wm * 32 + mt * 16 + gid;
                af[mt][0] = __float_as_uint(As[row][kb + tig]);
                af[mt][1] = __float_as_uint(As[row + 8][kb + tig]);
                af[mt][2] = __float_as_uint(As[row][kb + tig + 4]);
                af[mt][3] = __float_as_uint(As[row + 8][kb + tig + 4]);
            }
            uint32_t bf[8][2];
#pragma unroll
            for (int nt = 0; nt < 8; nt++) {
                int col = wn * 64 + nt * 8 + gid;
                bf[nt][0] = __float_as_uint(Bs[col][kb + tig]);
                bf[nt][1] = __float_as_uint(Bs[col][kb + tig + 4]);
            }
#pragma unroll
            for (int mt = 0; mt < 2; mt++)
#pragma unroll
                for (int nt = 0; nt < 8; nt++)
                    mma_tf32(acc[mt][nt], af[mt], bf[nt]);
        }
        __syncthreads();
    }

    // epilogue: c0/c1 at (row, 2*tig), c2/c3 at (row+8, 2*tig)
#pragma unroll
    for (int mt = 0; mt < 2; mt++) {
#pragma unroll
        for (int half = 0; half < 2; half++) {
            int row = bm + wm * 32 + mt * 16 + half * 8 + gid;
            if (row >= Rr) continue;
            float* crow = C + (size_t)row * Cn;
            const float* rrow = WITH_RES ? (Rd + (size_t)row * Cn) : nullptr;
#pragma unroll
            for (int nt = 0; nt < 8; nt++) {
                int col = bn + wn * 64 + nt * 8 + 2 * tig;
                float v0 = acc[mt][nt][half * 2 + 0];
                float v1 = acc[mt][nt][half * 2 + 1];
                if (WITH_BIAS) { v0 += bias[col]; v1 += bias[col + 1]; }
                if (WITH_GELU) { v0 = gelu_f(v0); v1 = gelu_f(v1); }
                if (WITH_RES)  { v0 += rrow[col]; v1 += rrow[col + 1]; }
                float2 o2; o2.x = v0; o2.y = v1;
                *reinterpret_cast<float2*>(crow + col) = o2;
            }
        }
    }
}

// ---------------- fp32 tiled GEMM (head GEMMs, tiny M) ----------------
template <bool WITH_BIAS, bool WITH_GELU, bool WITH_RES>
__global__ __launch_bounds__(256)
void gemm128(const float* __restrict__ A, const float* __restrict__ W,
             const float* __restrict__ bias, const float* __restrict__ Rd,
             float* __restrict__ C, int Rr, int Kd, int Cn) {
    __shared__ float As[8][132];
    __shared__ float Bs[8][64];
    const int bn = blockIdx.x * 64;
    const int bm = blockIdx.y * 128;
    const int tid = threadIdx.x;
    const int tx = tid & 15, ty = tid >> 4;
    float acc[8][4];
#pragma unroll
    for (int u = 0; u < 8; u++)
#pragma unroll
        for (int v = 0; v < 4; v++) acc[u][v] = 0.f;

    const int arow = bm + (tid >> 1);
    const int kh = (tid & 1) * 4;
    const bool aval = arow < Rr;
    const int am = tid >> 1;
    const int bk = tid >> 4;
    const int bn4 = (tid & 15) * 4;

    for (int k0 = 0; k0 < Kd; k0 += 8) {
        float4 av = make_float4(0.f, 0.f, 0.f, 0.f);
        if (aval) av = *reinterpret_cast<const float4*>(A + (size_t)arow * Kd + k0 + kh);
        As[kh + 0][am] = av.x; As[kh + 1][am] = av.y; As[kh + 2][am] = av.z; As[kh + 3][am] = av.w;
        if (tid < 128) {
            float4 bv = *reinterpret_cast<const float4*>(W + (size_t)(k0 + bk) * Cn + bn + bn4);
            *reinterpret_cast<float4*>(&Bs[bk][bn4]) = bv;
        }
        __syncthreads();
#pragma unroll
        for (int kk = 0; kk < 8; kk++) {
            float4 a0 = *reinterpret_cast<const float4*>(&As[kk][ty * 8]);
            float4 a1 = *reinterpret_cast<const float4*>(&As[kk][ty * 8 + 4]);
            float4 b4 = *reinterpret_cast<const float4*>(&Bs[kk][tx * 4]);
            float aa[8] = {a0.x, a0.y, a0.z, a0.w, a1.x, a1.y, a1.z, a1.w};
            float bb4[4] = {b4.x, b4.y, b4.z, b4.w};
#pragma unroll
            for (int u = 0; u < 8; u++)
#pragma unroll
                for (int v = 0; v < 4; v++) acc[u][v] = fmaf(aa[u], bb4[v], acc[u][v]);
        }
        __syncthreads();
    }
#pragma unroll
    for (int u = 0; u < 8; u++) {
        int row = bm + ty * 8 + u;
        if (row < Rr) {
#pragma unroll
            for (int v = 0; v < 4; v++) {
                int col = bn + tx * 4 + v;
                float c = acc[u][v];
                if (WITH_BIAS) c += bias[col];
                if (WITH_GELU) c = gelu_f(c);
                if (WITH_RES) c += Rd[(size_t)row * Cn + col];
                C[(size_t)row * Cn + col] = c;
            }
        }
    }
}

// ---------------- attention: flash-style, 4q x 4k register blocking ----------------
__global__ __launch_bounds__(256)
void attn_kernel(const float* __restrict__ qkv, float* __restrict__ o) {
    extern __shared__ float sm[];
    float* Qs = sm;                  // 64*65
    float* Ks = Qs + 64 * 65;        // 64*65
    float* Vs = Ks + 64 * 65;        // 64*64 (unpadded for float4)
    float* Ps = Vs + 64 * 64;        // 64*65

    const int qt = blockIdx.x, h = blockIdx.y, b = blockIdx.z;
    const int tid = threadIdx.x;
    const int tx = tid & 15, ty = tid >> 4;

#pragma unroll
    for (int i = 0; i < 16; i++) {
        int lid = tid + i * 256;
        int r = lid >> 6, d = lid & 63;
        int s = qt * 64 + r;
        Qs[r * 65 + d] = (s < SEQ) ? qkv[((size_t)(b * SEQ + s)) * (3 * INNER) + h * DH + d] : 0.f;
    }
    float oacc[4][4];
    float mcur[4], lcur[4];
#pragma unroll
    for (int u = 0; u < 4; u++) {
        mcur[u] = -1e30f; lcur[u] = 0.f;
#pragma unroll
        for (int v = 0; v < 4; v++) oacc[u][v] = 0.f;
    }
    __syncthreads();

    for (int kt = 0; kt < 13; kt++) {
#pragma unroll
        for (int i = 0; i < 16; i++) {
            int lid = tid + i * 256;
            int r = lid >> 6, d = lid & 63;
            int s = kt * 64 + r;
            size_t base = ((size_t)(b * SEQ + (s < SEQ ? s : 0))) * (3 * INNER) + h * DH + d;
            Ks[r * 65 + d] = (s < SEQ) ? qkv[base + INNER] : 0.f;
            Vs[r * 64 + d] = (s < SEQ) ? qkv[base + 2 * INNER] : 0.f;
        }
        __syncthreads();

        float sreg[4][4];
#pragma unroll
        for (int u = 0; u < 4; u++)
#pragma unroll
            for (int v = 0; v < 4; v++) sreg[u][v] = 0.f;
#pragma unroll 2
        for (int d = 0; d < 64; d++) {
            float qv[4], kv[4];
#pragma unroll
            for (int u = 0; u < 4; u++) qv[u] = Qs[(ty * 4 + u) * 65 + d];
#pragma unroll
            for (int v = 0; v < 4; v++) kv[v] = Ks[(tx * 4 + v) * 65 + d];
#pragma unroll
            for (int u = 0; u < 4; u++)
#pragma unroll
                for (int v = 0; v < 4; v++) sreg[u][v] = fmaf(qv[u], kv[v], sreg[u][v]);
        }
#pragma unroll
        for (int u = 0; u < 4; u++)
#pragma unroll
            for (int v = 0; v < 4; v++) {
                int kg = kt * 64 + tx * 4 + v;
                sreg[u][v] = (kg < SEQ) ? sreg[u][v] * 0.125f : -1e30f;
            }

        float corr[4];
#pragma unroll
        for (int u = 0; u < 4; u++) {
            float rm = fmaxf(fmaxf(sreg[u][0], sreg[u][1]), fmaxf(sreg[u][2], sreg[u][3]));
#pragma unroll
            for (int off = 1; off < 16; off <<= 1) rm = fmaxf(rm, __shfl_xor_sync(0xffffffffu, rm, off));
            float mnew = fmaxf(mcur[u], rm);
            corr[u] = __expf(mcur[u] - mnew);
            float ssum = 0.f;
#pragma unroll
            for (int v = 0; v < 4; v++) {
                float p = __expf(sreg[u][v] - mnew);
                Ps[(ty * 4 + u) * 65 + tx * 4 + v] = p;
                ssum += p;
            }
#pragma unroll
            for (int off = 1; off < 16; off <<= 1) ssum += __shfl_xor_sync(0xffffffffu, ssum, off);
            lcur[u] = lcur[u] * corr[u] + ssum;
            mcur[u] = mnew;
        }
        __syncwarp();

#pragma unroll
        for (int u = 0; u < 4; u++)
#pragma unroll
            for (int v = 0; v < 4; v++) oacc[u][v] *= corr[u];
#pragma unroll 2
        for (int k = 0; k < 64; k++) {
            float4 vv = *reinterpret_cast<const float4*>(&Vs[k * 64 + tx * 4]);
            float vvv[4] = {vv.x, vv.y, vv.z, vv.w};
#pragma unroll
            for (int u = 0; u < 4; u++) {
                float p = Ps[(ty * 4 + u) * 65 + k];
#pragma unroll
                for (int v = 0; v < 4; v++) oacc[u][v] = fmaf(p, vvv[v], oacc[u][v]);
            }
        }
        __syncthreads();
    }

#pragma unroll
    for (int u = 0; u < 4; u++) {
        int s = qt * 64 + ty * 4 + u;
        if (s < SEQ) {
            float inv = 1.0f / lcur[u];
#pragma unroll
            for (int v = 0; v < 4; v++)
                o[((size_t)(b * SEQ + s)) * INNER + h * DH + tx * 4 + v] = oacc[u][v] * inv;
        }
    }
}

// ---------------- max over sequence: two stage ----------------
__global__ void maxpool1_kernel(const float* __restrict__ x, float* __restrict__ part) {
    const int c = blockIdx.x, b = blockIdx.y;
    const int d = threadIdx.x;  // 512
    const int s0 = c * 60;
    float m0 = -1e30f, m1 = -1e30f, m2 = -1e30f, m3 = -1e30f;
    for (int s = s0; s < s0 + 60; s += 4) {
        m0 = fmaxf(m0, x[((size_t)(b * SEQ + s + 0)) * DIM + d]);
        m1 = fmaxf(m1, x[((size_t)(b * SEQ + s + 1)) * DIM + d]);
        m2 = fmaxf(m2, x[((size_t)(b * SEQ + s + 2)) * DIM + d]);
        m3 = fmaxf(m3, x[((size_t)(b * SEQ + s + 3)) * DIM + d]);
    }
    part[((size_t)(b * 13 + c)) * DIM + d] = fmaxf(fmaxf(m0, m1), fmaxf(m2, m3));
}

__global__ void maxpool2_kernel(const float* __restrict__ part, float* __restrict__ o) {
    const int b = blockIdx.x, d = threadIdx.x;
    float m = -1e30f;
#pragma unroll
    for (int c = 0; c < 13; c++) m = fmaxf(m, part[((size_t)(b * 13 + c)) * DIM + d]);
    o[b * DIM + d] = m;
}

// ---------------- head softmax @ anchors ----------------
__global__ void head_kernel(const float* __restrict__ h2, float* __restrict__ out) {
    const int bg = blockIdx.x;
    const int b = bg / 17, g = bg % 17;
    const int tid = threadIdx.x;  // 64
    float v = h2[b * OUTD + g * 64 + tid];
    __shared__ float wred[2];
    __shared__ float wts[64];
    float m = v;
    for (int off = 16; off; off >>= 1) m = fmaxf(m, __shfl_xor_sync(0xffffffffu, m, off));
    if ((tid & 31) == 0) wred[tid >> 5] = m;
    __syncthreads();
    m = fmaxf(wred[0], wred[1]);
    float e = expf(v - m);
    float s = e;
    for (int off = 16; off; off >>= 1) s += __shfl_xor_sync(0xffffffffu, s, off);
    __syncthreads();
    if ((tid & 31) == 0) wred[tid >> 5] = s;
    __syncthreads();
    float tot = wred[0] + wred[1];
    wts[tid] = e / tot;
    __syncthreads();
    if (tid < 3) {
        float acc = 0.f;
        for (int j = 0; j < 64; j++) {
            float ac = (tid == 0) ? (-1.5f + (float)(j >> 4))
                     : (tid == 1) ? (-1.5f + (float)((j >> 2) & 3))
                                  : (-1.5f + (float)(j & 3));
            acc += wts[j] * ac;
        }
        out[(size_t)(b * 17 + g) * 3 + tid] = acc;
    }
}

// ---------------- launch ----------------
#define FPS_SMEM (NTOT * 4 * 4)
#define ATTN_SMEM ((64 * 65 * 3 + 64 * 64) * 4)

extern "C" void kernel_launch(void* const* d_in, const int* in_sizes, int n_in,
                              void* d_out, int out_size) {
    const float* points     = (const float*)d_in[0];
    const float* conv_d_w   = (const float*)d_in[1];
    const float* conv_f_w   = (const float*)d_in[2];
    const float* pos_w      = (const float*)d_in[3];
    const float* pos_b      = (const float*)d_in[4];
    const float* ln1_g      = (const float*)d_in[5];
    const float* ln1_b      = (const float*)d_in[6];
    const float* qkv_w      = (const float*)d_in[7];
    const float* attn_out_w = (const float*)d_in[8];
    const float* attn_out_b = (const float*)d_in[9];
    const float* ln2_g      = (const float*)d_in[10];
    const float* ln2_b      = (const float*)d_in[11];
    const float* ff1_w      = (const float*)d_in[12];
    const float* ff1_b      = (const float*)d_in[13];
    const float* ff2_w      = (const float*)d_in[14];
    const float* ff2_b      = (const float*)d_in[15];
    const float* head_ln_g  = (const float*)d_in[16];
    const float* head_ln_b  = (const float*)d_in[17];
    const float* head1_w    = (const float*)d_in[18];
    const float* head1_b    = (const float*)d_in[19];
    const float* head2_w    = (const float*)d_in[20];
    const float* head2_b    = (const float*)d_in[21];
    float* out = (float*)d_out;

    static bool inited = false;
    static float *p_axyz, *p_x, *p_xn, *p_qkv, *p_att, *p_ff1, *p_pmax, *p_pool, *p_pooln, *p_h1, *p_h2;
    static float *p_t_qkv, *p_t_ao, *p_t_ff1, *p_t_ff2;
    if (!inited) {
        cudaGetSymbolAddress((void**)&p_axyz, g_axyz);
        cudaGetSymbolAddress((void**)&p_x, g_x);
        cudaGetSymbolAddress((void**)&p_xn, g_xn);
        cudaGetSymbolAddress((void**)&p_qkv, g_qkv);
        cudaGetSymbolAddress((void**)&p_att, g_att);
        cudaGetSymbolAddress((void**)&p_ff1, g_ff1);
        cudaGetSymbolAddress((void**)&p_pmax, g_pmax);
        cudaGetSymbolAddress((void**)&p_pool, g_pool);
        cudaGetSymbolAddress((void**)&p_pooln, g_pooln);
        cudaGetSymbolAddress((void**)&p_h1, g_h1);
        cudaGetSymbolAddress((void**)&p_h2, g_h2);
        cudaGetSymbolAddress((void**)&p_t_qkv, g_t_qkv);
        cudaGetSymbolAddress((void**)&p_t_ao, g_t_ao);
        cudaGetSymbolAddress((void**)&p_t_ff1, g_t_ff1);
        cudaGetSymbolAddress((void**)&p_t_ff2, g_t_ff2);
        cudaFuncSetAttribute(fps_kernel, cudaFuncAttributeMaxDynamicSharedMemorySize, FPS_SMEM);
        cudaFuncSetAttribute(attn_kernel, cudaFuncAttributeMaxDynamicSharedMemorySize, ATTN_SMEM);
        inited = true;
    }

    // 0. transpose + tf32-round weights into [n][k]
    {
        dim3 tb(32, 8);
        for (int l = 0; l < DEPTH; l++) {
            wtrans_kernel<<<dim3((3 * INNER) / 32, DIM / 32), tb>>>(
                qkv_w + (size_t)l * DIM * 3 * INNER, p_t_qkv + (size_t)l * 3 * INNER * DIM, DIM, 3 * INNER);
            wtrans_kernel<<<dim3(DIM / 32, INNER / 32), tb>>>(
                attn_out_w + (size_t)l * INNER * DIM, p_t_ao + (size_t)l * DIM * INNER, INNER, DIM);
            wtrans_kernel<<<dim3(MLP / 32, DIM / 32), tb>>>(
                ff1_w + (size_t)l * DIM * MLP, p_t_ff1 + (size_t)l * MLP * DIM, DIM, MLP);
            wtrans_kernel<<<dim3(DIM / 32, MLP / 32), tb>>>(
                ff2_w + (size_t)l * MLP * DIM, p_t_ff2 + (size_t)l * DIM * MLP, MLP, DIM);
        }
    }

    // 1. FPS anchors
    fps_kernel<<<BD * NF, 512, FPS_SMEM>>>(points, p_axyz);
    // 2. grouping + conv + max + positional embed -> x
    group_kernel<<<dim3(MM, NF, BD), 256>>>(points, conv_d_w, conv_f_w, pos_w, pos_b, p_axyz, p_x);

    // 3. transformer (tensor-core tf32 GEMMs)
    const int MT = (ROWS + 127) / 128;  // 49
    for (int l = 0; l < DEPTH; l++) {
        ln_kernel<<<ROWS, 128>>>(p_x, ln1_g + l * DIM, ln1_b + l * DIM, p_xn);
        mma_gemm<false, false, false><<<dim3((3 * INNER) / 128, MT), 256>>>(
            p_xn, p_t_qkv + (size_t)l * 3 * INNER * DIM, nullptr, nullptr, p_qkv, ROWS, DIM, 3 * INNER);
        attn_kernel<<<dim3(13, HEADS, BD), 256, ATTN_SMEM>>>(p_qkv, p_att);
        mma_gemm<true, false, true><<<dim3(DIM / 128, MT), 256>>>(
            p_att, p_t_ao + (size_t)l * DIM * INNER, attn_out_b + l * DIM, p_x, p_x, ROWS, INNER, DIM);
        ln_kernel<<<ROWS, 128>>>(p_x, ln2_g + l * DIM, ln2_b + l * DIM, p_xn);
        mma_gemm<true, true, false><<<dim3(MLP / 128, MT), 256>>>(
            p_xn, p_t_ff1 + (size_t)l * MLP * DIM, ff1_b + l * MLP, nullptr, p_ff1, ROWS, DIM, MLP);
        mma_gemm<true, false, true><<<dim3(DIM / 128, MT), 256>>>(
            p_ff1, p_t_ff2 + (size_t)l * DIM * MLP, ff2_b + l * DIM, p_x, p_x, ROWS, MLP, DIM);
    }

    // 4. head (tiny GEMMs stay on SIMT path)
    maxpool1_kernel<<<dim3(13, BD), DIM>>>(p_x, p_pmax);
    maxpool2_kernel<<<BD, DIM>>>(p_pmax, p_pool);
    ln_kernel<<<BD, 128>>>(p_pool, head_ln_g, head_ln_b, p_pooln);
    gemm128<true, true, false><<<dim3(MLP / 64, 1), 256>>>(p_pooln, head1_w, head1_b, nullptr, p_h1, BD, DIM, MLP);
    gemm128<true, false, false><<<dim3(OUTD / 64, 1), 256>>>(p_h1, head2_w, head2_b, nullptr, p_h2, BD, MLP, OUTD);
    head_kernel<<<BD * 17, 64>>>(p_h2, out);
}

// round 8
// speedup vs baseline: 2.9018x; 1.0467x over previous
#include <cuda_runtime.h>
#include <cuda_bf16.h>
#include <math.h>
#include <stdint.h>

// ---------------- problem constants ----------------
#define BD 8
#define LD 5
#define NP 4096
#define NANCH 64
#define NTOT 4160          // NP + NANCH
#define MM 260             // NTOT / 16
#define NF 3
#define SEQ 780            // NF*MM
#define ROWS 6240          // BD*SEQ
#define DIM 512
#define HEADS 8
#define DH 64
#define INNER 512
#define MLP 1024
#define OUTD 1088
#define KNN 32
#define DEPTH 5

// ---------------- scratch (device globals; no allocation allowed) ----------------
__device__ float g_axyz[BD * NF * MM * 3];
__device__ float g_x[ROWS * DIM];
__device__ float g_qkv[ROWS * 3 * INNER];
__device__ float g_att[ROWS * INNER];
__device__ float g_ff1[ROWS * MLP];
__device__ float2 g_stats[ROWS];
__device__ float g_pmax[BD * 13 * DIM];
__device__ float g_pool[BD * DIM];
__device__ float g_pooln[BD * DIM];
__device__ float g_h1[BD * MLP];
__device__ float g_h2[BD * OUTD];
// transposed (and tf32-rounded) weights, layout [n][k]
__device__ float g_t_qkv[DEPTH * 3 * INNER * DIM];
__device__ float g_t_ao [DEPTH * DIM * INNER];
__device__ float g_t_ff1[DEPTH * MLP * DIM];
__device__ float g_t_ff2[DEPTH * DIM * MLP];

// ---------------- helpers ----------------
__device__ __forceinline__ float to_tf32(float x) {
    uint32_t u; asm("cvt.rna.tf32.f32 %0, %1;" : "=r"(u) : "f"(x));
    return __uint_as_float(u);
}

__device__ __forceinline__ void get_pt(const float* __restrict__ pts, int b, int layer, int j,
                                       float& x, float& y, float& z) {
    if (j < NP) {
        const float* p = pts + ((size_t)((b * LD + layer) * NP + j)) * 3;
        x = p[0]; y = p[1]; z = p[2];
    } else {
        int i = j - NP;
        x = -1.5f + (float)(i >> 4);
        y = -1.5f + (float)((i >> 2) & 3);
        z = -1.5f + (float)(i & 3);
    }
}

__device__ __forceinline__ float gelu_f(float x) {
    return 0.5f * x * (1.0f + erff(x * 0.7071067811865476f));
}

__device__ __forceinline__ void mma_tf32(float* d, const uint32_t* a, const uint32_t* b) {
    asm volatile(
        "mma.sync.aligned.m16n8k8.row.col.f32.tf32.tf32.f32 "
        "{%0,%1,%2,%3}, {%4,%5,%6,%7}, {%8,%9}, {%0,%1,%2,%3};"
        : "+f"(d[0]), "+f"(d[1]), "+f"(d[2]), "+f"(d[3])
        : "r"(a[0]), "r"(a[1]), "r"(a[2]), "r"(a[3]), "r"(b[0]), "r"(b[1]));
}

// ---------------- FPS: one block per (b, frame) ----------------
__global__ void fps_kernel(const float* __restrict__ points, float* __restrict__ axyz) {
    const int bf = blockIdx.x;
    const int b = bf / NF, f = bf % NF;
    const int layer = 2 * f;
    extern __shared__ float sm[];
    float* sx = sm;
    float* sy = sm + NTOT;
    float* sz = sm + 2 * NTOT;
    float* dist = sm + 3 * NTOT;
    __shared__ float rv[16];
    __shared__ int ri[16];
    __shared__ int s_last;
    int tid = threadIdx.x;

    for (int j = tid; j < NTOT; j += 512) {
        float x, y, z;
        get_pt(points, b, layer, j, x, y, z);
        sx[j] = x; sy[j] = y; sz[j] = z;
        dist[j] = 1e10f;
    }
    __syncthreads();

    int last = 0;
    float* aout = axyz + (size_t)bf * MM * 3;
    for (int s = 0; s < MM; s++) {
        float lx = sx[last], ly = sy[last], lz = sz[last];
        if (tid == 0) { aout[s * 3 + 0] = lx; aout[s * 3 + 1] = ly; aout[s * 3 + 2] = lz; }
        float bv = -1.0f; int bi = 0x7fffffff;
        for (int j = tid; j < NTOT; j += 512) {
            float dx = sx[j] - lx, dy = sy[j] - ly, dz = sz[j] - lz;
            float d = __fadd_rn(__fadd_rn(__fmul_rn(dx, dx), __fmul_rn(dy, dy)), __fmul_rn(dz, dz));
            float nd = fminf(dist[j], d);
            dist[j] = nd;
            if (nd > bv) { bv = nd; bi = j; }
        }
        for (int off = 16; off; off >>= 1) {
            float ov = __shfl_down_sync(0xffffffffu, bv, off);
            int oi = __shfl_down_sync(0xffffffffu, bi, off);
            if (ov > bv || (ov == bv && oi < bi)) { bv = ov; bi = oi; }
        }
        if ((tid & 31) == 0) { rv[tid >> 5] = bv; ri[tid >> 5] = bi; }
        __syncthreads();
        if (tid < 32) {
            float v2 = (tid < 16) ? rv[tid] : -2.0f;
            int i2 = (tid < 16) ? ri[tid] : 0x7fffffff;
            for (int off = 8; off; off >>= 1) {
                float ov = __shfl_down_sync(0xffffffffu, v2, off);
                int oi = __shfl_down_sync(0xffffffffu, i2, off);
                if (ov > v2 || (ov == v2 && oi < i2)) { v2 = ov; i2 = oi; }
            }
            if (tid == 0) s_last = i2;
        }
        __syncthreads();
        last = s_last;
    }
}

// ---------------- ball query + conv + maxpool + pos embed ----------------
__global__ void group_kernel(const float* __restrict__ points,
                             const float* __restrict__ conv_d_w,
                             const float* __restrict__ conv_f_w,
                             const float* __restrict__ pos_w,
                             const float* __restrict__ pos_b,
                             const float* __restrict__ axyz,
                             float* __restrict__ xout) {
    const int m = blockIdx.x, f = blockIdx.y, b = blockIdx.z;
    __shared__ float gpts[3][KNN][3];
    __shared__ int scnt[3];
    __shared__ float sa[3];
    const int tid = threadIdx.x;

    if (tid < 3) sa[tid] = axyz[((size_t)((b * NF + f) * MM + m)) * 3 + tid];
    __syncthreads();
    const float ax = sa[0], ay = sa[1], az = sa[2];

    const int w = tid >> 5, lane = tid & 31;
    if (w < 3) {
        int layer = 2 * f - 1 + w;
        layer = layer < 0 ? 0 : (layer > 4 ? 4 : layer);
        const float R2 = (float)(0.7 * 0.7);
        int cnt = 0;
        for (int j0 = 0; j0 < NTOT && cnt < KNN; j0 += 32) {
            int j = j0 + lane;
            float px, py, pz;
            get_pt(points, b, layer, j, px, py, pz);
            float dx = px - ax, dy = py - ay, dz = pz - az;
            float d2 = __fadd_rn(__fadd_rn(__fmul_rn(dx, dx), __fmul_rn(dy, dy)), __fmul_rn(dz, dz));
            unsigned mask = __ballot_sync(0xffffffffu, d2 < R2);
            while (mask && cnt < KNN) {
                int src = __ffs(mask) - 1;
                mask &= mask - 1;
                float gx = __shfl_sync(0xffffffffu, px, src);
                float gy = __shfl_sync(0xffffffffu, py, src);
                float gz = __shfl_sync(0xffffffffu, pz, src);
                if (lane == 0) { gpts[w][cnt][0] = gx; gpts[w][cnt][1] = gy; gpts[w][cnt][2] = gz; }
                cnt++;
            }
        }
        if (cnt == 0) {
            if (lane == 0) {
                float gx, gy, gz;
                get_pt(points, b, layer, 0, gx, gy, gz);
                gpts[w][0][0] = gx; gpts[w][0][1] = gy; gpts[w][0][2] = gz;
            }
            cnt = 1;
        }
        if (lane == 0) scnt[w] = cnt;
    }
    __syncthreads();

    const int cs[3] = {scnt[0], scnt[1], scnt[2]};
#pragma unroll
    for (int dd = 0; dd < 2; dd++) {
        int d = tid + dd * 256;
        float wf0 = conv_f_w[d * 3 + 0], wf1 = conv_f_w[d * 3 + 1], wf2 = conv_f_w[d * 3 + 2];
        float wd0 = conv_d_w[d * 4 + 0], wd1 = conv_d_w[d * 4 + 1], wd2 = conv_d_w[d * 4 + 2], wd3 = conv_d_w[d * 4 + 3];
        float ws0 = wf0 + wd0, ws1 = wf1 + wd1, ws2 = wf2 + wd2;
        float adot = ax * wd0 + ay * wd1 + az * wd2;
        float maxv = -1e30f;
        for (int ww = 0; ww < 3; ww++) {
            float dt = (float)(ww - 1);
            float base = dt * wd3 - adot;
            int cn = cs[ww];
            for (int k = 0; k < cn; k++) {
                float gx = gpts[ww][k][0], gy = gpts[ww][k][1], gz = gpts[ww][k][2];
                float v = fmaf(gx, ws0, fmaf(gy, ws1, fmaf(gz, ws2, base)));
                maxv = fmaxf(maxv, v);
            }
        }
        float pw0 = pos_w[d * 4 + 0], pw1 = pos_w[d * 4 + 1], pw2 = pos_w[d * 4 + 2], pw3 = pos_w[d * 4 + 3];
        float t = (float)(f + 1);
        float outv = maxv + ax * pw0 + ay * pw1 + az * pw2 + t * pw3 + pos_b[d];
        xout[((size_t)(b * SEQ + f * MM + m)) * DIM + d] = outv;
    }
}

// ---------------- per-row LN stats: one warp per row ----------------
__global__ __launch_bounds__(256)
void ln_stats_kernel(const float* __restrict__ x, float2* __restrict__ stats) {
    const int row = blockIdx.x * 8 + (threadIdx.x >> 5);
    const int lane = threadIdx.x & 31;
    const float* xr = x + (size_t)row * DIM;
    float4 v[4];
#pragma unroll
    for (int i = 0; i < 4; i++) v[i] = *reinterpret_cast<const float4*>(xr + i * 128 + lane * 4);
    float s = 0.f;
#pragma unroll
    for (int i = 0; i < 4; i++) s += v[i].x + v[i].y + v[i].z + v[i].w;
    for (int off = 16; off; off >>= 1) s += __shfl_xor_sync(0xffffffffu, s, off);
    float mu = s * (1.0f / DIM);
    float q = 0.f;
#pragma unroll
    for (int i = 0; i < 4; i++) {
        float a = v[i].x - mu, b = v[i].y - mu, c = v[i].z - mu, d = v[i].w - mu;
        q += a * a + b * b + c * c + d * d;
    }
    for (int off = 16; off; off >>= 1) q += __shfl_xor_sync(0xffffffffu, q, off);
    if (lane == 0) {
        float2 st; st.x = mu; st.y = rsqrtf(q * (1.0f / DIM) + 1e-5f);
        stats[row] = st;
    }
}

// ---------------- LayerNorm (head path, rows x 512) ----------------
__global__ void ln_kernel(const float* __restrict__ x, const float* __restrict__ gg,
                          const float* __restrict__ bb, float* __restrict__ y) {
    const int r = blockIdx.x;
    const float* xr = x + (size_t)r * DIM;
    float* yr = y + (size_t)r * DIM;
    const int tid = threadIdx.x;
    float v[4];
    float s = 0.f;
#pragma unroll
    for (int i = 0; i < 4; i++) { v[i] = xr[tid + i * 128]; s += v[i]; }
    __shared__ float red[4];
    __shared__ float s_stat;
    for (int off = 16; off; off >>= 1) s += __shfl_down_sync(0xffffffffu, s, off);
    if ((tid & 31) == 0) red[tid >> 5] = s;
    __syncthreads();
    if (tid == 0) s_stat = (red[0] + red[1] + red[2] + red[3]) * (1.0f / DIM);
    __syncthreads();
    float mu = s_stat;
    float q = 0.f;
#pragma unroll
    for (int i = 0; i < 4; i++) { float d = v[i] - mu; q += d * d; }
    __syncthreads();
    for (int off = 16; off; off >>= 1) q += __shfl_down_sync(0xffffffffu, q, off);
    if ((tid & 31) == 0) red[tid >> 5] = q;
    __syncthreads();
    if (tid == 0) s_stat = (red[0] + red[1] + red[2] + red[3]) * (1.0f / DIM);
    __syncthreads();
    float inv = rsqrtf(s_stat + 1e-5f);
#pragma unroll
    for (int i = 0; i < 4; i++) {
        int c = tid + i * 128;
        yr[c] = (v[i] - mu) * inv * gg[c] + bb[c];
    }
}

// ---------------- merged weight transpose (+tf32 round), all 20 matrices ----------------
// per-layer tiles: qkv 48x16=768, ao 16x16=256, ff1 32x16=512, ff2 16x32=512 -> 2048
__global__ __launch_bounds__(256)
void wtrans_all_kernel(const float* __restrict__ qkv_w, const float* __restrict__ ao_w,
                       const float* __restrict__ ff1_w, const float* __restrict__ ff2_w,
                       float* __restrict__ t_qkv, float* __restrict__ t_ao,
                       float* __restrict__ t_ff1, float* __restrict__ t_ff2) {
    __shared__ float t[32][33];
    const int tile = blockIdx.x;
    const int l = tile / 2048;
    int r = tile % 2048;
    const float* W; float* Wt; int K, N, bx, by;
    if (r < 768) {
        W = qkv_w + (size_t)l * DIM * 1536; Wt = t_qkv + (size_t)l * 1536 * DIM;
        K = DIM; N = 1536; bx = r % 48; by = r / 48;
    } else if (r < 1024) {
        r -= 768;
        W = ao_w + (size_t)l * INNER * DIM; Wt = t_ao + (size_t)l * DIM * INNER;
        K = INNER; N = DIM; bx = r % 16; by = r / 16;
    } else if (r < 1536) {
        r -= 1024;
        W = ff1_w + (size_t)l * DIM * MLP; Wt = t_ff1 + (size_t)l * MLP * DIM;
        K = DIM; N = MLP; bx = r % 32; by = r / 32;
    } else {
        r -= 1536;
        W = ff2_w + (size_t)l * MLP * DIM; Wt = t_ff2 + (size_t)l * DIM * MLP;
        K = MLP; N = DIM; bx = r % 16; by = r / 16;
    }
    const int n0 = bx * 32, k0 = by * 32;
    const int x = threadIdx.x & 31, y = threadIdx.x >> 5;  // 32 x 8
#pragma unroll
    for (int i = y; i < 32; i += 8)
        t[i][x] = W[(size_t)(k0 + i) * N + n0 + x];
    __syncthreads();
#pragma unroll
    for (int i = y; i < 32; i += 8)
        Wt[(size_t)(n0 + i) * K + k0 + x] = to_tf32(t[x][i]);
}

// ---------------- tensor-core tf32 GEMM via mma.sync: C = A @ Bt^T ----------------
// tile 128x128x32; 256 threads = 8 warps (4m x 2n); optional fused LN on A
template <bool WITH_LN, bool WITH_BIAS, bool WITH_GELU, bool WITH_RES>
__global__ __launch_bounds__(256)
void mma_gemm(const float* __restrict__ A, const float* __restrict__ Bt,
              const float2* __restrict__ stats, const float* __restrict__ lng,
              const float* __restrict__ lnb,
              const float* __restrict__ bias, const float* __restrict__ Rd,
              float* __restrict__ C, int Rr, int Kd, int Cn) {
    __shared__ float As[128][36];
    __shared__ float Bs[128][36];
    const int bm = blockIdx.y * 128, bn = blockIdx.x * 128;
    const int tid = threadIdx.x, wid = tid >> 5, lane = tid & 31;
    const int wm = wid & 3, wn = wid >> 2;
    const int gid = lane >> 2, tig = lane & 3;

    float acc[2][8][4];
#pragma unroll
    for (int mt = 0; mt < 2; mt++)
#pragma unroll
        for (int nt = 0; nt < 8; nt++)
#pragma unroll
            for (int i = 0; i < 4; i++) acc[mt][nt][i] = 0.f;

    for (int k0 = 0; k0 < Kd; k0 += 32) {
#pragma unroll
        for (int i = 0; i < 4; i++) {
            int lin = tid + i * 256;
            int row = lin >> 3, kq = (lin & 7) * 4;
            float4 v = make_float4(0.f, 0.f, 0.f, 0.f);
            if (bm + row < Rr) {
                v = *reinterpret_cast<const float4*>(A + (size_t)(bm + row) * Kd + k0 + kq);
                if (WITH_LN) {
                    float2 st = stats[bm + row];
                    float4 gv = *reinterpret_cast<const float4*>(lng + k0 + kq);
                    float4 bv = *reinterpret_cast<const float4*>(lnb + k0 + kq);
                    v.x = (v.x - st.x) * st.y * gv.x + bv.x;
                    v.y = (v.y - st.x) * st.y * gv.y + bv.y;
                    v.z = (v.z - st.x) * st.y * gv.z + bv.z;
                    v.w = (v.w - st.x) * st.y * gv.w + bv.w;
                }
            }
            v.x = to_tf32(v.x); v.y = to_tf32(v.y); v.z = to_tf32(v.z); v.w = to_tf32(v.w);
            As[row][kq] = v.x; As[row][kq + 1] = v.y; As[row][kq + 2] = v.z; As[row][kq + 3] = v.w;
            float4 wv = *reinterpret_cast<const float4*>(Bt + (size_t)(bn + row) * Kd + k0 + kq);
            Bs[row][kq] = wv.x; Bs[row][kq + 1] = wv.y; Bs[row][kq + 2] = wv.z; Bs[row][kq + 3] = wv.w;
        }
        __syncthreads();
#pragma unroll
        for (int ks = 0; ks < 4; ks++) {
            const int kb = ks * 8;
            uint32_t af[2][4];
#pragma unroll
            for (int mt = 0; mt < 2; mt++) {
                int row = wm * 32 + mt * 16 + gid;
                af[mt][0] = __float_as_uint(As[row][kb + tig]);
                af[mt][1] = __float_as_uint(As[row + 8][kb + tig]);
                af[mt][2] = __float_as_uint(As[row][kb + tig + 4]);
                af[mt][3] = __float_as_uint(As[row + 8][kb + tig + 4]);
            }
            uint32_t bf[8][2];
#pragma unroll
            for (int nt = 0; nt < 8; nt++) {
                int col = wn * 64 + nt * 8 + gid;
                bf[nt][0] = __float_as_uint(Bs[col][kb + tig]);
                bf[nt][1] = __float_as_uint(Bs[col][kb + tig + 4]);
            }
#pragma unroll
            for (int mt = 0; mt < 2; mt++)
#pragma unroll
                for (int nt = 0; nt < 8; nt++)
                    mma_tf32(acc[mt][nt], af[mt], bf[nt]);
        }
        __syncthreads();
    }

#pragma unroll
    for (int mt = 0; mt < 2; mt++) {
#pragma unroll
        for (int half = 0; half < 2; half++) {
            int row = bm + wm * 32 + mt * 16 + half * 8 + gid;
            if (row >= Rr) continue;
            float* crow = C + (size_t)row * Cn;
            const float* rrow = WITH_RES ? (Rd + (size_t)row * Cn) : nullptr;
#pragma unroll
            for (int nt = 0; nt < 8; nt++) {
                int col = bn + wn * 64 + nt * 8 + 2 * tig;
                float v0 = acc[mt][nt][half * 2 + 0];
                float v1 = acc[mt][nt][half * 2 + 1];
                if (WITH_BIAS) { v0 += bias[col]; v1 += bias[col + 1]; }
                if (WITH_GELU) { v0 = gelu_f(v0); v1 = gelu_f(v1); }
                if (WITH_RES)  { v0 += rrow[col]; v1 += rrow[col + 1]; }
                float2 o2; o2.x = v0; o2.y = v1;
                *reinterpret_cast<float2*>(crow + col) = o2;
            }
        }
    }
}

// ---------------- fp32 tiled GEMM (head GEMMs, tiny M) ----------------
template <bool WITH_BIAS, bool WITH_GELU, bool WITH_RES>
__global__ __launch_bounds__(256)
void gemm128(const float* __restrict__ A, const float* __restrict__ W,
             const float* __restrict__ bias, const float* __restrict__ Rd,
             float* __restrict__ C, int Rr, int Kd, int Cn) {
    __shared__ float As[8][132];
    __shared__ float Bs[8][64];
    const int bn = blockIdx.x * 64;
    const int bm = blockIdx.y * 128;
    const int tid = threadIdx.x;
    const int tx = tid & 15, ty = tid >> 4;
    float acc[8][4];
#pragma unroll
    for (int u = 0; u < 8; u++)
#pragma unroll
        for (int v = 0; v < 4; v++) acc[u][v] = 0.f;

    const int arow = bm + (tid >> 1);
    const int kh = (tid & 1) * 4;
    const bool aval = arow < Rr;
    const int am = tid >> 1;
    const int bk = tid >> 4;
    const int bn4 = (tid & 15) * 4;

    for (int k0 = 0; k0 < Kd; k0 += 8) {
        float4 av = make_float4(0.f, 0.f, 0.f, 0.f);
        if (aval) av = *reinterpret_cast<const float4*>(A + (size_t)arow * Kd + k0 + kh);
        As[kh + 0][am] = av.x; As[kh + 1][am] = av.y; As[kh + 2][am] = av.z; As[kh + 3][am] = av.w;
        if (tid < 128) {
            float4 bv = *reinterpret_cast<const float4*>(W + (size_t)(k0 + bk) * Cn + bn + bn4);
            *reinterpret_cast<float4*>(&Bs[bk][bn4]) = bv;
        }
        __syncthreads();
#pragma unroll
        for (int kk = 0; kk < 8; kk++) {
            float4 a0 = *reinterpret_cast<const float4*>(&As[kk][ty * 8]);
            float4 a1 = *reinterpret_cast<const float4*>(&As[kk][ty * 8 + 4]);
            float4 b4 = *reinterpret_cast<const float4*>(&Bs[kk][tx * 4]);
            float aa[8] = {a0.x, a0.y, a0.z, a0.w, a1.x, a1.y, a1.z, a1.w};
            float bb4[4] = {b4.x, b4.y, b4.z, b4.w};
#pragma unroll
            for (int u = 0; u < 8; u++)
#pragma unroll
                for (int v = 0; v < 4; v++) acc[u][v] = fmaf(aa[u], bb4[v], acc[u][v]);
        }
        __syncthreads();
    }
#pragma unroll
    for (int u = 0; u < 8; u++) {
        int row = bm + ty * 8 + u;
        if (row < Rr) {
#pragma unroll
            for (int v = 0; v < 4; v++) {
                int col = bn + tx * 4 + v;
                float c = acc[u][v];
                if (WITH_BIAS) c += bias[col];
                if (WITH_GELU) c = gelu_f(c);
                if (WITH_RES) c += Rd[(size_t)row * Cn + col];
                C[(size_t)row * Cn + col] = c;
            }
        }
    }
}

// ---------------- attention: flash-style, transposed Q/K tiles, all-float4 ----------------
// dyn smem: QsT[64][68] (d-major), KsT[64][68] (d-major), Vs[64][68] (k-major), Ps[64][68]
#define ATTN_STRIDE 68
__global__ __launch_bounds__(256)
void attn_kernel(const float* __restrict__ qkv, float* __restrict__ o) {
    extern __shared__ float sm[];
    float* QsT = sm;
    float* KsT = QsT + 64 * ATTN_STRIDE;
    float* Vs  = KsT + 64 * ATTN_STRIDE;
    float* Ps  = Vs  + 64 * ATTN_STRIDE;

    const int qt = blockIdx.x, h = blockIdx.y, b = blockIdx.z;
    const int tid = threadIdx.x;
    const int tx = tid & 15, ty = tid >> 4;

    // load Q tile transposed: QsT[d][q]
#pragma unroll
    for (int i = 0; i < 16; i++) {
        int lid = tid + i * 256;
        int r = lid >> 6, d = lid & 63;
        int s = qt * 64 + r;
        QsT[d * ATTN_STRIDE + r] = (s < SEQ) ? qkv[((size_t)(b * SEQ + s)) * (3 * INNER) + h * DH + d] : 0.f;
    }
    float oacc[4][4];
    float mcur[4], lcur[4];
#pragma unroll
    for (int u = 0; u < 4; u++) {
        mcur[u] = -1e30f; lcur[u] = 0.f;
#pragma unroll
        for (int v = 0; v < 4; v++) oacc[u][v] = 0.f;
    }
    __syncthreads();

    for (int kt = 0; kt < 13; kt++) {
#pragma unroll
        for (int i = 0; i < 16; i++) {
            int lid = tid + i * 256;
            int r = lid >> 6, d = lid & 63;
            int s = kt * 64 + r;
            size_t base = ((size_t)(b * SEQ + (s < SEQ ? s : 0))) * (3 * INNER) + h * DH + d;
            KsT[d * ATTN_STRIDE + r] = (s < SEQ) ? qkv[base + INNER] : 0.f;
            Vs[r * ATTN_STRIDE + d] = (s < SEQ) ? qkv[base + 2 * INNER] : 0.f;
        }
        __syncthreads();

        float sreg[4][4];
#pragma unroll
        for (int u = 0; u < 4; u++)
#pragma unroll
            for (int v = 0; v < 4; v++) sreg[u][v] = 0.f;
#pragma unroll 4
        for (int d = 0; d < 64; d++) {
            float4 qv = *reinterpret_cast<const float4*>(&QsT[d * ATTN_STRIDE + ty * 4]);
            float4 kv = *reinterpret_cast<const float4*>(&KsT[d * ATTN_STRIDE + tx * 4]);
            float qa[4] = {qv.x, qv.y, qv.z, qv.w};
            float ka[4] = {kv.x, kv.y, kv.z, kv.w};
#pragma unroll
            for (int u = 0; u < 4; u++)
#pragma unroll
                for (int v = 0; v < 4; v++) sreg[u][v] = fmaf(qa[u], ka[v], sreg[u][v]);
        }
#pragma unroll
        for (int u = 0; u < 4; u++)
#pragma unroll
            for (int v = 0; v < 4; v++) {
                int kg = kt * 64 + tx * 4 + v;
                sreg[u][v] = (kg < SEQ) ? sreg[u][v] * 0.125f : -1e30f;
            }

        float corr[4];
#pragma unroll
        for (int u = 0; u < 4; u++) {
            float rm = fmaxf(fmaxf(sreg[u][0], sreg[u][1]), fmaxf(sreg[u][2], sreg[u][3]));
#pragma unroll
            for (int off = 1; off < 16; off <<= 1) rm = fmaxf(rm, __shfl_xor_sync(0xffffffffu, rm, off));
            float mnew = fmaxf(mcur[u], rm);
            corr[u] = __expf(mcur[u] - mnew);
            float ssum = 0.f;
#pragma unroll
            for (int v = 0; v < 4; v++) {
                float p = __expf(sreg[u][v] - mnew);
                Ps[(ty * 4 + u) * ATTN_STRIDE + tx * 4 + v] = p;
                ssum += p;
            }
#pragma unroll
            for (int off = 1; off < 16; off <<= 1) ssum += __shfl_xor_sync(0xffffffffu, ssum, off);
            lcur[u] = lcur[u] * corr[u] + ssum;
            mcur[u] = mnew;
        }
        __syncwarp();

#pragma unroll
        for (int u = 0; u < 4; u++)
#pragma unroll
            for (int v = 0; v < 4; v++) oacc[u][v] *= corr[u];
#pragma unroll 2
        for (int k = 0; k < 64; k += 4) {
            float4 p4[4], v4[4];
#pragma unroll
            for (int u = 0; u < 4; u++)
                p4[u] = *reinterpret_cast<const float4*>(&Ps[(ty * 4 + u) * ATTN_STRIDE + k]);
#pragma unroll
            for (int j = 0; j < 4; j++)
                v4[j] = *reinterpret_cast<const float4*>(&Vs[(k + j) * ATTN_STRIDE + tx * 4]);
#pragma unroll
            for (int u = 0; u < 4; u++) {
                float pu[4] = {p4[u].x, p4[u].y, p4[u].z, p4[u].w};
#pragma unroll
                for (int j = 0; j < 4; j++) {
                    oacc[u][0] = fmaf(pu[j], v4[j].x, oacc[u][0]);
                    oacc[u][1] = fmaf(pu[j], v4[j].y, oacc[u][1]);
                    oacc[u][2] = fmaf(pu[j], v4[j].z, oacc[u][2]);
                    oacc[u][3] = fmaf(pu[j], v4[j].w, oacc[u][3]);
                }
            }
        }
        __syncthreads();
    }

#pragma unroll
    for (int u = 0; u < 4; u++) {
        int s = qt * 64 + ty * 4 + u;
        if (s < SEQ) {
            float inv = 1.0f / lcur[u];
#pragma unroll
            for (int v = 0; v < 4; v++)
                o[((size_t)(b * SEQ + s)) * INNER + h * DH + tx * 4 + v] = oacc[u][v] * inv;
        }
    }
}

// ---------------- max over sequence: two stage ----------------
__global__ void maxpool1_kernel(const float* __restrict__ x, float* __restrict__ part) {
    const int c = blockIdx.x, b = blockIdx.y;
    const int d = threadIdx.x;  // 512
    const int s0 = c * 60;
    float m0 = -1e30f, m1 = -1e30f, m2 = -1e30f, m3 = -1e30f;
    for (int s = s0; s < s0 + 60; s += 4) {
        m0 = fmaxf(m0, x[((size_t)(b * SEQ + s + 0)) * DIM + d]);
        m1 = fmaxf(m1, x[((size_t)(b * SEQ + s + 1)) * DIM + d]);
        m2 = fmaxf(m2, x[((size_t)(b * SEQ + s + 2)) * DIM + d]);
        m3 = fmaxf(m3, x[((size_t)(b * SEQ + s + 3)) * DIM + d]);
    }
    part[((size_t)(b * 13 + c)) * DIM + d] = fmaxf(fmaxf(m0, m1), fmaxf(m2, m3));
}

__global__ void maxpool2_kernel(const float* __restrict__ part, float* __restrict__ o) {
    const int b = blockIdx.x, d = threadIdx.x;
    float m = -1e30f;
#pragma unroll
    for (int c = 0; c < 13; c++) m = fmaxf(m, part[((size_t)(b * 13 + c)) * DIM + d]);
    o[b * DIM + d] = m;
}

// ---------------- head softmax @ anchors ----------------
__global__ void head_kernel(const float* __restrict__ h2, float* __restrict__ out) {
    const int bg = blockIdx.x;
    const int b = bg / 17, g = bg % 17;
    const int tid = threadIdx.x;  // 64
    float v = h2[b * OUTD + g * 64 + tid];
    __shared__ float wred[2];
    __shared__ float wts[64];
    float m = v;
    for (int off = 16; off; off >>= 1) m = fmaxf(m, __shfl_xor_sync(0xffffffffu, m, off));
    if ((tid & 31) == 0) wred[tid >> 5] = m;
    __syncthreads();
    m = fmaxf(wred[0], wred[1]);
    float e = expf(v - m);
    float s = e;
    for (int off = 16; off; off >>= 1) s += __shfl_xor_sync(0xffffffffu, s, off);
    __syncthreads();
    if ((tid & 31) == 0) wred[tid >> 5] = s;
    __syncthreads();
    float tot = wred[0] + wred[1];
    wts[tid] = e / tot;
    __syncthreads();
    if (tid < 3) {
        float acc = 0.f;
        for (int j = 0; j < 64; j++) {
            float ac = (tid == 0) ? (-1.5f + (float)(j >> 4))
                     : (tid == 1) ? (-1.5f + (float)((j >> 2) & 3))
                                  : (-1.5f + (float)(j & 3));
            acc += wts[j] * ac;
        }
        out[(size_t)(b * 17 + g) * 3 + tid] = acc;
    }
}

// ---------------- launch ----------------
#define FPS_SMEM (NTOT * 4 * 4)
#define ATTN_SMEM (64 * ATTN_STRIDE * 4 * 4)

extern "C" void kernel_launch(void* const* d_in, const int* in_sizes, int n_in,
                              void* d_out, int out_size) {
    const float* points     = (const float*)d_in[0];
    const float* conv_d_w   = (const float*)d_in[1];
    const float* conv_f_w   = (const float*)d_in[2];
    const float* pos_w      = (const float*)d_in[3];
    const float* pos_b      = (const float*)d_in[4];
    const float* ln1_g      = (const float*)d_in[5];
    const float* ln1_b      = (const float*)d_in[6];
    const float* qkv_w      = (const float*)d_in[7];
    const float* attn_out_w = (const float*)d_in[8];
    const float* attn_out_b = (const float*)d_in[9];
    const float* ln2_g      = (const float*)d_in[10];
    const float* ln2_b      = (const float*)d_in[11];
    const float* ff1_w      = (const float*)d_in[12];
    const float* ff1_b      = (const float*)d_in[13];
    const float* ff2_w      = (const float*)d_in[14];
    const float* ff2_b      = (const float*)d_in[15];
    const float* head_ln_g  = (const float*)d_in[16];
    const float* head_ln_b  = (const float*)d_in[17];
    const float* head1_w    = (const float*)d_in[18];
    const float* head1_b    = (const float*)d_in[19];
    const float* head2_w    = (const float*)d_in[20];
    const float* head2_b    = (const float*)d_in[21];
    float* out = (float*)d_out;

    static bool inited = false;
    static float *p_axyz, *p_x, *p_qkv, *p_att, *p_ff1, *p_pmax, *p_pool, *p_pooln, *p_h1, *p_h2;
    static float2* p_stats;
    static float *p_t_qkv, *p_t_ao, *p_t_ff1, *p_t_ff2;
    if (!inited) {
        cudaGetSymbolAddress((void**)&p_axyz, g_axyz);
        cudaGetSymbolAddress((void**)&p_x, g_x);
        cudaGetSymbolAddress((void**)&p_qkv, g_qkv);
        cudaGetSymbolAddress((void**)&p_att, g_att);
        cudaGetSymbolAddress((void**)&p_ff1, g_ff1);
        cudaGetSymbolAddress((void**)&p_stats, g_stats);
        cudaGetSymbolAddress((void**)&p_pmax, g_pmax);
        cudaGetSymbolAddress((void**)&p_pool, g_pool);
        cudaGetSymbolAddress((void**)&p_pooln, g_pooln);
        cudaGetSymbolAddress((void**)&p_h1, g_h1);
        cudaGetSymbolAddress((void**)&p_h2, g_h2);
        cudaGetSymbolAddress((void**)&p_t_qkv, g_t_qkv);
        cudaGetSymbolAddress((void**)&p_t_ao, g_t_ao);
        cudaGetSymbolAddress((void**)&p_t_ff1, g_t_ff1);
        cudaGetSymbolAddress((void**)&p_t_ff2, g_t_ff2);
        cudaFuncSetAttribute(fps_kernel, cudaFuncAttributeMaxDynamicSharedMemorySize, FPS_SMEM);
        cudaFuncSetAttribute(attn_kernel, cudaFuncAttributeMaxDynamicSharedMemorySize, ATTN_SMEM);
        inited = true;
    }

    // 0. transpose + tf32-round all weights (single launch)
    wtrans_all_kernel<<<DEPTH * 2048, 256>>>(qkv_w, attn_out_w, ff1_w, ff2_w,
                                             p_t_qkv, p_t_ao, p_t_ff1, p_t_ff2);

    // 1. FPS anchors
    fps_kernel<<<BD * NF, 512, FPS_SMEM>>>(points, p_axyz);
    // 2. grouping + conv + max + positional embed -> x
    group_kernel<<<dim3(MM, NF, BD), 256>>>(points, conv_d_w, conv_f_w, pos_w, pos_b, p_axyz, p_x);

    // 3. transformer (tensor-core tf32 GEMMs, LN fused into A-load)
    const int MT = (ROWS + 127) / 128;  // 49
    for (int l = 0; l < DEPTH; l++) {
        ln_stats_kernel<<<ROWS / 8, 256>>>(p_x, p_stats);
        mma_gemm<true, false, false, false><<<dim3((3 * INNER) / 128, MT), 256>>>(
            p_x, p_t_qkv + (size_t)l * 3 * INNER * DIM, p_stats, ln1_g + l * DIM, ln1_b + l * DIM,
            nullptr, nullptr, p_qkv, ROWS, DIM, 3 * INNER);
        attn_kernel<<<dim3(13, HEADS, BD), 256, ATTN_SMEM>>>(p_qkv, p_att);
        mma_gemm<false, true, false, true><<<dim3(DIM / 128, MT), 256>>>(
            p_att, p_t_ao + (size_t)l * DIM * INNER, nullptr, nullptr, nullptr,
            attn_out_b + l * DIM, p_x, p_x, ROWS, INNER, DIM);
        ln_stats_kernel<<<ROWS / 8, 256>>>(p_x, p_stats);
        mma_gemm<true, true, true, false><<<dim3(MLP / 128, MT), 256>>>(
            p_x, p_t_ff1 + (size_t)l * MLP * DIM, p_stats, ln2_g + l * DIM, ln2_b + l * DIM,
            ff1_b + l * MLP, nullptr, p_ff1, ROWS, DIM, MLP);
        mma_gemm<false, true, false, true><<<dim3(DIM / 128, MT), 256>>>(
            p_ff1, p_t_ff2 + (size_t)l * DIM * MLP, nullptr, nullptr, nullptr,
            ff2_b + l * DIM, p_x, p_x, ROWS, MLP, DIM);
    }

    // 4. head (tiny GEMMs stay on SIMT path)
    maxpool1_kernel<<<dim3(13, BD), DIM>>>(p_x, p_pmax);
    maxpool2_kernel<<<BD, DIM>>>(p_pmax, p_pool);
    ln_kernel<<<BD, 128>>>(p_pool, head_ln_g, head_ln_b, p_pooln);
    gemm128<true, true, false><<<dim3(MLP / 64, 1), 256>>>(p_pooln, head1_w, head1_b, nullptr, p_h1, BD, DIM, MLP);
    gemm128<true, false, false><<<dim3(OUTD / 64, 1), 256>>>(p_h1, head2_w, head2_b, nullptr, p_h2, BD, MLP, OUTD);
    head_kernel<<<BD * 17, 64>>>(p_h2, out);
}

// round 10
// speedup vs baseline: 3.2942x; 1.1352x over previous
#include <cuda_runtime.h>
#include <cuda_bf16.h>
#include <math.h>
#include <stdint.h>

// ---------------- problem constants ----------------
#define BD 8
#define LD 5
#define NP 4096
#define NANCH 64
#define NTOT 4160          // NP + NANCH
#define MM 260             // NTOT / 16
#define NF 3
#define SEQ 780            // NF*MM
#define ROWS 6240          // BD*SEQ
#define DIM 512
#define HEADS 8
#define DH 64
#define INNER 512
#define MLP 1024
#define OUTD 1088
#define KNN 32
#define DEPTH 5

// ---------------- scratch (device globals; no allocation allowed) ----------------
__device__ float g_axyz[BD * NF * MM * 3];
__device__ float g_x[ROWS * DIM];
__device__ float g_qkv[ROWS * 3 * INNER];
__device__ float g_att[ROWS * INNER];
__device__ float g_ff1[ROWS * MLP];
__device__ float2 g_stats[ROWS];
__device__ float g_pmax[BD * 13 * DIM];
__device__ float g_pool[BD * DIM];
__device__ float g_pooln[BD * DIM];
__device__ float g_h1[BD * MLP];
__device__ float g_h2[BD * OUTD];
// transposed (and tf32-rounded) weights, layout [n][k]
__device__ float g_t_qkv[DEPTH * 3 * INNER * DIM];
__device__ float g_t_ao [DEPTH * DIM * INNER];
__device__ float g_t_ff1[DEPTH * MLP * DIM];
__device__ float g_t_ff2[DEPTH * DIM * MLP];

// ---------------- helpers ----------------
__device__ __forceinline__ float to_tf32(float x) {
    uint32_t u; asm("cvt.rna.tf32.f32 %0, %1;" : "=r"(u) : "f"(x));
    return __uint_as_float(u);
}

__device__ __forceinline__ void get_pt(const float* __restrict__ pts, int b, int layer, int j,
                                       float& x, float& y, float& z) {
    if (j < NP) {
        const float* p = pts + ((size_t)((b * LD + layer) * NP + j)) * 3;
        x = p[0]; y = p[1]; z = p[2];
    } else {
        int i = j - NP;
        x = -1.5f + (float)(i >> 4);
        y = -1.5f + (float)((i >> 2) & 3);
        z = -1.5f + (float)(i & 3);
    }
}

__device__ __forceinline__ float gelu_f(float x) {
    return 0.5f * x * (1.0f + erff(x * 0.7071067811865476f));
}

__device__ __forceinline__ void mma_tf32(float* d, const uint32_t* a, const uint32_t* b) {
    asm volatile(
        "mma.sync.aligned.m16n8k8.row.col.f32.tf32.tf32.f32 "
        "{%0,%1,%2,%3}, {%4,%5,%6,%7}, {%8,%9}, {%0,%1,%2,%3};"
        : "+f"(d[0]), "+f"(d[1]), "+f"(d[2]), "+f"(d[3])
        : "r"(a[0]), "r"(a[1]), "r"(a[2]), "r"(a[3]), "r"(b[0]), "r"(b[1]));
}

// ---------------- FPS: one block per (b, frame) ----------------
__global__ void fps_kernel(const float* __restrict__ points, float* __restrict__ axyz) {
    const int bf = blockIdx.x;
    const int b = bf / NF, f = bf % NF;
    const int layer = 2 * f;
    extern __shared__ float sm[];
    float* sx = sm;
    float* sy = sm + NTOT;
    float* sz = sm + 2 * NTOT;
    float* dist = sm + 3 * NTOT;
    __shared__ float rv[16];
    __shared__ int ri[16];
    __shared__ int s_last;
    int tid = threadIdx.x;

    for (int j = tid; j < NTOT; j += 512) {
        float x, y, z;
        get_pt(points, b, layer, j, x, y, z);
        sx[j] = x; sy[j] = y; sz[j] = z;
        dist[j] = 1e10f;
    }
    __syncthreads();

    int last = 0;
    float* aout = axyz + (size_t)bf * MM * 3;
    for (int s = 0; s < MM; s++) {
        float lx = sx[last], ly = sy[last], lz = sz[last];
        if (tid == 0) { aout[s * 3 + 0] = lx; aout[s * 3 + 1] = ly; aout[s * 3 + 2] = lz; }
        float bv = -1.0f; int bi = 0x7fffffff;
        for (int j = tid; j < NTOT; j += 512) {
            float dx = sx[j] - lx, dy = sy[j] - ly, dz = sz[j] - lz;
            float d = __fadd_rn(__fadd_rn(__fmul_rn(dx, dx), __fmul_rn(dy, dy)), __fmul_rn(dz, dz));
            float nd = fminf(dist[j], d);
            dist[j] = nd;
            if (nd > bv) { bv = nd; bi = j; }
        }
        for (int off = 16; off; off >>= 1) {
            float ov = __shfl_down_sync(0xffffffffu, bv, off);
            int oi = __shfl_down_sync(0xffffffffu, bi, off);
            if (ov > bv || (ov == bv && oi < bi)) { bv = ov; bi = oi; }
        }
        if ((tid & 31) == 0) { rv[tid >> 5] = bv; ri[tid >> 5] = bi; }
        __syncthreads();
        if (tid < 32) {
            float v2 = (tid < 16) ? rv[tid] : -2.0f;
            int i2 = (tid < 16) ? ri[tid] : 0x7fffffff;
            for (int off = 8; off; off >>= 1) {
                float ov = __shfl_down_sync(0xffffffffu, v2, off);
                int oi = __shfl_down_sync(0xffffffffu, i2, off);
                if (ov > v2 || (ov == v2 && oi < i2)) { v2 = ov; i2 = oi; }
            }
            if (tid == 0) s_last = i2;
        }
        __syncthreads();
        last = s_last;
    }
}

// ---------------- ball query + conv + maxpool + pos embed ----------------
__global__ void group_kernel(const float* __restrict__ points,
                             const float* __restrict__ conv_d_w,
                             const float* __restrict__ conv_f_w,
                             const float* __restrict__ pos_w,
                             const float* __restrict__ pos_b,
                             const float* __restrict__ axyz,
                             float* __restrict__ xout) {
    const int m = blockIdx.x, f = blockIdx.y, b = blockIdx.z;
    __shared__ float gpts[3][KNN][3];
    __shared__ int scnt[3];
    __shared__ float sa[3];
    const int tid = threadIdx.x;

    if (tid < 3) sa[tid] = axyz[((size_t)((b * NF + f) * MM + m)) * 3 + tid];
    __syncthreads();
    const float ax = sa[0], ay = sa[1], az = sa[2];

    const int w = tid >> 5, lane = tid & 31;
    if (w < 3) {
        int layer = 2 * f - 1 + w;
        layer = layer < 0 ? 0 : (layer > 4 ? 4 : layer);
        const float R2 = (float)(0.7 * 0.7);
        int cnt = 0;
        for (int j0 = 0; j0 < NTOT && cnt < KNN; j0 += 32) {
            int j = j0 + lane;
            float px, py, pz;
            get_pt(points, b, layer, j, px, py, pz);
            float dx = px - ax, dy = py - ay, dz = pz - az;
            float d2 = __fadd_rn(__fadd_rn(__fmul_rn(dx, dx), __fmul_rn(dy, dy)), __fmul_rn(dz, dz));
            unsigned mask = __ballot_sync(0xffffffffu, d2 < R2);
            while (mask && cnt < KNN) {
                int src = __ffs(mask) - 1;
                mask &= mask - 1;
                float gx = __shfl_sync(0xffffffffu, px, src);
                float gy = __shfl_sync(0xffffffffu, py, src);
                float gz = __shfl_sync(0xffffffffu, pz, src);
                if (lane == 0) { gpts[w][cnt][0] = gx; gpts[w][cnt][1] = gy; gpts[w][cnt][2] = gz; }
                cnt++;
            }
        }
        if (cnt == 0) {
            if (lane == 0) {
                float gx, gy, gz;
                get_pt(points, b, layer, 0, gx, gy, gz);
                gpts[w][0][0] = gx; gpts[w][0][1] = gy; gpts[w][0][2] = gz;
            }
            cnt = 1;
        }
        if (lane == 0) scnt[w] = cnt;
    }
    __syncthreads();

    const int cs[3] = {scnt[0], scnt[1], scnt[2]};
#pragma unroll
    for (int dd = 0; dd < 2; dd++) {
        int d = tid + dd * 256;
        float wf0 = conv_f_w[d * 3 + 0], wf1 = conv_f_w[d * 3 + 1], wf2 = conv_f_w[d * 3 + 2];
        float wd0 = conv_d_w[d * 4 + 0], wd1 = conv_d_w[d * 4 + 1], wd2 = conv_d_w[d * 4 + 2], wd3 = conv_d_w[d * 4 + 3];
        float ws0 = wf0 + wd0, ws1 = wf1 + wd1, ws2 = wf2 + wd2;
        float adot = ax * wd0 + ay * wd1 + az * wd2;
        float maxv = -1e30f;
        for (int ww = 0; ww < 3; ww++) {
            float dt = (float)(ww - 1);
            float base = dt * wd3 - adot;
            int cn = cs[ww];
            for (int k = 0; k < cn; k++) {
                float gx = gpts[ww][k][0], gy = gpts[ww][k][1], gz = gpts[ww][k][2];
                float v = fmaf(gx, ws0, fmaf(gy, ws1, fmaf(gz, ws2, base)));
                maxv = fmaxf(maxv, v);
            }
        }
        float pw0 = pos_w[d * 4 + 0], pw1 = pos_w[d * 4 + 1], pw2 = pos_w[d * 4 + 2], pw3 = pos_w[d * 4 + 3];
        float t = (float)(f + 1);
        float outv = maxv + ax * pw0 + ay * pw1 + az * pw2 + t * pw3 + pos_b[d];
        xout[((size_t)(b * SEQ + f * MM + m)) * DIM + d] = outv;
    }
}

// ---------------- per-row LN stats: one warp per row ----------------
__global__ __launch_bounds__(256)
void ln_stats_kernel(const float* __restrict__ x, float2* __restrict__ stats) {
    const int row = blockIdx.x * 8 + (threadIdx.x >> 5);
    const int lane = threadIdx.x & 31;
    const float* xr = x + (size_t)row * DIM;
    float4 v[4];
#pragma unroll
    for (int i = 0; i < 4; i++) v[i] = *reinterpret_cast<const float4*>(xr + i * 128 + lane * 4);
    float s = 0.f;
#pragma unroll
    for (int i = 0; i < 4; i++) s += v[i].x + v[i].y + v[i].z + v[i].w;
    for (int off = 16; off; off >>= 1) s += __shfl_xor_sync(0xffffffffu, s, off);
    float mu = s * (1.0f / DIM);
    float q = 0.f;
#pragma unroll
    for (int i = 0; i < 4; i++) {
        float a = v[i].x - mu, b = v[i].y - mu, c = v[i].z - mu, d = v[i].w - mu;
        q += a * a + b * b + c * c + d * d;
    }
    for (int off = 16; off; off >>= 1) q += __shfl_xor_sync(0xffffffffu, q, off);
    if (lane == 0) {
        float2 st; st.x = mu; st.y = rsqrtf(q * (1.0f / DIM) + 1e-5f);
        stats[row] = st;
    }
}

// ---------------- LayerNorm (head path, rows x 512) ----------------
__global__ void ln_kernel(const float* __restrict__ x, const float* __restrict__ gg,
                          const float* __restrict__ bb, float* __restrict__ y) {
    const int r = blockIdx.x;
    const float* xr = x + (size_t)r * DIM;
    float* yr = y + (size_t)r * DIM;
    const int tid = threadIdx.x;
    float v[4];
    float s = 0.f;
#pragma unroll
    for (int i = 0; i < 4; i++) { v[i] = xr[tid + i * 128]; s += v[i]; }
    __shared__ float red[4];
    __shared__ float s_stat;
    for (int off = 16; off; off >>= 1) s += __shfl_down_sync(0xffffffffu, s, off);
    if ((tid & 31) == 0) red[tid >> 5] = s;
    __syncthreads();
    if (tid == 0) s_stat = (red[0] + red[1] + red[2] + red[3]) * (1.0f / DIM);
    __syncthreads();
    float mu = s_stat;
    float q = 0.f;
#pragma unroll
    for (int i = 0; i < 4; i++) { float d = v[i] - mu; q += d * d; }
    __syncthreads();
    for (int off = 16; off; off >>= 1) q += __shfl_down_sync(0xffffffffu, q, off);
    if ((tid & 31) == 0) red[tid >> 5] = q;
    __syncthreads();
    if (tid == 0) s_stat = (red[0] + red[1] + red[2] + red[3]) * (1.0f / DIM);
    __syncthreads();
    float inv = rsqrtf(s_stat + 1e-5f);
#pragma unroll
    for (int i = 0; i < 4; i++) {
        int c = tid + i * 128;
        yr[c] = (v[i] - mu) * inv * gg[c] + bb[c];
    }
}

// ---------------- merged weight transpose (+tf32 round), all 20 matrices ----------------
__global__ __launch_bounds__(256)
void wtrans_all_kernel(const float* __restrict__ qkv_w, const float* __restrict__ ao_w,
                       const float* __restrict__ ff1_w, const float* __restrict__ ff2_w,
                       float* __restrict__ t_qkv, float* __restrict__ t_ao,
                       float* __restrict__ t_ff1, float* __restrict__ t_ff2) {
    __shared__ float t[32][33];
    const int tile = blockIdx.x;
    const int l = tile / 2048;
    int r = tile % 2048;
    const float* W; float* Wt; int K, N, bx, by;
    if (r < 768) {
        W = qkv_w + (size_t)l * DIM * 1536; Wt = t_qkv + (size_t)l * 1536 * DIM;
        K = DIM; N = 1536; bx = r % 48; by = r / 48;
    } else if (r < 1024) {
        r -= 768;
        W = ao_w + (size_t)l * INNER * DIM; Wt = t_ao + (size_t)l * DIM * INNER;
        K = INNER; N = DIM; bx = r % 16; by = r / 16;
    } else if (r < 1536) {
        r -= 1024;
        W = ff1_w + (size_t)l * DIM * MLP; Wt = t_ff1 + (size_t)l * MLP * DIM;
        K = DIM; N = MLP; bx = r % 32; by = r / 32;
    } else {
        r -= 1536;
        W = ff2_w + (size_t)l * MLP * DIM; Wt = t_ff2 + (size_t)l * DIM * MLP;
        K = MLP; N = DIM; bx = r % 16; by = r / 16;
    }
    const int n0 = bx * 32, k0 = by * 32;
    const int x = threadIdx.x & 31, y = threadIdx.x >> 5;  // 32 x 8
#pragma unroll
    for (int i = y; i < 32; i += 8)
        t[i][x] = W[(size_t)(k0 + i) * N + n0 + x];
    __syncthreads();
#pragma unroll
    for (int i = y; i < 32; i += 8)
        Wt[(size_t)(n0 + i) * K + k0 + x] = to_tf32(t[x][i]);
}

// ---------------- tensor-core tf32 GEMM via mma.sync: C = A @ Bt^T ----------------
template <bool WITH_LN, bool WITH_BIAS, bool WITH_GELU, bool WITH_RES>
__global__ __launch_bounds__(256)
void mma_gemm(const float* __restrict__ A, const float* __restrict__ Bt,
              const float2* __restrict__ stats, const float* __restrict__ lng,
              const float* __restrict__ lnb,
              const float* __restrict__ bias, const float* __restrict__ Rd,
              float* __restrict__ C, int Rr, int Kd, int Cn) {
    __shared__ float As[128][36];
    __shared__ float Bs[128][36];
    const int bm = blockIdx.y * 128, bn = blockIdx.x * 128;
    const int tid = threadIdx.x, wid = tid >> 5, lane = tid & 31;
    const int wm = wid & 3, wn = wid >> 2;
    const int gid = lane >> 2, tig = lane & 3;

    float acc[2][8][4];
#pragma unroll
    for (int mt = 0; mt < 2; mt++)
#pragma unroll
        for (int nt = 0; nt < 8; nt++)
#pragma unroll
            for (int i = 0; i < 4; i++) acc[mt][nt][i] = 0.f;

    for (int k0 = 0; k0 < Kd; k0 += 32) {
#pragma unroll
        for (int i = 0; i < 4; i++) {
            int lin = tid + i * 256;
            int row = lin >> 3, kq = (lin & 7) * 4;
            float4 v = make_float4(0.f, 0.f, 0.f, 0.f);
            if (bm + row < Rr) {
                v = *reinterpret_cast<const float4*>(A + (size_t)(bm + row) * Kd + k0 + kq);
                if (WITH_LN) {
                    float2 st = stats[bm + row];
                    float4 gv = *reinterpret_cast<const float4*>(lng + k0 + kq);
                    float4 bv = *reinterpret_cast<const float4*>(lnb + k0 + kq);
                    v.x = (v.x - st.x) * st.y * gv.x + bv.x;
                    v.y = (v.y - st.x) * st.y * gv.y + bv.y;
                    v.z = (v.z - st.x) * st.y * gv.z + bv.z;
                    v.w = (v.w - st.x) * st.y * gv.w + bv.w;
                }
            }
            v.x = to_tf32(v.x); v.y = to_tf32(v.y); v.z = to_tf32(v.z); v.w = to_tf32(v.w);
            As[row][kq] = v.x; As[row][kq + 1] = v.y; As[row][kq + 2] = v.z; As[row][kq + 3] = v.w;
            float4 wv = *reinterpret_cast<const float4*>(Bt + (size_t)(bn + row) * Kd + k0 + kq);
            Bs[row][kq] = wv.x; Bs[row][kq + 1] = wv.y; Bs[row][kq + 2] = wv.z; Bs[row][kq + 3] = wv.w;
        }
        __syncthreads();
#pragma unroll
        for (int ks = 0; ks < 4; ks++) {
            const int kb = ks * 8;
            uint32_t af[2][4];
#pragma unroll
            for (int mt = 0; mt < 2; mt++) {
                int row = wm * 32 + mt * 16 + gid;
                af[mt][0] = __float_as_uint(As[row][kb + tig]);
                af[mt][1] = __float_as_uint(As[row + 8][kb + tig]);
                af[mt][2] = __float_as_uint(As[row][kb + tig + 4]);
                af[mt][3] = __float_as_uint(As[row + 8][kb + tig + 4]);
            }
            uint32_t bf[8][2];
#pragma unroll
            for (int nt = 0; nt < 8; nt++) {
                int col = wn * 64 + nt * 8 + gid;
                bf[nt][0] = __float_as_uint(Bs[col][kb + tig]);
                bf[nt][1] = __float_as_uint(Bs[col][kb + tig + 4]);
            }
#pragma unroll
            for (int mt = 0; mt < 2; mt++)
#pragma unroll
                for (int nt = 0; nt < 8; nt++)
                    mma_tf32(acc[mt][nt], af[mt], bf[nt]);
        }
        __syncthreads();
    }

#pragma unroll
    for (int mt = 0; mt < 2; mt++) {
#pragma unroll
        for (int half = 0; half < 2; half++) {
            int row = bm + wm * 32 + mt * 16 + half * 8 + gid;
            if (row >= Rr) continue;
            float* crow = C + (size_t)row * Cn;
            const float* rrow = WITH_RES ? (Rd + (size_t)row * Cn) : nullptr;
#pragma unroll
            for (int nt = 0; nt < 8; nt++) {
                int col = bn + wn * 64 + nt * 8 + 2 * tig;
                float v0 = acc[mt][nt][half * 2 + 0];
                float v1 = acc[mt][nt][half * 2 + 1];
                if (WITH_BIAS) { v0 += bias[col]; v1 += bias[col + 1]; }
                if (WITH_GELU) { v0 = gelu_f(v0); v1 = gelu_f(v1); }
                if (WITH_RES)  { v0 += rrow[col]; v1 += rrow[col + 1]; }
                float2 o2; o2.x = v0; o2.y = v1;
                *reinterpret_cast<float2*>(crow + col) = o2;
            }
        }
    }
}

// ---------------- fp32 tiled GEMM (head GEMMs, tiny M) ----------------
template <bool WITH_BIAS, bool WITH_GELU, bool WITH_RES>
__global__ __launch_bounds__(256)
void gemm128(const float* __restrict__ A, const float* __restrict__ W,
             const float* __restrict__ bias, const float* __restrict__ Rd,
             float* __restrict__ C, int Rr, int Kd, int Cn) {
    __shared__ float As[8][132];
    __shared__ float Bs[8][64];
    const int bn = blockIdx.x * 64;
    const int bm = blockIdx.y * 128;
    const int tid = threadIdx.x;
    const int tx = tid & 15, ty = tid >> 4;
    float acc[8][4];
#pragma unroll
    for (int u = 0; u < 8; u++)
#pragma unroll
        for (int v = 0; v < 4; v++) acc[u][v] = 0.f;

    const int arow = bm + (tid >> 1);
    const int kh = (tid & 1) * 4;
    const bool aval = arow < Rr;
    const int am = tid >> 1;
    const int bk = tid >> 4;
    const int bn4 = (tid & 15) * 4;

    for (int k0 = 0; k0 < Kd; k0 += 8) {
        float4 av = make_float4(0.f, 0.f, 0.f, 0.f);
        if (aval) av = *reinterpret_cast<const float4*>(A + (size_t)arow * Kd + k0 + kh);
        As[kh + 0][am] = av.x; As[kh + 1][am] = av.y; As[kh + 2][am] = av.z; As[kh + 3][am] = av.w;
        if (tid < 128) {
            float4 bv = *reinterpret_cast<const float4*>(W + (size_t)(k0 + bk) * Cn + bn + bn4);
            *reinterpret_cast<float4*>(&Bs[bk][bn4]) = bv;
        }
        __syncthreads();
#pragma unroll
        for (int kk = 0; kk < 8; kk++) {
            float4 a0 = *reinterpret_cast<const float4*>(&As[kk][ty * 8]);
            float4 a1 = *reinterpret_cast<const float4*>(&As[kk][ty * 8 + 4]);
            float4 b4 = *reinterpret_cast<const float4*>(&Bs[kk][tx * 4]);
            float aa[8] = {a0.x, a0.y, a0.z, a0.w, a1.x, a1.y, a1.z, a1.w};
            float bb4[4] = {b4.x, b4.y, b4.z, b4.w};
#pragma unroll
            for (int u = 0; u < 8; u++)
#pragma unroll
                for (int v = 0; v < 4; v++) acc[u][v] = fmaf(aa[u], bb4[v], acc[u][v]);
        }
        __syncthreads();
    }
#pragma unroll
    for (int u = 0; u < 8; u++) {
        int row = bm + ty * 8 + u;
        if (row < Rr) {
#pragma unroll
            for (int v = 0; v < 4; v++) {
                int col = bn + tx * 4 + v;
                float c = acc[u][v];
                if (WITH_BIAS) c += bias[col];
                if (WITH_GELU) c = gelu_f(c);
                if (WITH_RES) c += Rd[(size_t)row * Cn + col];
                C[(size_t)row * Cn + col] = c;
            }
        }
    }
}

// ---------------- attention: flash, tensor-core QK^T and PV (tf32, A-operands split hi/lo) ----------------
// smem tiles stride 68: Qhi, Qlo, Ks, Vs, Ph(S then p_hi), Pl + crow[64] + lrow[64]
#define ASTR 68
#define ATTN_SMEM ((6 * 64 * ASTR + 128) * 4)
__global__ __launch_bounds__(256)
void attn_kernel(const float* __restrict__ qkv, float* __restrict__ o) {
    extern __shared__ float sm[];
    float* Qhi = sm;
    float* Qlo = Qhi + 64 * ASTR;
    float* Ks  = Qlo + 64 * ASTR;
    float* Vs  = Ks  + 64 * ASTR;
    float* Ph  = Vs  + 64 * ASTR;
    float* Pl  = Ph  + 64 * ASTR;
    float* crow = Pl + 64 * ASTR;   // 64
    float* lrow = crow + 64;        // 64

    const int qt = blockIdx.x, h = blockIdx.y, b = blockIdx.z;
    const int tid = threadIdx.x, lane = tid & 31, wid = tid >> 5;
    const int wm = wid & 3, wn = wid >> 2;      // 4m x 2n warp grid over 64x64
    const int gid = lane >> 2, tig = lane & 3;

    // load Q tile, split hi/lo
#pragma unroll
    for (int i = 0; i < 16; i++) {
        int lid = tid + i * 256;
        int r = lid >> 6, d = lid & 63;
        int s = qt * 64 + r;
        float q = (s < SEQ) ? qkv[((size_t)(b * SEQ + s)) * (3 * INNER) + h * DH + d] : 0.f;
        float qh = to_tf32(q);
        Qhi[r * ASTR + d] = qh;
        Qlo[r * ASTR + d] = to_tf32(q - qh);
    }

    float oacc[4][4];
#pragma unroll
    for (int nt = 0; nt < 4; nt++)
#pragma unroll
        for (int i = 0; i < 4; i++) oacc[nt][i] = 0.f;
    float mcur = -1e30f, lcur = 0.f;   // softmax-thread state (row = tid>>2)
    const int srow = tid >> 2;
    const int scol = (tid & 3) * 16;
    __syncthreads();

    for (int kt = 0; kt < 13; kt++) {
        // load K/V tiles (k-major, tf32-rounded)
#pragma unroll
        for (int i = 0; i < 16; i++) {
            int lid = tid + i * 256;
            int r = lid >> 6, d = lid & 63;
            int s = kt * 64 + r;
            size_t base = ((size_t)(b * SEQ + (s < SEQ ? s : 0))) * (3 * INNER) + h * DH + d;
            Ks[r * ASTR + d] = (s < SEQ) ? to_tf32(qkv[base + INNER]) : 0.f;
            Vs[r * ASTR + d] = (s < SEQ) ? to_tf32(qkv[base + 2 * INNER]) : 0.f;
        }
        __syncthreads();

        // S = Q @ K^T  (m16 rows = wm*16.., n32 cols = wn*32..)
        float sacc[4][4];
#pragma unroll
        for (int nt = 0; nt < 4; nt++)
#pragma unroll
            for (int i = 0; i < 4; i++) sacc[nt][i] = 0.f;
#pragma unroll
        for (int ks = 0; ks < 8; ks++) {
            const int kb = ks * 8;
            const int r0 = (wm * 16 + gid) * ASTR;
            uint32_t ah[4], al[4];
            ah[0] = __float_as_uint(Qhi[r0 + kb + tig]);
            ah[1] = __float_as_uint(Qhi[r0 + 8 * ASTR + kb + tig]);
            ah[2] = __float_as_uint(Qhi[r0 + kb + tig + 4]);
            ah[3] = __float_as_uint(Qhi[r0 + 8 * ASTR + kb + tig + 4]);
            al[0] = __float_as_uint(Qlo[r0 + kb + tig]);
            al[1] = __float_as_uint(Qlo[r0 + 8 * ASTR + kb + tig]);
            al[2] = __float_as_uint(Qlo[r0 + kb + tig + 4]);
            al[3] = __float_as_uint(Qlo[r0 + 8 * ASTR + kb + tig + 4]);
#pragma unroll
            for (int nt = 0; nt < 4; nt++) {
                const int nc = (wn * 32 + nt * 8 + gid) * ASTR;
                uint32_t bf[2];
                bf[0] = __float_as_uint(Ks[nc + kb + tig]);
                bf[1] = __float_as_uint(Ks[nc + kb + tig + 4]);
                mma_tf32(sacc[nt], ah, bf);
                mma_tf32(sacc[nt], al, bf);
            }
        }
        // write S (scaled, masked) to Ph
        {
            const int r0 = wm * 16 + gid;
#pragma unroll
            for (int nt = 0; nt < 4; nt++) {
                int c = wn * 32 + nt * 8 + 2 * tig;
                int kg = kt * 64 + c;
                float2 s01, s23;
                s01.x = (kg < SEQ)     ? sacc[nt][0] * 0.125f : -1e30f;
                s01.y = (kg + 1 < SEQ) ? sacc[nt][1] * 0.125f : -1e30f;
                s23.x = (kg < SEQ)     ? sacc[nt][2] * 0.125f : -1e30f;
                s23.y = (kg + 1 < SEQ) ? sacc[nt][3] * 0.125f : -1e30f;
                *reinterpret_cast<float2*>(&Ph[r0 * ASTR + c]) = s01;
                *reinterpret_cast<float2*>(&Ph[(r0 + 8) * ASTR + c]) = s23;
            }
        }
        __syncthreads();

        // softmax: 4 lanes per row, 16 cols each; in-place Ph -> p_hi, Pl -> p_lo
        {
            float sv[16];
#pragma unroll
            for (int i = 0; i < 4; i++) {
                float4 v4 = *reinterpret_cast<const float4*>(&Ph[srow * ASTR + scol + i * 4]);
                sv[i * 4 + 0] = v4.x; sv[i * 4 + 1] = v4.y; sv[i * 4 + 2] = v4.z; sv[i * 4 + 3] = v4.w;
            }
            float rm = sv[0];
#pragma unroll
            for (int i = 1; i < 16; i++) rm = fmaxf(rm, sv[i]);
            rm = fmaxf(rm, __shfl_xor_sync(0xffffffffu, rm, 1));
            rm = fmaxf(rm, __shfl_xor_sync(0xffffffffu, rm, 2));
            float mnew = fmaxf(mcur, rm);
            float corr = __expf(mcur - mnew);
            float ssum = 0.f;
#pragma unroll
            for (int i = 0; i < 4; i++) {
                float4 hv, lv;
                float p0 = __expf(sv[i * 4 + 0] - mnew);
                float p1 = __expf(sv[i * 4 + 1] - mnew);
                float p2 = __expf(sv[i * 4 + 2] - mnew);
                float p3 = __expf(sv[i * 4 + 3] - mnew);
                ssum += (p0 + p1) + (p2 + p3);
                hv.x = to_tf32(p0); hv.y = to_tf32(p1); hv.z = to_tf32(p2); hv.w = to_tf32(p3);
                lv.x = to_tf32(p0 - hv.x); lv.y = to_tf32(p1 - hv.y);
                lv.z = to_tf32(p2 - hv.z); lv.w = to_tf32(p3 - hv.w);
                *reinterpret_cast<float4*>(&Ph[srow * ASTR + scol + i * 4]) = hv;
                *reinterpret_cast<float4*>(&Pl[srow * ASTR + scol + i * 4]) = lv;
            }
            ssum += __shfl_xor_sync(0xffffffffu, ssum, 1);
            ssum += __shfl_xor_sync(0xffffffffu, ssum, 2);
            lcur = lcur * corr + ssum;
            mcur = mnew;
            if ((tid & 3) == 0) crow[srow] = corr;
        }
        __syncthreads();

        // rescale O by corr, then O += P @ V
        {
            float c0 = crow[wm * 16 + gid];
            float c1 = crow[wm * 16 + gid + 8];
#pragma unroll
            for (int nt = 0; nt < 4; nt++) {
                oacc[nt][0] *= c0; oacc[nt][1] *= c0;
                oacc[nt][2] *= c1; oacc[nt][3] *= c1;
            }
        }
#pragma unroll
        for (int ks = 0; ks < 8; ks++) {
            const int kb = ks * 8;
            const int r0 = (wm * 16 + gid) * ASTR;
            uint32_t ah[4], al[4];
            ah[0] = __float_as_uint(Ph[r0 + kb + tig]);
            ah[1] = __float_as_uint(Ph[r0 + 8 * ASTR + kb + tig]);
            ah[2] = __float_as_uint(Ph[r0 + kb + tig + 4]);
            ah[3] = __float_as_uint(Ph[r0 + 8 * ASTR + kb + tig + 4]);
            al[0] = __float_as_uint(Pl[r0 + kb + tig]);
            al[1] = __float_as_uint(Pl[r0 + 8 * ASTR + kb + tig]);
            al[2] = __float_as_uint(Pl[r0 + kb + tig + 4]);
            al[3] = __float_as_uint(Pl[r0 + 8 * ASTR + kb + tig + 4]);
#pragma unroll
            for (int nt = 0; nt < 4; nt++) {
                const int nc = wn * 32 + nt * 8 + gid;
                uint32_t bf[2];
                bf[0] = __float_as_uint(Vs[(kb + tig) * ASTR + nc]);
                bf[1] = __float_as_uint(Vs[(kb + tig + 4) * ASTR + nc]);
                mma_tf32(oacc[nt], ah, bf);
                mma_tf32(oacc[nt], al, bf);
            }
        }
        __syncthreads();
    }

    if ((tid & 3) == 0) lrow[srow] = lcur;
    __syncthreads();

    // store O
    {
        const int r0 = wm * 16 + gid;
        const int s0 = qt * 64 + r0, s1 = s0 + 8;
        float inv0 = 1.0f / lrow[r0];
        float inv1 = 1.0f / lrow[r0 + 8];
#pragma unroll
        for (int nt = 0; nt < 4; nt++) {
            int d = wn * 32 + nt * 8 + 2 * tig;
            if (s0 < SEQ) {
                float2 o2; o2.x = oacc[nt][0] * inv0; o2.y = oacc[nt][1] * inv0;
                *reinterpret_cast<float2*>(o + ((size_t)(b * SEQ + s0)) * INNER + h * DH + d) = o2;
            }
            if (s1 < SEQ) {
                float2 o2; o2.x = oacc[nt][2] * inv1; o2.y = oacc[nt][3] * inv1;
                *reinterpret_cast<float2*>(o + ((size_t)(b * SEQ + s1)) * INNER + h * DH + d) = o2;
            }
        }
    }
}

// ---------------- max over sequence: two stage ----------------
__global__ void maxpool1_kernel(const float* __restrict__ x, float* __restrict__ part) {
    const int c = blockIdx.x, b = blockIdx.y;
    const int d = threadIdx.x;  // 512
    const int s0 = c * 60;
    float m0 = -1e30f, m1 = -1e30f, m2 = -1e30f, m3 = -1e30f;
    for (int s = s0; s < s0 + 60; s += 4) {
        m0 = fmaxf(m0, x[((size_t)(b * SEQ + s + 0)) * DIM + d]);
        m1 = fmaxf(m1, x[((size_t)(b * SEQ + s + 1)) * DIM + d]);
        m2 = fmaxf(m2, x[((size_t)(b * SEQ + s + 2)) * DIM + d]);
        m3 = fmaxf(m3, x[((size_t)(b * SEQ + s + 3)) * DIM + d]);
    }
    part[((size_t)(b * 13 + c)) * DIM + d] = fmaxf(fmaxf(m0, m1), fmaxf(m2, m3));
}

__global__ void maxpool2_kernel(const float* __restrict__ part, float* __restrict__ o) {
    const int b = blockIdx.x, d = threadIdx.x;
    float m = -1e30f;
#pragma unroll
    for (int c = 0; c < 13; c++) m = fmaxf(m, part[((size_t)(b * 13 + c)) * DIM + d]);
    o[b * DIM + d] = m;
}

// ---------------- head softmax @ anchors ----------------
__global__ void head_kernel(const float* __restrict__ h2, float* __restrict__ out) {
    const int bg = blockIdx.x;
    const int b = bg / 17, g = bg % 17;
    const int tid = threadIdx.x;  // 64
    float v = h2[b * OUTD + g * 64 + tid];
    __shared__ float wred[2];
    __shared__ float wts[64];
    float m = v;
    for (int off = 16; off; off >>= 1) m = fmaxf(m, __shfl_xor_sync(0xffffffffu, m, off));
    if ((tid & 31) == 0) wred[tid >> 5] = m;
    __syncthreads();
    m = fmaxf(wred[0], wred[1]);
    float e = expf(v - m);
    float s = e;
    for (int off = 16; off; off >>= 1) s += __shfl_xor_sync(0xffffffffu, s, off);
    __syncthreads();
    if ((tid & 31) == 0) wred[tid >> 5] = s;
    __syncthreads();
    float tot = wred[0] + wred[1];
    wts[tid] = e / tot;
    __syncthreads();
    if (tid < 3) {
        float acc = 0.f;
        for (int j = 0; j < 64; j++) {
            float ac = (tid == 0) ? (-1.5f + (float)(j >> 4))
                     : (tid == 1) ? (-1.5f + (float)((j >> 2) & 3))
                                  : (-1.5f + (float)(j & 3));
            acc += wts[j] * ac;
        }
        out[(size_t)(b * 17 + g) * 3 + tid] = acc;
    }
}

// ---------------- launch ----------------
#define FPS_SMEM (NTOT * 4 * 4)

extern "C" void kernel_launch(void* const* d_in, const int* in_sizes, int n_in,
                              void* d_out, int out_size) {
    const float* points     = (const float*)d_in[0];
    const float* conv_d_w   = (const float*)d_in[1];
    const float* conv_f_w   = (const float*)d_in[2];
    const float* pos_w      = (const float*)d_in[3];
    const float* pos_b      = (const float*)d_in[4];
    const float* ln1_g      = (const float*)d_in[5];
    const float* ln1_b      = (const float*)d_in[6];
    const float* qkv_w      = (const float*)d_in[7];
    const float* attn_out_w = (const float*)d_in[8];
    const float* attn_out_b = (const float*)d_in[9];
    const float* ln2_g      = (const float*)d_in[10];
    const float* ln2_b      = (const float*)d_in[11];
    const float* ff1_w      = (const float*)d_in[12];
    const float* ff1_b      = (const float*)d_in[13];
    const float* ff2_w      = (const float*)d_in[14];
    const float* ff2_b      = (const float*)d_in[15];
    const float* head_ln_g  = (const float*)d_in[16];
    const float* head_ln_b  = (const float*)d_in[17];
    const float* head1_w    = (const float*)d_in[18];
    const float* head1_b    = (const float*)d_in[19];
    const float* head2_w    = (const float*)d_in[20];
    const float* head2_b    = (const float*)d_in[21];
    float* out = (float*)d_out;

    static bool inited = false;
    static float *p_axyz, *p_x, *p_qkv, *p_att, *p_ff1, *p_pmax, *p_pool, *p_pooln, *p_h1, *p_h2;
    static float2* p_stats;
    static float *p_t_qkv, *p_t_ao, *p_t_ff1, *p_t_ff2;
    if (!inited) {
        cudaGetSymbolAddress((void**)&p_axyz, g_axyz);
        cudaGetSymbolAddress((void**)&p_x, g_x);
        cudaGetSymbolAddress((void**)&p_qkv, g_qkv);
        cudaGetSymbolAddress((void**)&p_att, g_att);
        cudaGetSymbolAddress((void**)&p_ff1, g_ff1);
        cudaGetSymbolAddress((void**)&p_stats, g_stats);
        cudaGetSymbolAddress((void**)&p_pmax, g_pmax);
        cudaGetSymbolAddress((void**)&p_pool, g_pool);
        cudaGetSymbolAddress((void**)&p_pooln, g_pooln);
        cudaGetSymbolAddress((void**)&p_h1, g_h1);
        cudaGetSymbolAddress((void**)&p_h2, g_h2);
        cudaGetSymbolAddress((void**)&p_t_qkv, g_t_qkv);
        cudaGetSymbolAddress((void**)&p_t_ao, g_t_ao);
        cudaGetSymbolAddress((void**)&p_t_ff1, g_t_ff1);
        cudaGetSymbolAddress((void**)&p_t_ff2, g_t_ff2);
        cudaFuncSetAttribute(fps_kernel, cudaFuncAttributeMaxDynamicSharedMemorySize, FPS_SMEM);
        cudaFuncSetAttribute(attn_kernel, cudaFuncAttributeMaxDynamicSharedMemorySize, ATTN_SMEM);
        inited = true;
    }

    // 0. transpose + tf32-round all weights (single launch)
    wtrans_all_kernel<<<DEPTH * 2048, 256>>>(qkv_w, attn_out_w, ff1_w, ff2_w,
                                             p_t_qkv, p_t_ao, p_t_ff1, p_t_ff2);

    // 1. FPS anchors
    fps_kernel<<<BD * NF, 512, FPS_SMEM>>>(points, p_axyz);
    // 2. grouping + conv + max + positional embed -> x
    group_kernel<<<dim3(MM, NF, BD), 256>>>(points, conv_d_w, conv_f_w, pos_w, pos_b, p_axyz, p_x);

    // 3. transformer (tensor-core tf32 GEMMs + tensor-core attention)
    const int MT = (ROWS + 127) / 128;  // 49
    for (int l = 0; l < DEPTH; l++) {
        ln_stats_kernel<<<ROWS / 8, 256>>>(p_x, p_stats);
        mma_gemm<true, false, false, false><<<dim3((3 * INNER) / 128, MT), 256>>>(
            p_x, p_t_qkv + (size_t)l * 3 * INNER * DIM, p_stats, ln1_g + l * DIM, ln1_b + l * DIM,
            nullptr, nullptr, p_qkv, ROWS, DIM, 3 * INNER);
        attn_kernel<<<dim3(13, HEADS, BD), 256, ATTN_SMEM>>>(p_qkv, p_att);
        mma_gemm<false, true, false, true><<<dim3(DIM / 128, MT), 256>>>(
            p_att, p_t_ao + (size_t)l * DIM * INNER, nullptr, nullptr, nullptr,
            attn_out_b + l * DIM, p_x, p_x, ROWS, INNER, DIM);
        ln_stats_kernel<<<ROWS / 8, 256>>>(p_x, p_stats);
        mma_gemm<true, true, true, false><<<dim3(MLP / 128, MT), 256>>>(
            p_x, p_t_ff1 + (size_t)l * MLP * DIM, p_stats, ln2_g + l * DIM, ln2_b + l * DIM,
            ff1_b + l * MLP, nullptr, p_ff1, ROWS, DIM, MLP);
        mma_gemm<false, true, false, true><<<dim3(DIM / 128, MT), 256>>>(
            p_ff1, p_t_ff2 + (size_t)l * DIM * MLP, nullptr, nullptr, nullptr,
            ff2_b + l * DIM, p_x, p_x, ROWS, MLP, DIM);
    }

    // 4. head (tiny GEMMs stay on SIMT path)
    maxpool1_kernel<<<dim3(13, BD), DIM>>>(p_x, p_pmax);
    maxpool2_kernel<<<BD, DIM>>>(p_pmax, p_pool);
    ln_kernel<<<BD, 128>>>(p_pool, head_ln_g, head_ln_b, p_pooln);
    gemm128<true, true, false><<<dim3(MLP / 64, 1), 256>>>(p_pooln, head1_w, head1_b, nullptr, p_h1, BD, DIM, MLP);
    gemm128<true, false, false><<<dim3(OUTD / 64, 1), 256>>>(p_h1, head2_w, head2_b, nullptr, p_h2, BD, MLP, OUTD);
    head_kernel<<<BD * 17, 64>>>(p_h2, out);
}

// round 11
// speedup vs baseline: 3.5030x; 1.0634x over previous
#include <cuda_runtime.h>
#include <cuda_bf16.h>
#include <math.h>
#include <stdint.h>

// ---------------- problem constants ----------------
#define BD 8
#define LD 5
#define NP 4096
#define NANCH 64
#define NTOT 4160          // NP + NANCH
#define MM 260             // NTOT / 16
#define NF 3
#define SEQ 780            // NF*MM
#define ROWS 6240          // BD*SEQ
#define DIM 512
#define HEADS 8
#define DH 64
#define INNER 512
#define MLP 1024
#define OUTD 1088
#define KNN 32
#define DEPTH 5

// ---------------- scratch (device globals; no allocation allowed) ----------------
__device__ float g_axyz[BD * NF * MM * 3];
__device__ float g_x[ROWS * DIM];
__device__ float g_qkv[ROWS * 3 * INNER];
__device__ float g_att[ROWS * INNER];
__device__ float g_ff1[ROWS * MLP];
__device__ float2 g_stats[ROWS];
__device__ float g_pmax[BD * 13 * DIM];
__device__ float g_pool[BD * DIM];
__device__ float g_pooln[BD * DIM];
__device__ float g_h1[BD * MLP];
__device__ float g_h2[BD * OUTD];
// transposed (and tf32-rounded) weights, layout [n][k]
__device__ float g_t_qkv[DEPTH * 3 * INNER * DIM];
__device__ float g_t_ao [DEPTH * DIM * INNER];
__device__ float g_t_ff1[DEPTH * MLP * DIM];
__device__ float g_t_ff2[DEPTH * DIM * MLP];

// ---------------- helpers ----------------
__device__ __forceinline__ float to_tf32(float x) {
    uint32_t u; asm("cvt.rna.tf32.f32 %0, %1;" : "=r"(u) : "f"(x));
    return __uint_as_float(u);
}

__device__ __forceinline__ void get_pt(const float* __restrict__ pts, int b, int layer, int j,
                                       float& x, float& y, float& z) {
    if (j < NP) {
        const float* p = pts + ((size_t)((b * LD + layer) * NP + j)) * 3;
        x = p[0]; y = p[1]; z = p[2];
    } else {
        int i = j - NP;
        x = -1.5f + (float)(i >> 4);
        y = -1.5f + (float)((i >> 2) & 3);
        z = -1.5f + (float)(i & 3);
    }
}

__device__ __forceinline__ float gelu_f(float x) {
    return 0.5f * x * (1.0f + erff(x * 0.7071067811865476f));
}

__device__ __forceinline__ void mma_tf32(float* d, const uint32_t* a, const uint32_t* b) {
    asm volatile(
        "mma.sync.aligned.m16n8k8.row.col.f32.tf32.tf32.f32 "
        "{%0,%1,%2,%3}, {%4,%5,%6,%7}, {%8,%9}, {%0,%1,%2,%3};"
        : "+f"(d[0]), "+f"(d[1]), "+f"(d[2]), "+f"(d[3])
        : "r"(a[0]), "r"(a[1]), "r"(a[2]), "r"(a[3]), "r"(b[0]), "r"(b[1]));
}

// ---------------- FPS: one block per (b, frame) ----------------
__global__ void fps_kernel(const float* __restrict__ points, float* __restrict__ axyz) {
    const int bf = blockIdx.x;
    const int b = bf / NF, f = bf % NF;
    const int layer = 2 * f;
    extern __shared__ float sm[];
    float* sx = sm;
    float* sy = sm + NTOT;
    float* sz = sm + 2 * NTOT;
    float* dist = sm + 3 * NTOT;
    __shared__ float rv[16];
    __shared__ int ri[16];
    __shared__ int s_last;
    int tid = threadIdx.x;

    for (int j = tid; j < NTOT; j += 512) {
        float x, y, z;
        get_pt(points, b, layer, j, x, y, z);
        sx[j] = x; sy[j] = y; sz[j] = z;
        dist[j] = 1e10f;
    }
    __syncthreads();

    int last = 0;
    float* aout = axyz + (size_t)bf * MM * 3;
    for (int s = 0; s < MM; s++) {
        float lx = sx[last], ly = sy[last], lz = sz[last];
        if (tid == 0) { aout[s * 3 + 0] = lx; aout[s * 3 + 1] = ly; aout[s * 3 + 2] = lz; }
        float bv = -1.0f; int bi = 0x7fffffff;
        for (int j = tid; j < NTOT; j += 512) {
            float dx = sx[j] - lx, dy = sy[j] - ly, dz = sz[j] - lz;
            float d = __fadd_rn(__fadd_rn(__fmul_rn(dx, dx), __fmul_rn(dy, dy)), __fmul_rn(dz, dz));
            float nd = fminf(dist[j], d);
            dist[j] = nd;
            if (nd > bv) { bv = nd; bi = j; }
        }
        for (int off = 16; off; off >>= 1) {
            float ov = __shfl_down_sync(0xffffffffu, bv, off);
            int oi = __shfl_down_sync(0xffffffffu, bi, off);
            if (ov > bv || (ov == bv && oi < bi)) { bv = ov; bi = oi; }
        }
        if ((tid & 31) == 0) { rv[tid >> 5] = bv; ri[tid >> 5] = bi; }
        __syncthreads();
        if (tid < 32) {
            float v2 = (tid < 16) ? rv[tid] : -2.0f;
            int i2 = (tid < 16) ? ri[tid] : 0x7fffffff;
            for (int off = 8; off; off >>= 1) {
                float ov = __shfl_down_sync(0xffffffffu, v2, off);
                int oi = __shfl_down_sync(0xffffffffu, i2, off);
                if (ov > v2 || (ov == v2 && oi < i2)) { v2 = ov; i2 = oi; }
            }
            if (tid == 0) s_last = i2;
        }
        __syncthreads();
        last = s_last;
    }
}

// ---------------- ball query + conv + maxpool + pos embed ----------------
__global__ void group_kernel(const float* __restrict__ points,
                             const float* __restrict__ conv_d_w,
                             const float* __restrict__ conv_f_w,
                             const float* __restrict__ pos_w,
                             const float* __restrict__ pos_b,
                             const float* __restrict__ axyz,
                             float* __restrict__ xout) {
    const int m = blockIdx.x, f = blockIdx.y, b = blockIdx.z;
    __shared__ float gpts[3][KNN][3];
    __shared__ int scnt[3];
    __shared__ float sa[3];
    const int tid = threadIdx.x;

    if (tid < 3) sa[tid] = axyz[((size_t)((b * NF + f) * MM + m)) * 3 + tid];
    __syncthreads();
    const float ax = sa[0], ay = sa[1], az = sa[2];

    const int w = tid >> 5, lane = tid & 31;
    if (w < 3) {
        int layer = 2 * f - 1 + w;
        layer = layer < 0 ? 0 : (layer > 4 ? 4 : layer);
        const float R2 = (float)(0.7 * 0.7);
        int cnt = 0;
        for (int j0 = 0; j0 < NTOT && cnt < KNN; j0 += 32) {
            int j = j0 + lane;
            float px, py, pz;
            get_pt(points, b, layer, j, px, py, pz);
            float dx = px - ax, dy = py - ay, dz = pz - az;
            float d2 = __fadd_rn(__fadd_rn(__fmul_rn(dx, dx), __fmul_rn(dy, dy)), __fmul_rn(dz, dz));
            unsigned mask = __ballot_sync(0xffffffffu, d2 < R2);
            while (mask && cnt < KNN) {
                int src = __ffs(mask) - 1;
                mask &= mask - 1;
                float gx = __shfl_sync(0xffffffffu, px, src);
                float gy = __shfl_sync(0xffffffffu, py, src);
                float gz = __shfl_sync(0xffffffffu, pz, src);
                if (lane == 0) { gpts[w][cnt][0] = gx; gpts[w][cnt][1] = gy; gpts[w][cnt][2] = gz; }
                cnt++;
            }
        }
        if (cnt == 0) {
            if (lane == 0) {
                float gx, gy, gz;
                get_pt(points, b, layer, 0, gx, gy, gz);
                gpts[w][0][0] = gx; gpts[w][0][1] = gy; gpts[w][0][2] = gz;
            }
            cnt = 1;
        }
        if (lane == 0) scnt[w] = cnt;
    }
    __syncthreads();

    const int cs[3] = {scnt[0], scnt[1], scnt[2]};
#pragma unroll
    for (int dd = 0; dd < 2; dd++) {
        int d = tid + dd * 256;
        float wf0 = conv_f_w[d * 3 + 0], wf1 = conv_f_w[d * 3 + 1], wf2 = conv_f_w[d * 3 + 2];
        float wd0 = conv_d_w[d * 4 + 0], wd1 = conv_d_w[d * 4 + 1], wd2 = conv_d_w[d * 4 + 2], wd3 = conv_d_w[d * 4 + 3];
        float ws0 = wf0 + wd0, ws1 = wf1 + wd1, ws2 = wf2 + wd2;
        float adot = ax * wd0 + ay * wd1 + az * wd2;
        float maxv = -1e30f;
        for (int ww = 0; ww < 3; ww++) {
            float dt = (float)(ww - 1);
            float base = dt * wd3 - adot;
            int cn = cs[ww];
            for (int k = 0; k < cn; k++) {
                float gx = gpts[ww][k][0], gy = gpts[ww][k][1], gz = gpts[ww][k][2];
                float v = fmaf(gx, ws0, fmaf(gy, ws1, fmaf(gz, ws2, base)));
                maxv = fmaxf(maxv, v);
            }
        }
        float pw0 = pos_w[d * 4 + 0], pw1 = pos_w[d * 4 + 1], pw2 = pos_w[d * 4 + 2], pw3 = pos_w[d * 4 + 3];
        float t = (float)(f + 1);
        float outv = maxv + ax * pw0 + ay * pw1 + az * pw2 + t * pw3 + pos_b[d];
        xout[((size_t)(b * SEQ + f * MM + m)) * DIM + d] = outv;
    }
}

// ---------------- per-row LN stats: one warp per row ----------------
__global__ __launch_bounds__(256)
void ln_stats_kernel(const float* __restrict__ x, float2* __restrict__ stats) {
    const int row = blockIdx.x * 8 + (threadIdx.x >> 5);
    const int lane = threadIdx.x & 31;
    const float* xr = x + (size_t)row * DIM;
    float4 v[4];
#pragma unroll
    for (int i = 0; i < 4; i++) v[i] = *reinterpret_cast<const float4*>(xr + i * 128 + lane * 4);
    float s = 0.f;
#pragma unroll
    for (int i = 0; i < 4; i++) s += v[i].x + v[i].y + v[i].z + v[i].w;
    for (int off = 16; off; off >>= 1) s += __shfl_xor_sync(0xffffffffu, s, off);
    float mu = s * (1.0f / DIM);
    float q = 0.f;
#pragma unroll
    for (int i = 0; i < 4; i++) {
        float a = v[i].x - mu, b = v[i].y - mu, c = v[i].z - mu, d = v[i].w - mu;
        q += a * a + b * b + c * c + d * d;
    }
    for (int off = 16; off; off >>= 1) q += __shfl_xor_sync(0xffffffffu, q, off);
    if (lane == 0) {
        float2 st; st.x = mu; st.y = rsqrtf(q * (1.0f / DIM) + 1e-5f);
        stats[row] = st;
    }
}

// ---------------- LayerNorm (head path, rows x 512) ----------------
__global__ void ln_kernel(const float* __restrict__ x, const float* __restrict__ gg,
                          const float* __restrict__ bb, float* __restrict__ y) {
    const int r = blockIdx.x;
    const float* xr = x + (size_t)r * DIM;
    float* yr = y + (size_t)r * DIM;
    const int tid = threadIdx.x;
    float v[4];
    float s = 0.f;
#pragma unroll
    for (int i = 0; i < 4; i++) { v[i] = xr[tid + i * 128]; s += v[i]; }
    __shared__ float red[4];
    __shared__ float s_stat;
    for (int off = 16; off; off >>= 1) s += __shfl_down_sync(0xffffffffu, s, off);
    if ((tid & 31) == 0) red[tid >> 5] = s;
    __syncthreads();
    if (tid == 0) s_stat = (red[0] + red[1] + red[2] + red[3]) * (1.0f / DIM);
    __syncthreads();
    float mu = s_stat;
    float q = 0.f;
#pragma unroll
    for (int i = 0; i < 4; i++) { float d = v[i] - mu; q += d * d; }
    __syncthreads();
    for (int off = 16; off; off >>= 1) q += __shfl_down_sync(0xffffffffu, q, off);
    if ((tid & 31) == 0) red[tid >> 5] = q;
    __syncthreads();
    if (tid == 0) s_stat = (red[0] + red[1] + red[2] + red[3]) * (1.0f / DIM);
    __syncthreads();
    float inv = rsqrtf(s_stat + 1e-5f);
#pragma unroll
    for (int i = 0; i < 4; i++) {
        int c = tid + i * 128;
        yr[c] = (v[i] - mu) * inv * gg[c] + bb[c];
    }
}

// ---------------- merged weight transpose (+tf32 round), all 20 matrices ----------------
__global__ __launch_bounds__(256)
void wtrans_all_kernel(const float* __restrict__ qkv_w, const float* __restrict__ ao_w,
                       const float* __restrict__ ff1_w, const float* __restrict__ ff2_w,
                       float* __restrict__ t_qkv, float* __restrict__ t_ao,
                       float* __restrict__ t_ff1, float* __restrict__ t_ff2) {
    __shared__ float t[32][33];
    const int tile = blockIdx.x;
    const int l = tile / 2048;
    int r = tile % 2048;
    const float* W; float* Wt; int K, N, bx, by;
    if (r < 768) {
        W = qkv_w + (size_t)l * DIM * 1536; Wt = t_qkv + (size_t)l * 1536 * DIM;
        K = DIM; N = 1536; bx = r % 48; by = r / 48;
    } else if (r < 1024) {
        r -= 768;
        W = ao_w + (size_t)l * INNER * DIM; Wt = t_ao + (size_t)l * DIM * INNER;
        K = INNER; N = DIM; bx = r % 16; by = r / 16;
    } else if (r < 1536) {
        r -= 1024;
        W = ff1_w + (size_t)l * DIM * MLP; Wt = t_ff1 + (size_t)l * MLP * DIM;
        K = DIM; N = MLP; bx = r % 32; by = r / 32;
    } else {
        r -= 1536;
        W = ff2_w + (size_t)l * MLP * DIM; Wt = t_ff2 + (size_t)l * DIM * MLP;
        K = MLP; N = DIM; bx = r % 16; by = r / 16;
    }
    const int n0 = bx * 32, k0 = by * 32;
    const int x = threadIdx.x & 31, y = threadIdx.x >> 5;  // 32 x 8
#pragma unroll
    for (int i = y; i < 32; i += 8)
        t[i][x] = W[(size_t)(k0 + i) * N + n0 + x];
    __syncthreads();
#pragma unroll
    for (int i = y; i < 32; i += 8)
        Wt[(size_t)(n0 + i) * K + k0 + x] = to_tf32(t[x][i]);
}

// ---------------- tensor-core tf32 GEMM via mma.sync, register-prefetch pipelined ----------------
template <bool WITH_LN, bool WITH_BIAS, bool WITH_GELU, bool WITH_RES>
__global__ __launch_bounds__(256)
void mma_gemm(const float* __restrict__ A, const float* __restrict__ Bt,
              const float2* __restrict__ stats, const float* __restrict__ lng,
              const float* __restrict__ lnb,
              const float* __restrict__ bias, const float* __restrict__ Rd,
              float* __restrict__ C, int Rr, int Kd, int Cn) {
    __shared__ float As[128][36];
    __shared__ float Bs[128][36];
    const int bm = blockIdx.y * 128, bn = blockIdx.x * 128;
    const int tid = threadIdx.x, wid = tid >> 5, lane = tid & 31;
    const int wm = wid & 3, wn = wid >> 2;
    const int gid = lane >> 2, tig = lane & 3;

    // per-thread staging indices (fixed across chunks)
    int rowi[4], kqi[4];
    bool aoki[4];
    float2 sti[4];
#pragma unroll
    for (int i = 0; i < 4; i++) {
        int lin = tid + i * 256;
        rowi[i] = lin >> 3;
        kqi[i] = (lin & 7) * 4;
        aoki[i] = (bm + rowi[i]) < Rr;
        if (WITH_LN) sti[i] = aoki[i] ? stats[bm + rowi[i]] : make_float2(0.f, 1.f);
    }

    float acc[2][8][4];
#pragma unroll
    for (int mt = 0; mt < 2; mt++)
#pragma unroll
        for (int nt = 0; nt < 8; nt++)
#pragma unroll
            for (int i = 0; i < 4; i++) acc[mt][nt][i] = 0.f;

    const int nk = Kd >> 5;
    float4 pa[4], pb[4];

    // prefetch chunk 0
#pragma unroll
    for (int i = 0; i < 4; i++) {
        pa[i] = make_float4(0.f, 0.f, 0.f, 0.f);
        if (aoki[i]) pa[i] = *reinterpret_cast<const float4*>(A + (size_t)(bm + rowi[i]) * Kd + kqi[i]);
        pb[i] = *reinterpret_cast<const float4*>(Bt + (size_t)(bn + rowi[i]) * Kd + kqi[i]);
    }
    // store chunk 0
#pragma unroll
    for (int i = 0; i < 4; i++) {
        float4 v = pa[i];
        if (WITH_LN) {
            float4 gv = *reinterpret_cast<const float4*>(lng + kqi[i]);
            float4 bv = *reinterpret_cast<const float4*>(lnb + kqi[i]);
            v.x = (v.x - sti[i].x) * sti[i].y * gv.x + bv.x;
            v.y = (v.y - sti[i].x) * sti[i].y * gv.y + bv.y;
            v.z = (v.z - sti[i].x) * sti[i].y * gv.z + bv.z;
            v.w = (v.w - sti[i].x) * sti[i].y * gv.w + bv.w;
        }
        int row = rowi[i], kq = kqi[i];
        As[row][kq] = to_tf32(v.x); As[row][kq + 1] = to_tf32(v.y);
        As[row][kq + 2] = to_tf32(v.z); As[row][kq + 3] = to_tf32(v.w);
        Bs[row][kq] = pb[i].x; Bs[row][kq + 1] = pb[i].y;
        Bs[row][kq + 2] = pb[i].z; Bs[row][kq + 3] = pb[i].w;
    }
    __syncthreads();

    for (int c = 0; c < nk; c++) {
        const int k0n = (c + 1) * 32;
        if (c + 1 < nk) {
#pragma unroll
            for (int i = 0; i < 4; i++) {
                pa[i] = make_float4(0.f, 0.f, 0.f, 0.f);
                if (aoki[i]) pa[i] = *reinterpret_cast<const float4*>(A + (size_t)(bm + rowi[i]) * Kd + k0n + kqi[i]);
                pb[i] = *reinterpret_cast<const float4*>(Bt + (size_t)(bn + rowi[i]) * Kd + k0n + kqi[i]);
            }
        }
        // compute current chunk
#pragma unroll
        for (int ks = 0; ks < 4; ks++) {
            const int kb = ks * 8;
            uint32_t af[2][4];
#pragma unroll
            for (int mt = 0; mt < 2; mt++) {
                int row = wm * 32 + mt * 16 + gid;
                af[mt][0] = __float_as_uint(As[row][kb + tig]);
                af[mt][1] = __float_as_uint(As[row + 8][kb + tig]);
                af[mt][2] = __float_as_uint(As[row][kb + tig + 4]);
                af[mt][3] = __float_as_uint(As[row + 8][kb + tig + 4]);
            }
            uint32_t bf[8][2];
#pragma unroll
            for (int nt = 0; nt < 8; nt++) {
                int col = wn * 64 + nt * 8 + gid;
                bf[nt][0] = __float_as_uint(Bs[col][kb + tig]);
                bf[nt][1] = __float_as_uint(Bs[col][kb + tig + 4]);
            }
#pragma unroll
            for (int mt = 0; mt < 2; mt++)
#pragma unroll
                for (int nt = 0; nt < 8; nt++)
                    mma_tf32(acc[mt][nt], af[mt], bf[nt]);
        }
        __syncthreads();
        if (c + 1 < nk) {
#pragma unroll
            for (int i = 0; i < 4; i++) {
                float4 v = pa[i];
                if (WITH_LN) {
                    float4 gv = *reinterpret_cast<const float4*>(lng + k0n + kqi[i]);
                    float4 bv = *reinterpret_cast<const float4*>(lnb + k0n + kqi[i]);
                    v.x = (v.x - sti[i].x) * sti[i].y * gv.x + bv.x;
                    v.y = (v.y - sti[i].x) * sti[i].y * gv.y + bv.y;
                    v.z = (v.z - sti[i].x) * sti[i].y * gv.z + bv.z;
                    v.w = (v.w - sti[i].x) * sti[i].y * gv.w + bv.w;
                }
                int row = rowi[i], kq = kqi[i];
                As[row][kq] = to_tf32(v.x); As[row][kq + 1] = to_tf32(v.y);
                As[row][kq + 2] = to_tf32(v.z); As[row][kq + 3] = to_tf32(v.w);
                Bs[row][kq] = pb[i].x; Bs[row][kq + 1] = pb[i].y;
                Bs[row][kq + 2] = pb[i].z; Bs[row][kq + 3] = pb[i].w;
            }
            __syncthreads();
        }
    }

#pragma unroll
    for (int mt = 0; mt < 2; mt++) {
#pragma unroll
        for (int half = 0; half < 2; half++) {
            int row = bm + wm * 32 + mt * 16 + half * 8 + gid;
            if (row >= Rr) continue;
            float* crow = C + (size_t)row * Cn;
            const float* rrow = WITH_RES ? (Rd + (size_t)row * Cn) : nullptr;
#pragma unroll
            for (int nt = 0; nt < 8; nt++) {
                int col = bn + wn * 64 + nt * 8 + 2 * tig;
                float v0 = acc[mt][nt][half * 2 + 0];
                float v1 = acc[mt][nt][half * 2 + 1];
                if (WITH_BIAS) { v0 += bias[col]; v1 += bias[col + 1]; }
                if (WITH_GELU) { v0 = gelu_f(v0); v1 = gelu_f(v1); }
                if (WITH_RES)  { v0 += rrow[col]; v1 += rrow[col + 1]; }
                float2 o2; o2.x = v0; o2.y = v1;
                *reinterpret_cast<float2*>(crow + col) = o2;
            }
        }
    }
}

// ---------------- fp32 tiled GEMM (head GEMMs, tiny M) ----------------
template <bool WITH_BIAS, bool WITH_GELU, bool WITH_RES>
__global__ __launch_bounds__(256)
void gemm128(const float* __restrict__ A, const float* __restrict__ W,
             const float* __restrict__ bias, const float* __restrict__ Rd,
             float* __restrict__ C, int Rr, int Kd, int Cn) {
    __shared__ float As[8][132];
    __shared__ float Bs[8][64];
    const int bn = blockIdx.x * 64;
    const int bm = blockIdx.y * 128;
    const int tid = threadIdx.x;
    const int tx = tid & 15, ty = tid >> 4;
    float acc[8][4];
#pragma unroll
    for (int u = 0; u < 8; u++)
#pragma unroll
        for (int v = 0; v < 4; v++) acc[u][v] = 0.f;

    const int arow = bm + (tid >> 1);
    const int kh = (tid & 1) * 4;
    const bool aval = arow < Rr;
    const int am = tid >> 1;
    const int bk = tid >> 4;
    const int bn4 = (tid & 15) * 4;

    for (int k0 = 0; k0 < Kd; k0 += 8) {
        float4 av = make_float4(0.f, 0.f, 0.f, 0.f);
        if (aval) av = *reinterpret_cast<const float4*>(A + (size_t)arow * Kd + k0 + kh);
        As[kh + 0][am] = av.x; As[kh + 1][am] = av.y; As[kh + 2][am] = av.z; As[kh + 3][am] = av.w;
        if (tid < 128) {
            float4 bv = *reinterpret_cast<const float4*>(W + (size_t)(k0 + bk) * Cn + bn + bn4);
            *reinterpret_cast<float4*>(&Bs[bk][bn4]) = bv;
        }
        __syncthreads();
#pragma unroll
        for (int kk = 0; kk < 8; kk++) {
            float4 a0 = *reinterpret_cast<const float4*>(&As[kk][ty * 8]);
            float4 a1 = *reinterpret_cast<const float4*>(&As[kk][ty * 8 + 4]);
            float4 b4 = *reinterpret_cast<const float4*>(&Bs[kk][tx * 4]);
            float aa[8] = {a0.x, a0.y, a0.z, a0.w, a1.x, a1.y, a1.z, a1.w};
            float bb4[4] = {b4.x, b4.y, b4.z, b4.w};
#pragma unroll
            for (int u = 0; u < 8; u++)
#pragma unroll
                for (int v = 0; v < 4; v++) acc[u][v] = fmaf(aa[u], bb4[v], acc[u][v]);
        }
        __syncthreads();
    }
#pragma unroll
    for (int u = 0; u < 8; u++) {
        int row = bm + ty * 8 + u;
        if (row < Rr) {
#pragma unroll
            for (int v = 0; v < 4; v++) {
                int col = bn + tx * 4 + v;
                float c = acc[u][v];
                if (WITH_BIAS) c += bias[col];
                if (WITH_GELU) c = gelu_f(c);
                if (WITH_RES) c += Rd[(size_t)row * Cn + col];
                C[(size_t)row * Cn + col] = c;
            }
        }
    }
}

// ---------------- attention: flash, tensor-core QK^T and PV, K/V prefetch pipelined ----------------
#define ASTR 68
#define ATTN_SMEM ((6 * 64 * ASTR + 128) * 4)
__global__ __launch_bounds__(256)
void attn_kernel(const float* __restrict__ qkv, float* __restrict__ o) {
    extern __shared__ float sm[];
    float* Qhi = sm;
    float* Qlo = Qhi + 64 * ASTR;
    float* Ks  = Qlo + 64 * ASTR;
    float* Vs  = Ks  + 64 * ASTR;
    float* Ph  = Vs  + 64 * ASTR;
    float* Pl  = Ph  + 64 * ASTR;
    float* crow = Pl + 64 * ASTR;   // 64
    float* lrow = crow + 64;        // 64

    const int qt = blockIdx.x, h = blockIdx.y, b = blockIdx.z;
    const int tid = threadIdx.x, lane = tid & 31, wid = tid >> 5;
    const int wm = wid & 3, wn = wid >> 2;      // 4m x 2n warp grid over 64x64
    const int gid = lane >> 2, tig = lane & 3;

    // K/V staging indices: 4 x float4 per tile per array
    int kvr[4], kvd[4];
#pragma unroll
    for (int i = 0; i < 4; i++) {
        int lin = tid + i * 256;
        kvr[i] = lin >> 4;
        kvd[i] = (lin & 15) * 4;
    }
    float4 kpf[4], vpf[4];

    // load Q tile, split hi/lo
#pragma unroll
    for (int i = 0; i < 16; i++) {
        int lid = tid + i * 256;
        int r = lid >> 6, d = lid & 63;
        int s = qt * 64 + r;
        float q = (s < SEQ) ? qkv[((size_t)(b * SEQ + s)) * (3 * INNER) + h * DH + d] : 0.f;
        float qh = to_tf32(q);
        Qhi[r * ASTR + d] = qh;
        Qlo[r * ASTR + d] = to_tf32(q - qh);
    }
    // prefetch + store K/V tile 0
#pragma unroll
    for (int i = 0; i < 4; i++) {
        int s = kvr[i];  // kt=0
        size_t base = ((size_t)(b * SEQ + s)) * (3 * INNER) + h * DH + kvd[i];
        kpf[i] = *reinterpret_cast<const float4*>(qkv + base + INNER);
        vpf[i] = *reinterpret_cast<const float4*>(qkv + base + 2 * INNER);
    }
#pragma unroll
    for (int i = 0; i < 4; i++) {
        int off = kvr[i] * ASTR + kvd[i];
        Ks[off] = to_tf32(kpf[i].x); Ks[off + 1] = to_tf32(kpf[i].y);
        Ks[off + 2] = to_tf32(kpf[i].z); Ks[off + 3] = to_tf32(kpf[i].w);
        Vs[off] = to_tf32(vpf[i].x); Vs[off + 1] = to_tf32(vpf[i].y);
        Vs[off + 2] = to_tf32(vpf[i].z); Vs[off + 3] = to_tf32(vpf[i].w);
    }

    float oacc[4][4];
#pragma unroll
    for (int nt = 0; nt < 4; nt++)
#pragma unroll
        for (int i = 0; i < 4; i++) oacc[nt][i] = 0.f;
    float mcur = -1e30f, lcur = 0.f;
    const int srow = tid >> 2;
    const int scol = (tid & 3) * 16;
    __syncthreads();

    for (int kt = 0; kt < 13; kt++) {
        // S = Q @ K^T
        float sacc[4][4];
#pragma unroll
        for (int nt = 0; nt < 4; nt++)
#pragma unroll
            for (int i = 0; i < 4; i++) sacc[nt][i] = 0.f;
#pragma unroll
        for (int ks = 0; ks < 8; ks++) {
            const int kb = ks * 8;
            const int r0 = (wm * 16 + gid) * ASTR;
            uint32_t ah[4], al[4];
            ah[0] = __float_as_uint(Qhi[r0 + kb + tig]);
            ah[1] = __float_as_uint(Qhi[r0 + 8 * ASTR + kb + tig]);
            ah[2] = __float_as_uint(Qhi[r0 + kb + tig + 4]);
            ah[3] = __float_as_uint(Qhi[r0 + 8 * ASTR + kb + tig + 4]);
            al[0] = __float_as_uint(Qlo[r0 + kb + tig]);
            al[1] = __float_as_uint(Qlo[r0 + 8 * ASTR + kb + tig]);
            al[2] = __float_as_uint(Qlo[r0 + kb + tig + 4]);
            al[3] = __float_as_uint(Qlo[r0 + 8 * ASTR + kb + tig + 4]);
#pragma unroll
            for (int nt = 0; nt < 4; nt++) {
                const int nc = (wn * 32 + nt * 8 + gid) * ASTR;
                uint32_t bf[2];
                bf[0] = __float_as_uint(Ks[nc + kb + tig]);
                bf[1] = __float_as_uint(Ks[nc + kb + tig + 4]);
                mma_tf32(sacc[nt], ah, bf);
                mma_tf32(sacc[nt], al, bf);
            }
        }
        // write S (scaled, masked) to Ph
        {
            const int r0 = wm * 16 + gid;
#pragma unroll
            for (int nt = 0; nt < 4; nt++) {
                int c = wn * 32 + nt * 8 + 2 * tig;
                int kg = kt * 64 + c;
                float2 s01, s23;
                s01.x = (kg < SEQ)     ? sacc[nt][0] * 0.125f : -1e30f;
                s01.y = (kg + 1 < SEQ) ? sacc[nt][1] * 0.125f : -1e30f;
                s23.x = (kg < SEQ)     ? sacc[nt][2] * 0.125f : -1e30f;
                s23.y = (kg + 1 < SEQ) ? sacc[nt][3] * 0.125f : -1e30f;
                *reinterpret_cast<float2*>(&Ph[r0 * ASTR + c]) = s01;
                *reinterpret_cast<float2*>(&Ph[(r0 + 8) * ASTR + c]) = s23;
            }
        }
        __syncthreads();

        // softmax: 4 lanes per row, in-place Ph -> p_hi, Pl -> p_lo
        {
            float sv[16];
#pragma unroll
            for (int i = 0; i < 4; i++) {
                float4 v4 = *reinterpret_cast<const float4*>(&Ph[srow * ASTR + scol + i * 4]);
                sv[i * 4 + 0] = v4.x; sv[i * 4 + 1] = v4.y; sv[i * 4 + 2] = v4.z; sv[i * 4 + 3] = v4.w;
            }
            float rm = sv[0];
#pragma unroll
            for (int i = 1; i < 16; i++) rm = fmaxf(rm, sv[i]);
            rm = fmaxf(rm, __shfl_xor_sync(0xffffffffu, rm, 1));
            rm = fmaxf(rm, __shfl_xor_sync(0xffffffffu, rm, 2));
            float mnew = fmaxf(mcur, rm);
            float corr = __expf(mcur - mnew);
            float ssum = 0.f;
#pragma unroll
            for (int i = 0; i < 4; i++) {
                float4 hv, lv;
                float p0 = __expf(sv[i * 4 + 0] - mnew);
                float p1 = __expf(sv[i * 4 + 1] - mnew);
                float p2 = __expf(sv[i * 4 + 2] - mnew);
                float p3 = __expf(sv[i * 4 + 3] - mnew);
                ssum += (p0 + p1) + (p2 + p3);
                hv.x = to_tf32(p0); hv.y = to_tf32(p1); hv.z = to_tf32(p2); hv.w = to_tf32(p3);
                lv.x = to_tf32(p0 - hv.x); lv.y = to_tf32(p1 - hv.y);
                lv.z = to_tf32(p2 - hv.z); lv.w = to_tf32(p3 - hv.w);
                *reinterpret_cast<float4*>(&Ph[srow * ASTR + scol + i * 4]) = hv;
                *reinterpret_cast<float4*>(&Pl[srow * ASTR + scol + i * 4]) = lv;
            }
            ssum += __shfl_xor_sync(0xffffffffu, ssum, 1);
            ssum += __shfl_xor_sync(0xffffffffu, ssum, 2);
            lcur = lcur * corr + ssum;
            mcur = mnew;
            if ((tid & 3) == 0) crow[srow] = corr;
        }
        __syncthreads();

        // prefetch next K/V during PV compute
        if (kt + 1 < 13) {
#pragma unroll
            for (int i = 0; i < 4; i++) {
                int s = (kt + 1) * 64 + kvr[i];
                size_t base = ((size_t)(b * SEQ + (s < SEQ ? s : 0))) * (3 * INNER) + h * DH + kvd[i];
                if (s < SEQ) {
                    kpf[i] = *reinterpret_cast<const float4*>(qkv + base + INNER);
                    vpf[i] = *reinterpret_cast<const float4*>(qkv + base + 2 * INNER);
                } else {
                    kpf[i] = make_float4(0.f, 0.f, 0.f, 0.f);
                    vpf[i] = make_float4(0.f, 0.f, 0.f, 0.f);
                }
            }
        }

        // rescale O by corr, then O += P @ V
        {
            float c0 = crow[wm * 16 + gid];
            float c1 = crow[wm * 16 + gid + 8];
#pragma unroll
            for (int nt = 0; nt < 4; nt++) {
                oacc[nt][0] *= c0; oacc[nt][1] *= c0;
                oacc[nt][2] *= c1; oacc[nt][3] *= c1;
            }
        }
#pragma unroll
        for (int ks = 0; ks < 8; ks++) {
            const int kb = ks * 8;
            const int r0 = (wm * 16 + gid) * ASTR;
            uint32_t ah[4], al[4];
            ah[0] = __float_as_uint(Ph[r0 + kb + tig]);
            ah[1] = __float_as_uint(Ph[r0 + 8 * ASTR + kb + tig]);
            ah[2] = __float_as_uint(Ph[r0 + kb + tig + 4]);
            ah[3] = __float_as_uint(Ph[r0 + 8 * ASTR + kb + tig + 4]);
            al[0] = __float_as_uint(Pl[r0 + kb + tig]);
            al[1] = __float_as_uint(Pl[r0 + 8 * ASTR + kb + tig]);
            al[2] = __float_as_uint(Pl[r0 + kb + tig + 4]);
            al[3] = __float_as_uint(Pl[r0 + 8 * ASTR + kb + tig + 4]);
#pragma unroll
            for (int nt = 0; nt < 4; nt++) {
                const int nc = wn * 32 + nt * 8 + gid;
                uint32_t bf[2];
                bf[0] = __float_as_uint(Vs[(kb + tig) * ASTR + nc]);
                bf[1] = __float_as_uint(Vs[(kb + tig + 4) * ASTR + nc]);
                mma_tf32(oacc[nt], ah, bf);
                mma_tf32(oacc[nt], al, bf);
            }
        }
        __syncthreads();
        if (kt + 1 < 13) {
#pragma unroll
            for (int i = 0; i < 4; i++) {
                int off = kvr[i] * ASTR + kvd[i];
                Ks[off] = to_tf32(kpf[i].x); Ks[off + 1] = to_tf32(kpf[i].y);
                Ks[off + 2] = to_tf32(kpf[i].z); Ks[off + 3] = to_tf32(kpf[i].w);
                Vs[off] = to_tf32(vpf[i].x); Vs[off + 1] = to_tf32(vpf[i].y);
                Vs[off + 2] = to_tf32(vpf[i].z); Vs[off + 3] = to_tf32(vpf[i].w);
            }
            __syncthreads();
        }
    }

    if ((tid & 3) == 0) lrow[srow] = lcur;
    __syncthreads();

    // store O
    {
        const int r0 = wm * 16 + gid;
        const int s0 = qt * 64 + r0, s1 = s0 + 8;
        float inv0 = 1.0f / lrow[r0];
        float inv1 = 1.0f / lrow[r0 + 8];
#pragma unroll
        for (int nt = 0; nt < 4; nt++) {
            int d = wn * 32 + nt * 8 + 2 * tig;
            if (s0 < SEQ) {
                float2 o2; o2.x = oacc[nt][0] * inv0; o2.y = oacc[nt][1] * inv0;
                *reinterpret_cast<float2*>(o + ((size_t)(b * SEQ + s0)) * INNER + h * DH + d) = o2;
            }
            if (s1 < SEQ) {
                float2 o2; o2.x = oacc[nt][2] * inv1; o2.y = oacc[nt][3] * inv1;
                *reinterpret_cast<float2*>(o + ((size_t)(b * SEQ + s1)) * INNER + h * DH + d) = o2;
            }
        }
    }
}

// ---------------- max over sequence: two stage ----------------
__global__ void maxpool1_kernel(const float* __restrict__ x, float* __restrict__ part) {
    const int c = blockIdx.x, b = blockIdx.y;
    const int d = threadIdx.x;  // 512
    const int s0 = c * 60;
    float m0 = -1e30f, m1 = -1e30f, m2 = -1e30f, m3 = -1e30f;
    for (int s = s0; s < s0 + 60; s += 4) {
        m0 = fmaxf(m0, x[((size_t)(b * SEQ + s + 0)) * DIM + d]);
        m1 = fmaxf(m1, x[((size_t)(b * SEQ + s + 1)) * DIM + d]);
        m2 = fmaxf(m2, x[((size_t)(b * SEQ + s + 2)) * DIM + d]);
        m3 = fmaxf(m3, x[((size_t)(b * SEQ + s + 3)) * DIM + d]);
    }
    part[((size_t)(b * 13 + c)) * DIM + d] = fmaxf(fmaxf(m0, m1), fmaxf(m2, m3));
}

__global__ void maxpool2_kernel(const float* __restrict__ part, float* __restrict__ o) {
    const int b = blockIdx.x, d = threadIdx.x;
    float m = -1e30f;
#pragma unroll
    for (int c = 0; c < 13; c++) m = fmaxf(m, part[((size_t)(b * 13 + c)) * DIM + d]);
    o[b * DIM + d] = m;
}

// ---------------- head softmax @ anchors ----------------
__global__ void head_kernel(const float* __restrict__ h2, float* __restrict__ out) {
    const int bg = blockIdx.x;
    const int b = bg / 17, g = bg % 17;
    const int tid = threadIdx.x;  // 64
    float v = h2[b * OUTD + g * 64 + tid];
    __shared__ float wred[2];
    __shared__ float wts[64];
    float m = v;
    for (int off = 16; off; off >>= 1) m = fmaxf(m, __shfl_xor_sync(0xffffffffu, m, off));
    if ((tid & 31) == 0) wred[tid >> 5] = m;
    __syncthreads();
    m = fmaxf(wred[0], wred[1]);
    float e = expf(v - m);
    float s = e;
    for (int off = 16; off; off >>= 1) s += __shfl_xor_sync(0xffffffffu, s, off);
    __syncthreads();
    if ((tid & 31) == 0) wred[tid >> 5] = s;
    __syncthreads();
    float tot = wred[0] + wred[1];
    wts[tid] = e / tot;
    __syncthreads();
    if (tid < 3) {
        float acc = 0.f;
        for (int j = 0; j < 64; j++) {
            float ac = (tid == 0) ? (-1.5f + (float)(j >> 4))
                     : (tid == 1) ? (-1.5f + (float)((j >> 2) & 3))
                                  : (-1.5f + (float)(j & 3));
            acc += wts[j] * ac;
        }
        out[(size_t)(b * 17 + g) * 3 + tid] = acc;
    }
}

// ---------------- launch ----------------
#define FPS_SMEM (NTOT * 4 * 4)

extern "C" void kernel_launch(void* const* d_in, const int* in_sizes, int n_in,
                              void* d_out, int out_size) {
    const float* points     = (const float*)d_in[0];
    const float* conv_d_w   = (const float*)d_in[1];
    const float* conv_f_w   = (const float*)d_in[2];
    const float* pos_w      = (const float*)d_in[3];
    const float* pos_b      = (const float*)d_in[4];
    const float* ln1_g      = (const float*)d_in[5];
    const float* ln1_b      = (const float*)d_in[6];
    const float* qkv_w      = (const float*)d_in[7];
    const float* attn_out_w = (const float*)d_in[8];
    const float* attn_out_b = (const float*)d_in[9];
    const float* ln2_g      = (const float*)d_in[10];
    const float* ln2_b      = (const float*)d_in[11];
    const float* ff1_w      = (const float*)d_in[12];
    const float* ff1_b      = (const float*)d_in[13];
    const float* ff2_w      = (const float*)d_in[14];
    const float* ff2_b      = (const float*)d_in[15];
    const float* head_ln_g  = (const float*)d_in[16];
    const float* head_ln_b  = (const float*)d_in[17];
    const float* head1_w    = (const float*)d_in[18];
    const float* head1_b    = (const float*)d_in[19];
    const float* head2_w    = (const float*)d_in[20];
    const float* head2_b    = (const float*)d_in[21];
    float* out = (float*)d_out;

    static bool inited = false;
    static float *p_axyz, *p_x, *p_qkv, *p_att, *p_ff1, *p_pmax, *p_pool, *p_pooln, *p_h1, *p_h2;
    static float2* p_stats;
    static float *p_t_qkv, *p_t_ao, *p_t_ff1, *p_t_ff2;
    if (!inited) {
        cudaGetSymbolAddress((void**)&p_axyz, g_axyz);
        cudaGetSymbolAddress((void**)&p_x, g_x);
        cudaGetSymbolAddress((void**)&p_qkv, g_qkv);
        cudaGetSymbolAddress((void**)&p_att, g_att);
        cudaGetSymbolAddress((void**)&p_ff1, g_ff1);
        cudaGetSymbolAddress((void**)&p_stats, g_stats);
        cudaGetSymbolAddress((void**)&p_pmax, g_pmax);
        cudaGetSymbolAddress((void**)&p_pool, g_pool);
        cudaGetSymbolAddress((void**)&p_pooln, g_pooln);
        cudaGetSymbolAddress((void**)&p_h1, g_h1);
        cudaGetSymbolAddress((void**)&p_h2, g_h2);
        cudaGetSymbolAddress((void**)&p_t_qkv, g_t_qkv);
        cudaGetSymbolAddress((void**)&p_t_ao, g_t_ao);
        cudaGetSymbolAddress((void**)&p_t_ff1, g_t_ff1);
        cudaGetSymbolAddress((void**)&p_t_ff2, g_t_ff2);
        cudaFuncSetAttribute(fps_kernel, cudaFuncAttributeMaxDynamicSharedMemorySize, FPS_SMEM);
        cudaFuncSetAttribute(attn_kernel, cudaFuncAttributeMaxDynamicSharedMemorySize, ATTN_SMEM);
        inited = true;
    }

    // 0. transpose + tf32-round all weights (single launch)
    wtrans_all_kernel<<<DEPTH * 2048, 256>>>(qkv_w, attn_out_w, ff1_w, ff2_w,
                                             p_t_qkv, p_t_ao, p_t_ff1, p_t_ff2);

    // 1. FPS anchors
    fps_kernel<<<BD * NF, 512, FPS_SMEM>>>(points, p_axyz);
    // 2. grouping + conv + max + positional embed -> x
    group_kernel<<<dim3(MM, NF, BD), 256>>>(points, conv_d_w, conv_f_w, pos_w, pos_b, p_axyz, p_x);

    // 3. transformer (tensor-core tf32 GEMMs + tensor-core attention, pipelined loads)
    const int MT = (ROWS + 127) / 128;  // 49
    for (int l = 0; l < DEPTH; l++) {
        ln_stats_kernel<<<ROWS / 8, 256>>>(p_x, p_stats);
        mma_gemm<true, false, false, false><<<dim3((3 * INNER) / 128, MT), 256>>>(
            p_x, p_t_qkv + (size_t)l * 3 * INNER * DIM, p_stats, ln1_g + l * DIM, ln1_b + l * DIM,
            nullptr, nullptr, p_qkv, ROWS, DIM, 3 * INNER);
        attn_kernel<<<dim3(13, HEADS, BD), 256, ATTN_SMEM>>>(p_qkv, p_att);
        mma_gemm<false, true, false, true><<<dim3(DIM / 128, MT), 256>>>(
            p_att, p_t_ao + (size_t)l * DIM * INNER, nullptr, nullptr, nullptr,
            attn_out_b + l * DIM, p_x, p_x, ROWS, INNER, DIM);
        ln_stats_kernel<<<ROWS / 8, 256>>>(p_x, p_stats);
        mma_gemm<true, true, true, false><<<dim3(MLP / 128, MT), 256>>>(
            p_x, p_t_ff1 + (size_t)l * MLP * DIM, p_stats, ln2_g + l * DIM, ln2_b + l * DIM,
            ff1_b + l * MLP, nullptr, p_ff1, ROWS, DIM, MLP);
        mma_gemm<false, true, false, true><<<dim3(DIM / 128, MT), 256>>>(
            p_ff1, p_t_ff2 + (size_t)l * DIM * MLP, nullptr, nullptr, nullptr,
            ff2_b + l * DIM, p_x, p_x, ROWS, MLP, DIM);
    }

    // 4. head (tiny GEMMs stay on SIMT path)
    maxpool1_kernel<<<dim3(13, BD), DIM>>>(p_x, p_pmax);
    maxpool2_kernel<<<BD, DIM>>>(p_pmax, p_pool);
    ln_kernel<<<BD, 128>>>(p_pool, head_ln_g, head_ln_b, p_pooln);
    gemm128<true, true, false><<<dim3(MLP / 64, 1), 256>>>(p_pooln, head1_w, head1_b, nullptr, p_h1, BD, DIM, MLP);
    gemm128<true, false, false><<<dim3(OUTD / 64, 1), 256>>>(p_h1, head2_w, head2_b, nullptr, p_h2, BD, MLP, OUTD);
    head_kernel<<<BD * 17, 64>>>(p_h2, out);
}

// round 12
// speedup vs baseline: 3.9614x; 1.1309x over previous
#include <cuda_runtime.h>
#include <cuda_bf16.h>
#include <math.h>
#include <stdint.h>

// ---------------- problem constants ----------------
#define BD 8
#define LD 5
#define NP 4096
#define NANCH 64
#define NTOT 4160          // NP + NANCH
#define MM 260             // NTOT / 16
#define NF 3
#define SEQ 780            // NF*MM
#define ROWS 6240          // BD*SEQ
#define DIM 512
#define HEADS 8
#define DH 64
#define INNER 512
#define MLP 1024
#define OUTD 1088
#define KNN 32
#define DEPTH 5

// ---------------- scratch (device globals; no allocation allowed) ----------------
__device__ float g_axyz[BD * NF * MM * 3];
__device__ float g_x[ROWS * DIM];
__device__ float g_qkv[ROWS * 3 * INNER];
__device__ float g_att[ROWS * INNER];
__device__ float g_ff1[ROWS * MLP];
__device__ float2 g_stats[ROWS];
__device__ float g_pmax[BD * 13 * DIM];
__device__ float g_pool[BD * DIM];
__device__ float g_pooln[BD * DIM];
__device__ float g_h1[BD * MLP];
__device__ float g_h2[BD * OUTD];
// transposed (and tf32-rounded) weights, layout [n][k]
__device__ float g_t_qkv[DEPTH * 3 * INNER * DIM];
__device__ float g_t_ao [DEPTH * DIM * INNER];
__device__ float g_t_ff1[DEPTH * MLP * DIM];
__device__ float g_t_ff2[DEPTH * DIM * MLP];

// ---------------- helpers ----------------
__device__ __forceinline__ float to_tf32(float x) {
    uint32_t u; asm("cvt.rna.tf32.f32 %0, %1;" : "=r"(u) : "f"(x));
    return __uint_as_float(u);
}

__device__ __forceinline__ void cp_async16(uint32_t smem_addr, const void* gptr) {
    asm volatile("cp.async.cg.shared.global [%0], [%1], 16;" :: "r"(smem_addr), "l"(gptr));
}
#define CP_COMMIT() asm volatile("cp.async.commit_group;" ::: "memory")
#define CP_WAIT0()  asm volatile("cp.async.wait_group 0;" ::: "memory")

__device__ __forceinline__ void get_pt(const float* __restrict__ pts, int b, int layer, int j,
                                       float& x, float& y, float& z) {
    if (j < NP) {
        const float* p = pts + ((size_t)((b * LD + layer) * NP + j)) * 3;
        x = p[0]; y = p[1]; z = p[2];
    } else {
        int i = j - NP;
        x = -1.5f + (float)(i >> 4);
        y = -1.5f + (float)((i >> 2) & 3);
        z = -1.5f + (float)(i & 3);
    }
}

__device__ __forceinline__ float gelu_f(float x) {
    return 0.5f * x * (1.0f + erff(x * 0.7071067811865476f));
}

__device__ __forceinline__ void mma_tf32(float* d, const uint32_t* a, const uint32_t* b) {
    asm volatile(
        "mma.sync.aligned.m16n8k8.row.col.f32.tf32.tf32.f32 "
        "{%0,%1,%2,%3}, {%4,%5,%6,%7}, {%8,%9}, {%0,%1,%2,%3};"
        : "+f"(d[0]), "+f"(d[1]), "+f"(d[2]), "+f"(d[3])
        : "r"(a[0]), "r"(a[1]), "r"(a[2]), "r"(a[3]), "r"(b[0]), "r"(b[1]));
}

// ---------------- FPS: one block per (b, frame) ----------------
__global__ void fps_kernel(const float* __restrict__ points, float* __restrict__ axyz) {
    const int bf = blockIdx.x;
    const int b = bf / NF, f = bf % NF;
    const int layer = 2 * f;
    extern __shared__ float sm[];
    float* sx = sm;
    float* sy = sm + NTOT;
    float* sz = sm + 2 * NTOT;
    float* dist = sm + 3 * NTOT;
    __shared__ float rv[16];
    __shared__ int ri[16];
    __shared__ int s_last;
    int tid = threadIdx.x;

    for (int j = tid; j < NTOT; j += 512) {
        float x, y, z;
        get_pt(points, b, layer, j, x, y, z);
        sx[j] = x; sy[j] = y; sz[j] = z;
        dist[j] = 1e10f;
    }
    __syncthreads();

    int last = 0;
    float* aout = axyz + (size_t)bf * MM * 3;
    for (int s = 0; s < MM; s++) {
        float lx = sx[last], ly = sy[last], lz = sz[last];
        if (tid == 0) { aout[s * 3 + 0] = lx; aout[s * 3 + 1] = ly; aout[s * 3 + 2] = lz; }
        float bv = -1.0f; int bi = 0x7fffffff;
        for (int j = tid; j < NTOT; j += 512) {
            float dx = sx[j] - lx, dy = sy[j] - ly, dz = sz[j] - lz;
            float d = __fadd_rn(__fadd_rn(__fmul_rn(dx, dx), __fmul_rn(dy, dy)), __fmul_rn(dz, dz));
            float nd = fminf(dist[j], d);
            dist[j] = nd;
            if (nd > bv) { bv = nd; bi = j; }
        }
        for (int off = 16; off; off >>= 1) {
            float ov = __shfl_down_sync(0xffffffffu, bv, off);
            int oi = __shfl_down_sync(0xffffffffu, bi, off);
            if (ov > bv || (ov == bv && oi < bi)) { bv = ov; bi = oi; }
        }
        if ((tid & 31) == 0) { rv[tid >> 5] = bv; ri[tid >> 5] = bi; }
        __syncthreads();
        if (tid < 32) {
            float v2 = (tid < 16) ? rv[tid] : -2.0f;
            int i2 = (tid < 16) ? ri[tid] : 0x7fffffff;
            for (int off = 8; off; off >>= 1) {
                float ov = __shfl_down_sync(0xffffffffu, v2, off);
                int oi = __shfl_down_sync(0xffffffffu, i2, off);
                if (ov > v2 || (ov == v2 && oi < i2)) { v2 = ov; i2 = oi; }
            }
            if (tid == 0) s_last = i2;
        }
        __syncthreads();
        last = s_last;
    }
}

// ---------------- ball query + conv + maxpool + pos embed ----------------
__global__ void group_kernel(const float* __restrict__ points,
                             const float* __restrict__ conv_d_w,
                             const float* __restrict__ conv_f_w,
                             const float* __restrict__ pos_w,
                             const float* __restrict__ pos_b,
                             const float* __restrict__ axyz,
                             float* __restrict__ xout) {
    const int m = blockIdx.x, f = blockIdx.y, b = blockIdx.z;
    __shared__ float gpts[3][KNN][3];
    __shared__ int scnt[3];
    __shared__ float sa[3];
    const int tid = threadIdx.x;

    if (tid < 3) sa[tid] = axyz[((size_t)((b * NF + f) * MM + m)) * 3 + tid];
    __syncthreads();
    const float ax = sa[0], ay = sa[1], az = sa[2];

    const int w = tid >> 5, lane = tid & 31;
    if (w < 3) {
        int layer = 2 * f - 1 + w;
        layer = layer < 0 ? 0 : (layer > 4 ? 4 : layer);
        const float R2 = (float)(0.7 * 0.7);
        int cnt = 0;
        for (int j0 = 0; j0 < NTOT && cnt < KNN; j0 += 32) {
            int j = j0 + lane;
            float px, py, pz;
            get_pt(points, b, layer, j, px, py, pz);
            float dx = px - ax, dy = py - ay, dz = pz - az;
            float d2 = __fadd_rn(__fadd_rn(__fmul_rn(dx, dx), __fmul_rn(dy, dy)), __fmul_rn(dz, dz));
            unsigned mask = __ballot_sync(0xffffffffu, d2 < R2);
            while (mask && cnt < KNN) {
                int src = __ffs(mask) - 1;
                mask &= mask - 1;
                float gx = __shfl_sync(0xffffffffu, px, src);
                float gy = __shfl_sync(0xffffffffu, py, src);
                float gz = __shfl_sync(0xffffffffu, pz, src);
                if (lane == 0) { gpts[w][cnt][0] = gx; gpts[w][cnt][1] = gy; gpts[w][cnt][2] = gz; }
                cnt++;
            }
        }
        if (cnt == 0) {
            if (lane == 0) {
                float gx, gy, gz;
                get_pt(points, b, layer, 0, gx, gy, gz);
                gpts[w][0][0] = gx; gpts[w][0][1] = gy; gpts[w][0][2] = gz;
            }
            cnt = 1;
        }
        if (lane == 0) scnt[w] = cnt;
    }
    __syncthreads();

    const int cs[3] = {scnt[0], scnt[1], scnt[2]};
#pragma unroll
    for (int dd = 0; dd < 2; dd++) {
        int d = tid + dd * 256;
        float wf0 = conv_f_w[d * 3 + 0], wf1 = conv_f_w[d * 3 + 1], wf2 = conv_f_w[d * 3 + 2];
        float wd0 = conv_d_w[d * 4 + 0], wd1 = conv_d_w[d * 4 + 1], wd2 = conv_d_w[d * 4 + 2], wd3 = conv_d_w[d * 4 + 3];
        float ws0 = wf0 + wd0, ws1 = wf1 + wd1, ws2 = wf2 + wd2;
        float adot = ax * wd0 + ay * wd1 + az * wd2;
        float maxv = -1e30f;
        for (int ww = 0; ww < 3; ww++) {
            float dt = (float)(ww - 1);
            float base = dt * wd3 - adot;
            int cn = cs[ww];
            for (int k = 0; k < cn; k++) {
                float gx = gpts[ww][k][0], gy = gpts[ww][k][1], gz = gpts[ww][k][2];
                float v = fmaf(gx, ws0, fmaf(gy, ws1, fmaf(gz, ws2, base)));
                maxv = fmaxf(maxv, v);
            }
        }
        float pw0 = pos_w[d * 4 + 0], pw1 = pos_w[d * 4 + 1], pw2 = pos_w[d * 4 + 2], pw3 = pos_w[d * 4 + 3];
        float t = (float)(f + 1);
        float outv = maxv + ax * pw0 + ay * pw1 + az * pw2 + t * pw3 + pos_b[d];
        xout[((size_t)(b * SEQ + f * MM + m)) * DIM + d] = outv;
    }
}

// ---------------- per-row LN stats: one warp per row ----------------
__global__ __launch_bounds__(256)
void ln_stats_kernel(const float* __restrict__ x, float2* __restrict__ stats) {
    const int row = blockIdx.x * 8 + (threadIdx.x >> 5);
    const int lane = threadIdx.x & 31;
    const float* xr = x + (size_t)row * DIM;
    float4 v[4];
#pragma unroll
    for (int i = 0; i < 4; i++) v[i] = *reinterpret_cast<const float4*>(xr + i * 128 + lane * 4);
    float s = 0.f;
#pragma unroll
    for (int i = 0; i < 4; i++) s += v[i].x + v[i].y + v[i].z + v[i].w;
    for (int off = 16; off; off >>= 1) s += __shfl_xor_sync(0xffffffffu, s, off);
    float mu = s * (1.0f / DIM);
    float q = 0.f;
#pragma unroll
    for (int i = 0; i < 4; i++) {
        float a = v[i].x - mu, b = v[i].y - mu, c = v[i].z - mu, d = v[i].w - mu;
        q += a * a + b * b + c * c + d * d;
    }
    for (int off = 16; off; off >>= 1) q += __shfl_xor_sync(0xffffffffu, q, off);
    if (lane == 0) {
        float2 st; st.x = mu; st.y = rsqrtf(q * (1.0f / DIM) + 1e-5f);
        stats[row] = st;
    }
}

// ---------------- LayerNorm (head path, rows x 512) ----------------
__global__ void ln_kernel(const float* __restrict__ x, const float* __restrict__ gg,
                          const float* __restrict__ bb, float* __restrict__ y) {
    const int r = blockIdx.x;
    const float* xr = x + (size_t)r * DIM;
    float* yr = y + (size_t)r * DIM;
    const int tid = threadIdx.x;
    float v[4];
    float s = 0.f;
#pragma unroll
    for (int i = 0; i < 4; i++) { v[i] = xr[tid + i * 128]; s += v[i]; }
    __shared__ float red[4];
    __shared__ float s_stat;
    for (int off = 16; off; off >>= 1) s += __shfl_down_sync(0xffffffffu, s, off);
    if ((tid & 31) == 0) red[tid >> 5] = s;
    __syncthreads();
    if (tid == 0) s_stat = (red[0] + red[1] + red[2] + red[3]) * (1.0f / DIM);
    __syncthreads();
    float mu = s_stat;
    float q = 0.f;
#pragma unroll
    for (int i = 0; i < 4; i++) { float d = v[i] - mu; q += d * d; }
    __syncthreads();
    for (int off = 16; off; off >>= 1) q += __shfl_down_sync(0xffffffffu, q, off);
    if ((tid & 31) == 0) red[tid >> 5] = q;
    __syncthreads();
    if (tid == 0) s_stat = (red[0] + red[1] + red[2] + red[3]) * (1.0f / DIM);
    __syncthreads();
    float inv = rsqrtf(s_stat + 1e-5f);
#pragma unroll
    for (int i = 0; i < 4; i++) {
        int c = tid + i * 128;
        yr[c] = (v[i] - mu) * inv * gg[c] + bb[c];
    }
}

// ---------------- merged weight transpose (+tf32 round), all 20 matrices ----------------
__global__ __launch_bounds__(256)
void wtrans_all_kernel(const float* __restrict__ qkv_w, const float* __restrict__ ao_w,
                       const float* __restrict__ ff1_w, const float* __restrict__ ff2_w,
                       float* __restrict__ t_qkv, float* __restrict__ t_ao,
                       float* __restrict__ t_ff1, float* __restrict__ t_ff2) {
    __shared__ float t[32][33];
    const int tile = blockIdx.x;
    const int l = tile / 2048;
    int r = tile % 2048;
    const float* W; float* Wt; int K, N, bx, by;
    if (r < 768) {
        W = qkv_w + (size_t)l * DIM * 1536; Wt = t_qkv + (size_t)l * 1536 * DIM;
        K = DIM; N = 1536; bx = r % 48; by = r / 48;
    } else if (r < 1024) {
        r -= 768;
        W = ao_w + (size_t)l * INNER * DIM; Wt = t_ao + (size_t)l * DIM * INNER;
        K = INNER; N = DIM; bx = r % 16; by = r / 16;
    } else if (r < 1536) {
        r -= 1024;
        W = ff1_w + (size_t)l * DIM * MLP; Wt = t_ff1 + (size_t)l * MLP * DIM;
        K = DIM; N = MLP; bx = r % 32; by = r / 32;
    } else {
        r -= 1536;
        W = ff2_w + (size_t)l * MLP * DIM; Wt = t_ff2 + (size_t)l * DIM * MLP;
        K = MLP; N = DIM; bx = r % 16; by = r / 16;
    }
    const int n0 = bx * 32, k0 = by * 32;
    const int x = threadIdx.x & 31, y = threadIdx.x >> 5;  // 32 x 8
#pragma unroll
    for (int i = y; i < 32; i += 8)
        t[i][x] = W[(size_t)(k0 + i) * N + n0 + x];
    __syncthreads();
#pragma unroll
    for (int i = y; i < 32; i += 8)
        Wt[(size_t)(n0 + i) * K + k0 + x] = to_tf32(t[x][i]);
}

// ---------------- tensor-core tf32 GEMM, double-buffered smem + cp.async B ----------------
#define GEMM_TILE_F (128 * 36)
#define GEMM_SMEM (4 * GEMM_TILE_F * 4)   // 2 x As + 2 x Bs
template <bool WITH_LN, bool WITH_BIAS, bool WITH_GELU, bool WITH_RES>
__global__ __launch_bounds__(256)
void mma_gemm(const float* __restrict__ A, const float* __restrict__ Bt,
              const float2* __restrict__ stats, const float* __restrict__ lng,
              const float* __restrict__ lnb,
              const float* __restrict__ bias, const float* __restrict__ Rd,
              float* __restrict__ C, int Rr, int Kd, int Cn) {
    extern __shared__ float smbuf[];
    float* AsB = smbuf;                  // [2][128][36]
    float* BsB = smbuf + 2 * GEMM_TILE_F;
    const int bm = blockIdx.y * 128, bn = blockIdx.x * 128;
    const int tid = threadIdx.x, wid = tid >> 5, lane = tid & 31;
    const int wm = wid & 3, wn = wid >> 2;
    const int gid = lane >> 2, tig = lane & 3;

    // per-thread staging indices (fixed across chunks)
    int rowi[4], kqi[4];
    bool aoki[4];
    float2 sti[4];
    uint32_t bs_dst0[4];
#pragma unroll
    for (int i = 0; i < 4; i++) {
        int lin = tid + i * 256;
        rowi[i] = lin >> 3;
        kqi[i] = (lin & 7) * 4;
        aoki[i] = (bm + rowi[i]) < Rr;
        if (WITH_LN) sti[i] = aoki[i] ? stats[bm + rowi[i]] : make_float2(0.f, 1.f);
        bs_dst0[i] = (uint32_t)__cvta_generic_to_shared(BsB + rowi[i] * 36 + kqi[i]);
    }

    float acc[2][8][4];
#pragma unroll
    for (int mt = 0; mt < 2; mt++)
#pragma unroll
        for (int nt = 0; nt < 8; nt++)
#pragma unroll
            for (int i = 0; i < 4; i++) acc[mt][nt][i] = 0.f;

    const int nk = Kd >> 5;
    float4 pa[4];

    // stage chunk 0 into buffer 0
#pragma unroll
    for (int i = 0; i < 4; i++)
        cp_async16(bs_dst0[i], Bt + (size_t)(bn + rowi[i]) * Kd + kqi[i]);
    CP_COMMIT();
#pragma unroll
    for (int i = 0; i < 4; i++) {
        pa[i] = make_float4(0.f, 0.f, 0.f, 0.f);
        if (aoki[i]) pa[i] = *reinterpret_cast<const float4*>(A + (size_t)(bm + rowi[i]) * Kd + kqi[i]);
    }
#pragma unroll
    for (int i = 0; i < 4; i++) {
        float4 v = pa[i];
        if (WITH_LN) {
            float4 gv = *reinterpret_cast<const float4*>(lng + kqi[i]);
            float4 bv = *reinterpret_cast<const float4*>(lnb + kqi[i]);
            v.x = (v.x - sti[i].x) * sti[i].y * gv.x + bv.x;
            v.y = (v.y - sti[i].x) * sti[i].y * gv.y + bv.y;
            v.z = (v.z - sti[i].x) * sti[i].y * gv.z + bv.z;
            v.w = (v.w - sti[i].x) * sti[i].y * gv.w + bv.w;
        }
        float* as = AsB + rowi[i] * 36 + kqi[i];
        as[0] = to_tf32(v.x); as[1] = to_tf32(v.y); as[2] = to_tf32(v.z); as[3] = to_tf32(v.w);
    }
    CP_WAIT0();
    __syncthreads();

    for (int c = 0; c < nk; c++) {
        const int cur = c & 1, nxt = cur ^ 1;
        const int k0n = (c + 1) * 32;
        const bool more = (c + 1) < nk;
        if (more) {
            // issue next B cp.async into other buffer + next A LDG
#pragma unroll
            for (int i = 0; i < 4; i++)
                cp_async16(bs_dst0[i] + nxt * (GEMM_TILE_F * 4),
                           Bt + (size_t)(bn + rowi[i]) * Kd + k0n + kqi[i]);
            CP_COMMIT();
#pragma unroll
            for (int i = 0; i < 4; i++) {
                pa[i] = make_float4(0.f, 0.f, 0.f, 0.f);
                if (aoki[i]) pa[i] = *reinterpret_cast<const float4*>(A + (size_t)(bm + rowi[i]) * Kd + k0n + kqi[i]);
            }
        }
        // compute current buffer
        const float* Asc = AsB + cur * GEMM_TILE_F;
        const float* Bsc = BsB + cur * GEMM_TILE_F;
#pragma unroll
        for (int ks = 0; ks < 4; ks++) {
            const int kb = ks * 8;
            uint32_t af[2][4];
#pragma unroll
            for (int mt = 0; mt < 2; mt++) {
                int row = wm * 32 + mt * 16 + gid;
                af[mt][0] = __float_as_uint(Asc[row * 36 + kb + tig]);
                af[mt][1] = __float_as_uint(Asc[(row + 8) * 36 + kb + tig]);
                af[mt][2] = __float_as_uint(Asc[row * 36 + kb + tig + 4]);
                af[mt][3] = __float_as_uint(Asc[(row + 8) * 36 + kb + tig + 4]);
            }
            uint32_t bf[8][2];
#pragma unroll
            for (int nt = 0; nt < 8; nt++) {
                int col = wn * 64 + nt * 8 + gid;
                bf[nt][0] = __float_as_uint(Bsc[col * 36 + kb + tig]);
                bf[nt][1] = __float_as_uint(Bsc[col * 36 + kb + tig + 4]);
            }
#pragma unroll
            for (int mt = 0; mt < 2; mt++)
#pragma unroll
                for (int nt = 0; nt < 8; nt++)
                    mma_tf32(acc[mt][nt], af[mt], bf[nt]);
        }
        if (more) {
            // store next A into other buffer (not read until after the sync)
            float* Asn = AsB + nxt * GEMM_TILE_F;
#pragma unroll
            for (int i = 0; i < 4; i++) {
                float4 v = pa[i];
                if (WITH_LN) {
                    float4 gv = *reinterpret_cast<const float4*>(lng + k0n + kqi[i]);
                    float4 bv = *reinterpret_cast<const float4*>(lnb + k0n + kqi[i]);
                    v.x = (v.x - sti[i].x) * sti[i].y * gv.x + bv.x;
                    v.y = (v.y - sti[i].x) * sti[i].y * gv.y + bv.y;
                    v.z = (v.z - sti[i].x) * sti[i].y * gv.z + bv.z;
                    v.w = (v.w - sti[i].x) * sti[i].y * gv.w + bv.w;
                }
                float* as = Asn + rowi[i] * 36 + kqi[i];
                as[0] = to_tf32(v.x); as[1] = to_tf32(v.y); as[2] = to_tf32(v.z); as[3] = to_tf32(v.w);
            }
            CP_WAIT0();
            __syncthreads();
        }
    }

#pragma unroll
    for (int mt = 0; mt < 2; mt++) {
#pragma unroll
        for (int half = 0; half < 2; half++) {
            int row = bm + wm * 32 + mt * 16 + half * 8 + gid;
            if (row >= Rr) continue;
            float* crow = C + (size_t)row * Cn;
            const float* rrow = WITH_RES ? (Rd + (size_t)row * Cn) : nullptr;
#pragma unroll
            for (int nt = 0; nt < 8; nt++) {
                int col = bn + wn * 64 + nt * 8 + 2 * tig;
                float v0 = acc[mt][nt][half * 2 + 0];
                float v1 = acc[mt][nt][half * 2 + 1];
                if (WITH_BIAS) { v0 += bias[col]; v1 += bias[col + 1]; }
                if (WITH_GELU) { v0 = gelu_f(v0); v1 = gelu_f(v1); }
                if (WITH_RES)  { v0 += rrow[col]; v1 += rrow[col + 1]; }
                float2 o2; o2.x = v0; o2.y = v1;
                *reinterpret_cast<float2*>(crow + col) = o2;
            }
        }
    }
}

// ---------------- fp32 tiled GEMM (head GEMMs, tiny M) ----------------
template <bool WITH_BIAS, bool WITH_GELU, bool WITH_RES>
__global__ __launch_bounds__(256)
void gemm128(const float* __restrict__ A, const float* __restrict__ W,
             const float* __restrict__ bias, const float* __restrict__ Rd,
             float* __restrict__ C, int Rr, int Kd, int Cn) {
    __shared__ float As[8][132];
    __shared__ float Bs[8][64];
    const int bn = blockIdx.x * 64;
    const int bm = blockIdx.y * 128;
    const int tid = threadIdx.x;
    const int tx = tid & 15, ty = tid >> 4;
    float acc[8][4];
#pragma unroll
    for (int u = 0; u < 8; u++)
#pragma unroll
        for (int v = 0; v < 4; v++) acc[u][v] = 0.f;

    const int arow = bm + (tid >> 1);
    const int kh = (tid & 1) * 4;
    const bool aval = arow < Rr;
    const int am = tid >> 1;
    const int bk = tid >> 4;
    const int bn4 = (tid & 15) * 4;

    for (int k0 = 0; k0 < Kd; k0 += 8) {
        float4 av = make_float4(0.f, 0.f, 0.f, 0.f);
        if (aval) av = *reinterpret_cast<const float4*>(A + (size_t)arow * Kd + k0 + kh);
        As[kh + 0][am] = av.x; As[kh + 1][am] = av.y; As[kh + 2][am] = av.z; As[kh + 3][am] = av.w;
        if (tid < 128) {
            float4 bv = *reinterpret_cast<const float4*>(W + (size_t)(k0 + bk) * Cn + bn + bn4);
            *reinterpret_cast<float4*>(&Bs[bk][bn4]) = bv;
        }
        __syncthreads();
#pragma unroll
        for (int kk = 0; kk < 8; kk++) {
            float4 a0 = *reinterpret_cast<const float4*>(&As[kk][ty * 8]);
            float4 a1 = *reinterpret_cast<const float4*>(&As[kk][ty * 8 + 4]);
            float4 b4 = *reinterpret_cast<const float4*>(&Bs[kk][tx * 4]);
            float aa[8] = {a0.x, a0.y, a0.z, a0.w, a1.x, a1.y, a1.z, a1.w};
            float bb4[4] = {b4.x, b4.y, b4.z, b4.w};
#pragma unroll
            for (int u = 0; u < 8; u++)
#pragma unroll
                for (int v = 0; v < 4; v++) acc[u][v] = fmaf(aa[u], bb4[v], acc[u][v]);
        }
        __syncthreads();
    }
#pragma unroll
    for (int u = 0; u < 8; u++) {
        int row = bm + ty * 8 + u;
        if (row < Rr) {
#pragma unroll
            for (int v = 0; v < 4; v++) {
                int col = bn + tx * 4 + v;
                float c = acc[u][v];
                if (WITH_BIAS) c += bias[col];
                if (WITH_GELU) c = gelu_f(c);
                if (WITH_RES) c += Rd[(size_t)row * Cn + col];
                C[(size_t)row * Cn + col] = c;
            }
        }
    }
}

// ---------------- attention: flash, tensor-core QK^T and PV, K/V prefetch pipelined ----------------
#define ASTR 68
#define ATTN_SMEM ((6 * 64 * ASTR + 128) * 4)
__global__ __launch_bounds__(256)
void attn_kernel(const float* __restrict__ qkv, float* __restrict__ o) {
    extern __shared__ float sm[];
    float* Qhi = sm;
    float* Qlo = Qhi + 64 * ASTR;
    float* Ks  = Qlo + 64 * ASTR;
    float* Vs  = Ks  + 64 * ASTR;
    float* Ph  = Vs  + 64 * ASTR;
    float* Pl  = Ph  + 64 * ASTR;
    float* crow = Pl + 64 * ASTR;   // 64
    float* lrow = crow + 64;        // 64

    const int qt = blockIdx.x, h = blockIdx.y, b = blockIdx.z;
    const int tid = threadIdx.x, lane = tid & 31, wid = tid >> 5;
    const int wm = wid & 3, wn = wid >> 2;      // 4m x 2n warp grid over 64x64
    const int gid = lane >> 2, tig = lane & 3;

    // K/V staging indices: 4 x float4 per tile per array
    int kvr[4], kvd[4];
#pragma unroll
    for (int i = 0; i < 4; i++) {
        int lin = tid + i * 256;
        kvr[i] = lin >> 4;
        kvd[i] = (lin & 15) * 4;
    }
    float4 kpf[4], vpf[4];

    // load Q tile, split hi/lo
#pragma unroll
    for (int i = 0; i < 16; i++) {
        int lid = tid + i * 256;
        int r = lid >> 6, d = lid & 63;
        int s = qt * 64 + r;
        float q = (s < SEQ) ? qkv[((size_t)(b * SEQ + s)) * (3 * INNER) + h * DH + d] : 0.f;
        float qh = to_tf32(q);
        Qhi[r * ASTR + d] = qh;
        Qlo[r * ASTR + d] = to_tf32(q - qh);
    }
    // prefetch + store K/V tile 0
#pragma unroll
    for (int i = 0; i < 4; i++) {
        int s = kvr[i];  // kt=0
        size_t base = ((size_t)(b * SEQ + s)) * (3 * INNER) + h * DH + kvd[i];
        kpf[i] = *reinterpret_cast<const float4*>(qkv + base + INNER);
        vpf[i] = *reinterpret_cast<const float4*>(qkv + base + 2 * INNER);
    }
#pragma unroll
    for (int i = 0; i < 4; i++) {
        int off = kvr[i] * ASTR + kvd[i];
        Ks[off] = to_tf32(kpf[i].x); Ks[off + 1] = to_tf32(kpf[i].y);
        Ks[off + 2] = to_tf32(kpf[i].z); Ks[off + 3] = to_tf32(kpf[i].w);
        Vs[off] = to_tf32(vpf[i].x); Vs[off + 1] = to_tf32(vpf[i].y);
        Vs[off + 2] = to_tf32(vpf[i].z); Vs[off + 3] = to_tf32(vpf[i].w);
    }

    float oacc[4][4];
#pragma unroll
    for (int nt = 0; nt < 4; nt++)
#pragma unroll
        for (int i = 0; i < 4; i++) oacc[nt][i] = 0.f;
    float mcur = -1e30f, lcur = 0.f;
    const int srow = tid >> 2;
    const int scol = (tid & 3) * 16;
    __syncthreads();

    for (int kt = 0; kt < 13; kt++) {
        // S = Q @ K^T
        float sacc[4][4];
#pragma unroll
        for (int nt = 0; nt < 4; nt++)
#pragma unroll
            for (int i = 0; i < 4; i++) sacc[nt][i] = 0.f;
#pragma unroll
        for (int ks = 0; ks < 8; ks++) {
            const int kb = ks * 8;
            const int r0 = (wm * 16 + gid) * ASTR;
            uint32_t ah[4], al[4];
            ah[0] = __float_as_uint(Qhi[r0 + kb + tig]);
            ah[1] = __float_as_uint(Qhi[r0 + 8 * ASTR + kb + tig]);
            ah[2] = __float_as_uint(Qhi[r0 + kb + tig + 4]);
            ah[3] = __float_as_uint(Qhi[r0 + 8 * ASTR + kb + tig + 4]);
            al[0] = __float_as_uint(Qlo[r0 + kb + tig]);
            al[1] = __float_as_uint(Qlo[r0 + 8 * ASTR + kb + tig]);
            al[2] = __float_as_uint(Qlo[r0 + kb + tig + 4]);
            al[3] = __float_as_uint(Qlo[r0 + 8 * ASTR + kb + tig + 4]);
#pragma unroll
            for (int nt = 0; nt < 4; nt++) {
                const int nc = (wn * 32 + nt * 8 + gid) * ASTR;
                uint32_t bf[2];
                bf[0] = __float_as_uint(Ks[nc + kb + tig]);
                bf[1] = __float_as_uint(Ks[nc + kb + tig + 4]);
                mma_tf32(sacc[nt], ah, bf);
                mma_tf32(sacc[nt], al, bf);
            }
        }
        // write S (scaled, masked) to Ph
        {
            const int r0 = wm * 16 + gid;
#pragma unroll
            for (int nt = 0; nt < 4; nt++) {
                int c = wn * 32 + nt * 8 + 2 * tig;
                int kg = kt * 64 + c;
                float2 s01, s23;
                s01.x = (kg < SEQ)     ? sacc[nt][0] * 0.125f : -1e30f;
                s01.y = (kg + 1 < SEQ) ? sacc[nt][1] * 0.125f : -1e30f;
                s23.x = (kg < SEQ)     ? sacc[nt][2] * 0.125f : -1e30f;
                s23.y = (kg + 1 < SEQ) ? sacc[nt][3] * 0.125f : -1e30f;
                *reinterpret_cast<float2*>(&Ph[r0 * ASTR + c]) = s01;
                *reinterpret_cast<float2*>(&Ph[(r0 + 8) * ASTR + c]) = s23;
            }
        }
        __syncthreads();

        // softmax: 4 lanes per row, in-place Ph -> p_hi, Pl -> p_lo
        {
            float sv[16];
#pragma unroll
            for (int i = 0; i < 4; i++) {
                float4 v4 = *reinterpret_cast<const float4*>(&Ph[srow * ASTR + scol + i * 4]);
                sv[i * 4 + 0] = v4.x; sv[i * 4 + 1] = v4.y; sv[i * 4 + 2] = v4.z; sv[i * 4 + 3] = v4.w;
            }
            float rm = sv[0];
#pragma unroll
            for (int i = 1; i < 16; i++) rm = fmaxf(rm, sv[i]);
            rm = fmaxf(rm, __shfl_xor_sync(0xffffffffu, rm, 1));
            rm = fmaxf(rm, __shfl_xor_sync(0xffffffffu, rm, 2));
            float mnew = fmaxf(mcur, rm);
            float corr = __expf(mcur - mnew);
            float ssum = 0.f;
#pragma unroll
            for (int i = 0; i < 4; i++) {
                float4 hv, lv;
                float p0 = __expf(sv[i * 4 + 0] - mnew);
                float p1 = __expf(sv[i * 4 + 1] - mnew);
                float p2 = __expf(sv[i * 4 + 2] - mnew);
                float p3 = __expf(sv[i * 4 + 3] - mnew);
                ssum += (p0 + p1) + (p2 + p3);
                hv.x = to_tf32(p0); hv.y = to_tf32(p1); hv.z = to_tf32(p2); hv.w = to_tf32(p3);
                lv.x = to_tf32(p0 - hv.x); lv.y = to_tf32(p1 - hv.y);
                lv.z = to_tf32(p2 - hv.z); lv.w = to_tf32(p3 - hv.w);
                *reinterpret_cast<float4*>(&Ph[srow * ASTR + scol + i * 4]) = hv;
                *reinterpret_cast<float4*>(&Pl[srow * ASTR + scol + i * 4]) = lv;
            }
            ssum += __shfl_xor_sync(0xffffffffu, ssum, 1);
            ssum += __shfl_xor_sync(0xffffffffu, ssum, 2);
            lcur = lcur * corr + ssum;
            mcur = mnew;
            if ((tid & 3) == 0) crow[srow] = corr;
        }
        __syncthreads();

        // prefetch next K/V during PV compute
        if (kt + 1 < 13) {
#pragma unroll
            for (int i = 0; i < 4; i++) {
                int s = (kt + 1) * 64 + kvr[i];
                size_t base = ((size_t)(b * SEQ + (s < SEQ ? s : 0))) * (3 * INNER) + h * DH + kvd[i];
                if (s < SEQ) {
                    kpf[i] = *reinterpret_cast<const float4*>(qkv + base + INNER);
                    vpf[i] = *reinterpret_cast<const float4*>(qkv + base + 2 * INNER);
                } else {
                    kpf[i] = make_float4(0.f, 0.f, 0.f, 0.f);
                    vpf[i] = make_float4(0.f, 0.f, 0.f, 0.f);
                }
            }
        }

        // rescale O by corr, then O += P @ V
        {
            float c0 = crow[wm * 16 + gid];
            float c1 = crow[wm * 16 + gid + 8];
#pragma unroll
            for (int nt = 0; nt < 4; nt++) {
                oacc[nt][0] *= c0; oacc[nt][1] *= c0;
                oacc[nt][2] *= c1; oacc[nt][3] *= c1;
            }
        }
#pragma unroll
        for (int ks = 0; ks < 8; ks++) {
            const int kb = ks * 8;
            const int r0 = (wm * 16 + gid) * ASTR;
            uint32_t ah[4], al[4];
            ah[0] = __float_as_uint(Ph[r0 + kb + tig]);
            ah[1] = __float_as_uint(Ph[r0 + 8 * ASTR + kb + tig]);
            ah[2] = __float_as_uint(Ph[r0 + kb + tig + 4]);
            ah[3] = __float_as_uint(Ph[r0 + 8 * ASTR + kb + tig + 4]);
            al[0] = __float_as_uint(Pl[r0 + kb + tig]);
            al[1] = __float_as_uint(Pl[r0 + 8 * ASTR + kb + tig]);
            al[2] = __float_as_uint(Pl[r0 + kb + tig + 4]);
            al[3] = __float_as_uint(Pl[r0 + 8 * ASTR + kb + tig + 4]);
#pragma unroll
            for (int nt = 0; nt < 4; nt++) {
                const int nc = wn * 32 + nt * 8 + gid;
                uint32_t bf[2];
                bf[0] = __float_as_uint(Vs[(kb + tig) * ASTR + nc]);
                bf[1] = __float_as_uint(Vs[(kb + tig + 4) * ASTR + nc]);
                mma_tf32(oacc[nt], ah, bf);
                mma_tf32(oacc[nt], al, bf);
            }
        }
        __syncthreads();
        if (kt + 1 < 13) {
#pragma unroll
            for (int i = 0; i < 4; i++) {
                int off = kvr[i] * ASTR + kvd[i];
                Ks[off] = to_tf32(kpf[i].x); Ks[off + 1] = to_tf32(kpf[i].y);
                Ks[off + 2] = to_tf32(kpf[i].z); Ks[off + 3] = to_tf32(kpf[i].w);
                Vs[off] = to_tf32(vpf[i].x); Vs[off + 1] = to_tf32(vpf[i].y);
                Vs[off + 2] = to_tf32(vpf[i].z); Vs[off + 3] = to_tf32(vpf[i].w);
            }
            __syncthreads();
        }
    }

    if ((tid & 3) == 0) lrow[srow] = lcur;
    __syncthreads();

    // store O
    {
        const int r0 = wm * 16 + gid;
        const int s0 = qt * 64 + r0, s1 = s0 + 8;
        float inv0 = 1.0f / lrow[r0];
        float inv1 = 1.0f / lrow[r0 + 8];
#pragma unroll
        for (int nt = 0; nt < 4; nt++) {
            int d = wn * 32 + nt * 8 + 2 * tig;
            if (s0 < SEQ) {
                float2 o2; o2.x = oacc[nt][0] * inv0; o2.y = oacc[nt][1] * inv0;
                *reinterpret_cast<float2*>(o + ((size_t)(b * SEQ + s0)) * INNER + h * DH + d) = o2;
            }
            if (s1 < SEQ) {
                float2 o2; o2.x = oacc[nt][2] * inv1; o2.y = oacc[nt][3] * inv1;
                *reinterpret_cast<float2*>(o + ((size_t)(b * SEQ + s1)) * INNER + h * DH + d) = o2;
            }
        }
    }
}

// ---------------- max over sequence: two stage ----------------
__global__ void maxpool1_kernel(const float* __restrict__ x, float* __restrict__ part) {
    const int c = blockIdx.x, b = blockIdx.y;
    const int d = threadIdx.x;  // 512
    const int s0 = c * 60;
    float m0 = -1e30f, m1 = -1e30f, m2 = -1e30f, m3 = -1e30f;
    for (int s = s0; s < s0 + 60; s += 4) {
        m0 = fmaxf(m0, x[((size_t)(b * SEQ + s + 0)) * DIM + d]);
        m1 = fmaxf(m1, x[((size_t)(b * SEQ + s + 1)) * DIM + d]);
        m2 = fmaxf(m2, x[((size_t)(b * SEQ + s + 2)) * DIM + d]);
        m3 = fmaxf(m3, x[((size_t)(b * SEQ + s + 3)) * DIM + d]);
    }
    part[((size_t)(b * 13 + c)) * DIM + d] = fmaxf(fmaxf(m0, m1), fmaxf(m2, m3));
}

__global__ void maxpool2_kernel(const float* __restrict__ part, float* __restrict__ o) {
    const int b = blockIdx.x, d = threadIdx.x;
    float m = -1e30f;
#pragma unroll
    for (int c = 0; c < 13; c++) m = fmaxf(m, part[((size_t)(b * 13 + c)) * DIM + d]);
    o[b * DIM + d] = m;
}

// ---------------- head softmax @ anchors ----------------
__global__ void head_kernel(const float* __restrict__ h2, float* __restrict__ out) {
    const int bg = blockIdx.x;
    const int b = bg / 17, g = bg % 17;
    const int tid = threadIdx.x;  // 64
    float v = h2[b * OUTD + g * 64 + tid];
    __shared__ float wred[2];
    __shared__ float wts[64];
    float m = v;
    for (int off = 16; off; off >>= 1) m = fmaxf(m, __shfl_xor_sync(0xffffffffu, m, off));
    if ((tid & 31) == 0) wred[tid >> 5] = m;
    __syncthreads();
    m = fmaxf(wred[0], wred[1]);
    float e = expf(v - m);
    float s = e;
    for (int off = 16; off; off >>= 1) s += __shfl_xor_sync(0xffffffffu, s, off);
    __syncthreads();
    if ((tid & 31) == 0) wred[tid >> 5] = s;
    __syncthreads();
    float tot = wred[0] + wred[1];
    wts[tid] = e / tot;
    __syncthreads();
    if (tid < 3) {
        float acc = 0.f;
        for (int j = 0; j < 64; j++) {
            float ac = (tid == 0) ? (-1.5f + (float)(j >> 4))
                     : (tid == 1) ? (-1.5f + (float)((j >> 2) & 3))
                                  : (-1.5f + (float)(j & 3));
            acc += wts[j] * ac;
        }
        out[(size_t)(b * 17 + g) * 3 + tid] = acc;
    }
}

// ---------------- launch ----------------
#define FPS_SMEM (NTOT * 4 * 4)

extern "C" void kernel_launch(void* const* d_in, const int* in_sizes, int n_in,
                              void* d_out, int out_size) {
    const float* points     = (const float*)d_in[0];
    const float* conv_d_w   = (const float*)d_in[1];
    const float* conv_f_w   = (const float*)d_in[2];
    const float* pos_w      = (const float*)d_in[3];
    const float* pos_b      = (const float*)d_in[4];
    const float* ln1_g      = (const float*)d_in[5];
    const float* ln1_b      = (const float*)d_in[6];
    const float* qkv_w      = (const float*)d_in[7];
    const float* attn_out_w = (const float*)d_in[8];
    const float* attn_out_b = (const float*)d_in[9];
    const float* ln2_g      = (const float*)d_in[10];
    const float* ln2_b      = (const float*)d_in[11];
    const float* ff1_w      = (const float*)d_in[12];
    const float* ff1_b      = (const float*)d_in[13];
    const float* ff2_w      = (const float*)d_in[14];
    const float* ff2_b      = (const float*)d_in[15];
    const float* head_ln_g  = (const float*)d_in[16];
    const float* head_ln_b  = (const float*)d_in[17];
    const float* head1_w    = (const float*)d_in[18];
    const float* head1_b    = (const float*)d_in[19];
    const float* head2_w    = (const float*)d_in[20];
    const float* head2_b    = (const float*)d_in[21];
    float* out = (float*)d_out;

    static bool inited = false;
    static float *p_axyz, *p_x, *p_qkv, *p_att, *p_ff1, *p_pmax, *p_pool, *p_pooln, *p_h1, *p_h2;
    static float2* p_stats;
    static float *p_t_qkv, *p_t_ao, *p_t_ff1, *p_t_ff2;
    if (!inited) {
        cudaGetSymbolAddress((void**)&p_axyz, g_axyz);
        cudaGetSymbolAddress((void**)&p_x, g_x);
        cudaGetSymbolAddress((void**)&p_qkv, g_qkv);
        cudaGetSymbolAddress((void**)&p_att, g_att);
        cudaGetSymbolAddress((void**)&p_ff1, g_ff1);
        cudaGetSymbolAddress((void**)&p_stats, g_stats);
        cudaGetSymbolAddress((void**)&p_pmax, g_pmax);
        cudaGetSymbolAddress((void**)&p_pool, g_pool);
        cudaGetSymbolAddress((void**)&p_pooln, g_pooln);
        cudaGetSymbolAddress((void**)&p_h1, g_h1);
        cudaGetSymbolAddress((void**)&p_h2, g_h2);
        cudaGetSymbolAddress((void**)&p_t_qkv, g_t_qkv);
        cudaGetSymbolAddress((void**)&p_t_ao, g_t_ao);
        cudaGetSymbolAddress((void**)&p_t_ff1, g_t_ff1);
        cudaGetSymbolAddress((void**)&p_t_ff2, g_t_ff2);
        cudaFuncSetAttribute(fps_kernel, cudaFuncAttributeMaxDynamicSharedMemorySize, FPS_SMEM);
        cudaFuncSetAttribute(attn_kernel, cudaFuncAttributeMaxDynamicSharedMemorySize, ATTN_SMEM);
        cudaFuncSetAttribute(mma_gemm<true, false, false, false>, cudaFuncAttributeMaxDynamicSharedMemorySize, GEMM_SMEM);
        cudaFuncSetAttribute(mma_gemm<false, true, false, true>, cudaFuncAttributeMaxDynamicSharedMemorySize, GEMM_SMEM);
        cudaFuncSetAttribute(mma_gemm<true, true, true, false>, cudaFuncAttributeMaxDynamicSharedMemorySize, GEMM_SMEM);
        inited = true;
    }

    // 0. transpose + tf32-round all weights (single launch)
    wtrans_all_kernel<<<DEPTH * 2048, 256>>>(qkv_w, attn_out_w, ff1_w, ff2_w,
                                             p_t_qkv, p_t_ao, p_t_ff1, p_t_ff2);

    // 1. FPS anchors
    fps_kernel<<<BD * NF, 512, FPS_SMEM>>>(points, p_axyz);
    // 2. grouping + conv + max + positional embed -> x
    group_kernel<<<dim3(MM, NF, BD), 256>>>(points, conv_d_w, conv_f_w, pos_w, pos_b, p_axyz, p_x);

    // 3. transformer (tensor-core tf32 GEMMs + tensor-core attention, double-buffered)
    const int MT = (ROWS + 127) / 128;  // 49
    for (int l = 0; l < DEPTH; l++) {
        ln_stats_kernel<<<ROWS / 8, 256>>>(p_x, p_stats);
        mma_gemm<true, false, false, false><<<dim3((3 * INNER) / 128, MT), 256, GEMM_SMEM>>>(
            p_x, p_t_qkv + (size_t)l * 3 * INNER * DIM, p_stats, ln1_g + l * DIM, ln1_b + l * DIM,
            nullptr, nullptr, p_qkv, ROWS, DIM, 3 * INNER);
        attn_kernel<<<dim3(13, HEADS, BD), 256, ATTN_SMEM>>>(p_qkv, p_att);
        mma_gemm<false, true, false, true><<<dim3(DIM / 128, MT), 256, GEMM_SMEM>>>(
            p_att, p_t_ao + (size_t)l * DIM * INNER, nullptr, nullptr, nullptr,
            attn_out_b + l * DIM, p_x, p_x, ROWS, INNER, DIM);
        ln_stats_kernel<<<ROWS / 8, 256>>>(p_x, p_stats);
        mma_gemm<true, true, true, false><<<dim3(MLP / 128, MT), 256, GEMM_SMEM>>>(
            p_x, p_t_ff1 + (size_t)l * MLP * DIM, p_stats, ln2_g + l * DIM, ln2_b + l * DIM,
            ff1_b + l * MLP, nullptr, p_ff1, ROWS, DIM, MLP);
        mma_gemm<false, true, false, true><<<dim3(DIM / 128, MT), 256, GEMM_SMEM>>>(
            p_ff1, p_t_ff2 + (size_t)l * DIM * MLP, nullptr, nullptr, nullptr,
            ff2_b + l * DIM, p_x, p_x, ROWS, MLP, DIM);
    }

    // 4. head (tiny GEMMs stay on SIMT path)
    maxpool1_kernel<<<dim3(13, BD), DIM>>>(p_x, p_pmax);
    maxpool2_kernel<<<BD, DIM>>>(p_pmax, p_pool);
    ln_kernel<<<BD, 128>>>(p_pool, head_ln_g, head_ln_b, p_pooln);
    gemm128<true, true, false><<<dim3(MLP / 64, 1), 256>>>(p_pooln, head1_w, head1_b, nullptr, p_h1, BD, DIM, MLP);
    gemm128<true, false, false><<<dim3(OUTD / 64, 1), 256>>>(p_h1, head2_w, head2_b, nullptr, p_h2, BD, MLP, OUTD);
    head_kernel<<<BD * 17, 64>>>(p_h2, out);
}